// round 3
// baseline (speedup 1.0000x reference)
#include <cuda_runtime.h>

typedef unsigned long long u64;

__device__ __forceinline__ u64 pack2(float x, float y) {
    u64 r; asm("mov.b64 %0,{%1,%2};" : "=l"(r) : "f"(x), "f"(y)); return r;
}
__device__ __forceinline__ u64 dup2(float x) { return pack2(x, x); }
__device__ __forceinline__ void fma2(u64& d, u64 a, u64 b) {
    asm("fma.rn.f32x2 %0,%1,%2,%0;" : "+l"(d) : "l"(a), "l"(b));
}
__device__ __forceinline__ float2 unpk(u64 v) {
    float2 r; asm("mov.b64 {%0,%1},%2;" : "=f"(r.x), "=f"(r.y) : "l"(v)); return r;
}

__device__ float g_b0[32u * 128 * 128 * 128];
__device__ float g_b1[32u * 256 * 64 * 64];
__device__ float g_b2[32u * 512 * 32 * 32];
__device__ float g_b3[32u * 32 * 64 * 64];
__device__ float g_ze[32u * 64 * 32 * 32];
__device__ float g_zq[32u * 64 * 32 * 32];
__device__ float g_loss[1];

// ---------------- conv k4 s2 p1 : tile 128co x 2oh x 32ow, 256 thr ----------
// FFMA2 packed over Co pairs.
__global__ void __launch_bounds__(256) conv4s2_kernel(
    const float* __restrict__ in, const float* __restrict__ w,
    const float* __restrict__ bias, float* __restrict__ out,
    int Ci, int Co, int Hi, int Wi, int Ho, int Wo, int relu)
{
    __shared__ float w_s[2][16][128];
    __shared__ u64 x_s[2][6][66];
    const int tid = threadIdx.x;
    const int wx = tid & 7, cy = tid >> 3;
    const int w0 = blockIdx.x * 32, oh0 = blockIdx.y * 2;
    const int cot = Co >> 7;
    const int b = blockIdx.z / cot, c0 = (blockIdx.z % cot) << 7;
    const int ihb = 4 * (int)blockIdx.y - 1, iwb = 2 * w0 - 1;

    u64 acc[2][2][4];   // [co-pair][r][j]
#pragma unroll
    for (int p = 0; p < 2; p++)
#pragma unroll
        for (int r = 0; r < 2; r++)
#pragma unroll
            for (int j = 0; j < 4; j++) acc[p][r][j] = 0ull;

    for (int ci0 = 0; ci0 < Ci; ci0 += 2) {
        const int cik = min(2, Ci - ci0);
        for (int idx = tid; idx < cik * 6 * 66; idx += 256) {
            int lc = idx % 66, t = idx / 66, lr = t % 6, ci = t / 6;
            int ih = ihb + lr, iw = iwb + lc;
            float v = 0.f;
            if ((unsigned)ih < (unsigned)Hi && (unsigned)iw < (unsigned)Wi)
                v = in[((size_t)(b * Ci + ci0 + ci) * Hi + ih) * Wi + iw];
            x_s[ci][lr][lc] = dup2(v);
        }
        for (int idx = tid; idx < cik * 16 * 128; idx += 256) {
            int t = idx & 15, co = (idx >> 4) & 127, ci = idx >> 11;
            w_s[ci][t][co] = w[((size_t)(c0 + co) * Ci + ci0 + ci) * 16 + t];
        }
        __syncthreads();
        for (int ci = 0; ci < cik; ci++) {
#pragma unroll
            for (int kh = 0; kh < 4; kh++)
#pragma unroll
                for (int kw = 0; kw < 4; kw++) {
                    const ulonglong2 wp = *(const ulonglong2*)&w_s[ci][(kh << 2) + kw][cy << 2];
#pragma unroll
                    for (int r = 0; r < 2; r++) {
                        const u64* xr = &x_s[ci][2 * r + kh][(wx << 3) + kw];
#pragma unroll
                        for (int j = 0; j < 4; j++) {
                            const u64 xv = xr[2 * j];
                            fma2(acc[0][r][j], wp.x, xv);
                            fma2(acc[1][r][j], wp.y, xv);
                        }
                    }
                }
        }
        __syncthreads();
    }
#pragma unroll
    for (int p = 0; p < 2; p++)
#pragma unroll
        for (int r = 0; r < 2; r++) {
            float2 u[4];
#pragma unroll
            for (int j = 0; j < 4; j++) u[j] = unpk(acc[p][r][j]);
#pragma unroll
            for (int h = 0; h < 2; h++) {
                const int co = c0 + (cy << 2) + 2 * p + h;
                const float bv = bias ? bias[co] : 0.f;
                float4 o = h ? make_float4(u[0].y + bv, u[1].y + bv, u[2].y + bv, u[3].y + bv)
                             : make_float4(u[0].x + bv, u[1].x + bv, u[2].x + bv, u[3].x + bv);
                if (relu) {
                    o.x = fmaxf(o.x, 0.f); o.y = fmaxf(o.y, 0.f);
                    o.z = fmaxf(o.z, 0.f); o.w = fmaxf(o.w, 0.f);
                }
                *(float4*)&out[((size_t)(b * Co + co) * Ho + oh0 + r) * Wo + w0 + (wx << 2)] = o;
            }
        }
}

// ---------------- 3x3 conv pad1, Co=32, fused input relu, FFMA2 -------------
template <int COLS>
__global__ void __launch_bounds__(256) conv3x3_kernel(
    const float* __restrict__ in, const float* __restrict__ w,
    float* __restrict__ out, int Ci, int HW)
{
    constexpr int SLOTS = 8 * COLS / 4;
    __shared__ float w_s[4][9][32];
    __shared__ u64 x_s[4][10][COLS + 2];
    const int tid = threadIdx.x;
    const int s = tid % SLOTS, g = tid / SLOTS;
    const int r = s / (COLS / 4), cb = (s % (COLS / 4)) << 2;
    const int ow0 = blockIdx.x * COLS, oh0 = blockIdx.y * 8, b = blockIdx.z;
    const int NT = SLOTS * 8;

    u64 acc[2][4];
#pragma unroll
    for (int p = 0; p < 2; p++)
#pragma unroll
        for (int j = 0; j < 4; j++) acc[p][j] = 0ull;

    for (int ci0 = 0; ci0 < Ci; ci0 += 4) {
        for (int idx = tid; idx < 4 * 10 * (COLS + 2); idx += NT) {
            int lc = idx % (COLS + 2), t = idx / (COLS + 2), lr = t % 10, ci = t / 10;
            int ih = oh0 - 1 + lr, iw = ow0 - 1 + lc;
            float v = 0.f;
            if ((unsigned)ih < (unsigned)HW && (unsigned)iw < (unsigned)HW)
                v = in[((size_t)(b * Ci + ci0 + ci) * HW + ih) * HW + iw];
            x_s[ci][lr][lc] = dup2(fmaxf(v, 0.f));
        }
        for (int idx = tid; idx < 1152; idx += NT) {
            int t = idx % 9, q = idx / 9, ci = q & 3, co = q >> 2;
            w_s[ci][t][co] = w[((size_t)co * Ci + ci0 + ci) * 9 + t];
        }
        __syncthreads();
#pragma unroll
        for (int ci = 0; ci < 4; ci++)
#pragma unroll
            for (int kh = 0; kh < 3; kh++)
#pragma unroll
                for (int kw = 0; kw < 3; kw++) {
                    const ulonglong2 wp = *(const ulonglong2*)&w_s[ci][kh * 3 + kw][g << 2];
                    const u64* xr = &x_s[ci][r + kh][cb + kw];
#pragma unroll
                    for (int j = 0; j < 4; j++) {
                        const u64 xv = xr[j];
                        fma2(acc[0][j], wp.x, xv);
                        fma2(acc[1][j], wp.y, xv);
                    }
                }
        __syncthreads();
    }
#pragma unroll
    for (int p = 0; p < 2; p++) {
        float2 u[4];
#pragma unroll
        for (int j = 0; j < 4; j++) u[j] = unpk(acc[p][j]);
        const int cobase = (g << 2) + 2 * p;
        float4 oe = {u[0].x, u[1].x, u[2].x, u[3].x};
        float4 oo = {u[0].y, u[1].y, u[2].y, u[3].y};
        *(float4*)&out[(((size_t)b * 32 + cobase) * HW + oh0 + r) * HW + ow0 + cb] = oe;
        *(float4*)&out[(((size_t)b * 32 + cobase + 1) * HW + oh0 + r) * HW + ow0 + cb] = oo;
    }
}

// ---------------- 1x1 conv GEMM: 64co x 64px tile, 8co x 4px/thr, FFMA2 -----
__global__ void __launch_bounds__(128) conv1x1_kernel(
    const float* __restrict__ in, const float* __restrict__ w,
    const float* __restrict__ bias, float* __restrict__ out,
    int Ci, int Co, int P, int relu_in, int add_res)
{
    __shared__ float w_s[16][64];
    __shared__ u64 x_s[16][64];
    const int tid = threadIdx.x;
    const int tx = tid & 15, ty = tid >> 4;   // ty: 8 co-groups of 8
    const int p0 = blockIdx.x * 64, c0 = blockIdx.y * 64, b = blockIdx.z;

    u64 acc[4][4];   // 4 co-pairs x 4 px
#pragma unroll
    for (int p = 0; p < 4; p++)
#pragma unroll
        for (int j = 0; j < 4; j++) acc[p][j] = 0ull;

    for (int ci0 = 0; ci0 < Ci; ci0 += 16) {
        for (int idx = tid; idx < 1024; idx += 128) {
            int pp = idx & 63, ci = idx >> 6;
            float v = in[(size_t)(b * Ci + ci0 + ci) * P + p0 + pp];
            x_s[ci][pp] = dup2(relu_in ? fmaxf(v, 0.f) : v);
        }
        for (int idx = tid; idx < 1024; idx += 128) {
            int ci = idx & 15, co = idx >> 4;
            w_s[ci][co] = w[(size_t)(c0 + co) * Ci + ci0 + ci];
        }
        __syncthreads();
#pragma unroll
        for (int ci = 0; ci < 16; ci++) {
            const ulonglong2 wa = *(const ulonglong2*)&w_s[ci][ty << 3];
            const ulonglong2 wb = *(const ulonglong2*)&w_s[ci][(ty << 3) + 4];
            const u64* xr = &x_s[ci][tx << 2];
#pragma unroll
            for (int j = 0; j < 4; j++) {
                const u64 xv = xr[j];
                fma2(acc[0][j], wa.x, xv);
                fma2(acc[1][j], wa.y, xv);
                fma2(acc[2][j], wb.x, xv);
                fma2(acc[3][j], wb.y, xv);
            }
        }
        __syncthreads();
    }
#pragma unroll
    for (int p = 0; p < 4; p++) {
        float2 u[4];
#pragma unroll
        for (int j = 0; j < 4; j++) u[j] = unpk(acc[p][j]);
#pragma unroll
        for (int h = 0; h < 2; h++) {
            const int co = c0 + (ty << 3) + 2 * p + h;
            const float bv = bias ? bias[co] : 0.f;
            const size_t base = (size_t)(b * Co + co) * P + p0 + (tx << 2);
            float4 o = h ? make_float4(u[0].y + bv, u[1].y + bv, u[2].y + bv, u[3].y + bv)
                         : make_float4(u[0].x + bv, u[1].x + bv, u[2].x + bv, u[3].x + bv);
            if (add_res) {
                float4 rr = *(const float4*)&out[base];
                o.x += rr.x; o.y += rr.y; o.z += rr.z; o.w += rr.w;
            }
            *(float4*)&out[base] = o;
        }
    }
}

// ---------------- VQ: chunked codebook, FFMA2 dots ---------------------------
__global__ void __launch_bounds__(256) vq_kernel(
    const float* __restrict__ ze, const float* __restrict__ emb,
    float* __restrict__ zq, float* __restrict__ loss)
{
    __shared__ float e_s[128 * 64];
    __shared__ float n_s[128];
    const int tid = threadIdx.x;
    const int n = blockIdx.x * 256 + tid;
    const int b = n >> 10, hw = n & 1023;

    u64 xr2[32];
#pragma unroll
    for (int d2 = 0; d2 < 32; d2++) {
        float a = ze[((size_t)(b * 64 + 2 * d2) << 10) + hw];
        float c = ze[((size_t)(b * 64 + 2 * d2 + 1) << 10) + hw];
        xr2[d2] = pack2(a, c);
    }

    float best = 3.4e38f;
    int bi = 0;
    for (int kb = 0; kb < 4; kb++) {
        __syncthreads();
        for (int i = tid; i < 128 * 64; i += 256) e_s[i] = emb[kb * 128 * 64 + i];
        __syncthreads();
        if (tid < 128) {
            float s = 0.f;
#pragma unroll 8
            for (int d = 0; d < 64; d++) { float v = e_s[tid * 64 + d]; s = fmaf(v, v, s); }
            n_s[tid] = s;
        }
        __syncthreads();
        for (int k = 0; k < 128; k++) {
            const u64* e2 = (const u64*)(e_s + k * 64);
            u64 dd[4] = {0ull, 0ull, 0ull, 0ull};
#pragma unroll
            for (int d8 = 0; d8 < 8; d8++)
#pragma unroll
                for (int uu = 0; uu < 4; uu++)
                    fma2(dd[uu], e2[d8 * 4 + uu], xr2[d8 * 4 + uu]);
            float2 s0 = unpk(dd[0]), s1 = unpk(dd[1]), s2 = unpk(dd[2]), s3 = unpk(dd[3]);
            float dot = ((s0.x + s0.y) + (s1.x + s1.y)) + ((s2.x + s2.y) + (s3.x + s3.y));
            float dist = n_s[k] - 2.f * dot;
            if (dist < best) { best = dist; bi = kb * 128 + k; }
        }
    }

    float ls = 0.f;
#pragma unroll
    for (int d2 = 0; d2 < 32; d2++) {
        float2 xv = unpk(xr2[d2]);
        float e0 = emb[bi * 64 + 2 * d2], e1 = emb[bi * 64 + 2 * d2 + 1];
        zq[((size_t)(b * 64 + 2 * d2) << 10) + hw] = e0;
        zq[((size_t)(b * 64 + 2 * d2 + 1) << 10) + hw] = e1;
        float f0 = e0 - xv.x, f1 = e1 - xv.y;
        ls = fmaf(f0, f0, ls);
        ls = fmaf(f1, f1, ls);
    }
#pragma unroll
    for (int o = 16; o > 0; o >>= 1) ls += __shfl_down_sync(0xffffffffu, ls, o);
    if ((tid & 31) == 0) atomicAdd(loss, ls);
}

// ---------------- conv-transpose k4 s2 p1 (parity quads), FFMA2 -------------
template <int CO_TILE, int CO_PT, int M_TILE, int N_TILE>
__global__ void __launch_bounds__(256) tconv_kernel(
    const float* __restrict__ in, const float* __restrict__ w,
    const float* __restrict__ bias, float* __restrict__ out,
    int Ci, int Co, int Hi, int Wi, int relu_in, int relu_out)
{
    constexpr int NSLOT = (M_TILE * N_TILE) / 4;
    constexpr int CG = CO_TILE / CO_PT;
    constexpr int CPAIR = CO_PT / 2;
    static_assert(NSLOT * CG == 256, "map");
    static_assert(CO_PT % 2 == 0, "pairs");
    __shared__ float w_s[4][16][CO_TILE];
    __shared__ u64 x_s[4][M_TILE + 2][N_TILE + 2];

    const int tid = threadIdx.x;
    const int slot = tid % NSLOT, cg = tid / NSLOT;
    const int m_loc = slot / (N_TILE / 4);
    const int nb = (slot % (N_TILE / 4)) * 4;
    const int n0 = blockIdx.x * N_TILE, m0 = blockIdx.y * M_TILE;
    const int cot = (Co + CO_TILE - 1) / CO_TILE;
    const int b = blockIdx.z / cot, c0 = (blockIdx.z % cot) * CO_TILE;
    const int Ho = 2 * Hi, Wo2 = 2 * Wi;

    u64 acc[CPAIR][4][2][2];
#pragma unroll
    for (int p = 0; p < CPAIR; p++)
#pragma unroll
        for (int q = 0; q < 4; q++)
#pragma unroll
            for (int a = 0; a < 2; a++)
#pragma unroll
                for (int bb = 0; bb < 2; bb++) acc[p][q][a][bb] = 0ull;

    for (int ci0 = 0; ci0 < Ci; ci0 += 4) {
        for (int idx = tid; idx < 4 * (M_TILE + 2) * (N_TILE + 2); idx += 256) {
            int lc = idx % (N_TILE + 2);
            int t = idx / (N_TILE + 2);
            int lr = t % (M_TILE + 2), ci = t / (M_TILE + 2);
            int m = m0 - 1 + lr, nn = n0 - 1 + lc;
            float v = 0.f;
            if ((unsigned)m < (unsigned)Hi && (unsigned)nn < (unsigned)Wi)
                v = in[((size_t)(b * Ci + ci0 + ci) * Hi + m) * Wi + nn];
            if (relu_in) v = fmaxf(v, 0.f);
            x_s[ci][lr][lc] = dup2(v);
        }
        for (int idx = tid; idx < 4 * 16 * CO_TILE; idx += 256) {
            int t = idx & 15;
            int co = (idx >> 4) % CO_TILE;
            int ci = idx / (16 * CO_TILE);
            float v = 0.f;
            if (c0 + co < Co) v = w[((size_t)(ci0 + ci) * Co + c0 + co) * 16 + t];
            w_s[ci][t][co] = v;
        }
        __syncthreads();
#pragma unroll
        for (int ci = 0; ci < 4; ci++)
#pragma unroll
            for (int t = 0; t < 16; t++) {
                const int kh = t >> 2, kw = t & 3;
                const int a = 1 - (kh & 1);
                const int dm = (kh == 0) ? 1 : ((kh == 3) ? -1 : 0);
                const int bb = 1 - (kw & 1);
                const int dn = (kw == 0) ? 1 : ((kw == 3) ? -1 : 0);
                const u64* wrow = (const u64*)&w_s[ci][t][cg * CO_PT];
                u64 wp[CPAIR];
#pragma unroll
                for (int p = 0; p < CPAIR; p++) wp[p] = wrow[p];
                const u64* xrow = &x_s[ci][m_loc + dm + 1][nb + dn + 1];
#pragma unroll
                for (int q = 0; q < 4; q++) {
                    const u64 xv = xrow[q];
#pragma unroll
                    for (int p = 0; p < CPAIR; p++)
                        fma2(acc[p][q][a][bb], wp[p], xv);
                }
            }
        __syncthreads();
    }

    const int m = m0 + m_loc;
#pragma unroll
    for (int p = 0; p < CPAIR; p++)
#pragma unroll
        for (int h = 0; h < 2; h++) {
            const int co = c0 + cg * CO_PT + 2 * p + h;
            if (co < Co) {
                const float bv = bias[co];
#pragma unroll
                for (int q = 0; q < 4; q++) {
                    const int nn = n0 + nb + q;
#pragma unroll
                    for (int a = 0; a < 2; a++) {
                        float2 u0 = unpk(acc[p][q][a][0]);
                        float2 u1 = unpk(acc[p][q][a][1]);
                        float2 o = h ? make_float2(u0.y + bv, u1.y + bv)
                                     : make_float2(u0.x + bv, u1.x + bv);
                        if (relu_out) { o.x = fmaxf(o.x, 0.f); o.y = fmaxf(o.y, 0.f); }
                        *(float2*)&out[((size_t)(b * Co + co) * Ho + 2 * m + a) * Wo2 + 2 * nn] = o;
                    }
                }
            }
        }
}

__global__ void zero_loss_kernel(float* loss) { loss[0] = 0.f; }
__global__ void finish_loss_kernel(const float* __restrict__ loss, float* __restrict__ dst)
{
    dst[0] = 2.f * loss[0] / 2097152.f;
}

// ---------------------------------------------------------------------------
extern "C" void kernel_launch(void* const* d_in, const int* in_sizes, int n_in,
                              void* d_out, int out_size)
{
    (void)in_sizes; (void)n_in;
    const float* x       = (const float*)d_in[0];
    const float* enc_w1  = (const float*)d_in[1];
    const float* enc_b1  = (const float*)d_in[2];
    const float* enc_w2  = (const float*)d_in[3];
    const float* enc_b2  = (const float*)d_in[4];
    const float* enc_w3  = (const float*)d_in[5];
    const float* enc_b3  = (const float*)d_in[6];
    const float* enc_rw3 = (const float*)d_in[7];
    const float* enc_rw1 = (const float*)d_in[8];
    const float* prevq_w = (const float*)d_in[9];
    const float* prevq_b = (const float*)d_in[10];
    const float* emb     = (const float*)d_in[11];
    const float* dec_w1  = (const float*)d_in[12];
    const float* dec_b1  = (const float*)d_in[13];
    const float* dec_rw3 = (const float*)d_in[14];
    const float* dec_rw1 = (const float*)d_in[15];
    const float* dec_w2  = (const float*)d_in[16];
    const float* dec_b2  = (const float*)d_in[17];
    const float* dec_w3  = (const float*)d_in[18];
    const float* dec_b3  = (const float*)d_in[19];
    float* out = (float*)d_out;

    float *b0, *b1, *b2, *b3, *ze, *zq, *loss;
    cudaGetSymbolAddress((void**)&b0, g_b0);
    cudaGetSymbolAddress((void**)&b1, g_b1);
    cudaGetSymbolAddress((void**)&b2, g_b2);
    cudaGetSymbolAddress((void**)&b3, g_b3);
    cudaGetSymbolAddress((void**)&ze, g_ze);
    cudaGetSymbolAddress((void**)&zq, g_zq);
    cudaGetSymbolAddress((void**)&loss, g_loss);

    // ---- encoder ----
    conv4s2_kernel<<<dim3(4, 64, 32), 256>>>(x, enc_w1, enc_b1, b0, 3, 128, 256, 256, 128, 128, 1);
    conv4s2_kernel<<<dim3(2, 32, 64), 256>>>(b0, enc_w2, enc_b2, b1, 128, 256, 128, 128, 64, 64, 1);
    conv4s2_kernel<<<dim3(1, 16, 128), 256>>>(b1, enc_w3, enc_b3, b2, 256, 512, 64, 64, 32, 32, 0);
    for (int l = 0; l < 2; l++) {
        conv3x3_kernel<8><<<dim3(4, 4, 32), 128>>>(b2, enc_rw3, b3, 512, 32);
        conv1x1_kernel<<<dim3(16, 8, 32), 128>>>(b3, enc_rw1, nullptr, b2, 32, 512, 1024, 1, 1);
    }
    conv1x1_kernel<<<dim3(16, 1, 32), 128>>>(b2, prevq_w, prevq_b, ze, 512, 64, 1024, 1, 0);

    // ---- VQ ----
    zero_loss_kernel<<<1, 1>>>(loss);
    vq_kernel<<<128, 256>>>(ze, emb, zq, loss);
    finish_loss_kernel<<<1, 1>>>(loss, out + (out_size - 1));

    // ---- decoder ----
    tconv_kernel<64, 4, 8, 8><<<dim3(4, 4, 128), 256>>>(zq, dec_w1, dec_b1, b1, 64, 256, 32, 32, 0, 0);
    for (int l = 0; l < 2; l++) {
        conv3x3_kernel<16><<<dim3(4, 8, 32), 256>>>(b1, dec_rw3, b3, 256, 64);
        conv1x1_kernel<<<dim3(64, 4, 32), 128>>>(b3, dec_rw1, nullptr, b1, 32, 256, 4096, 1, 1);
    }
    tconv_kernel<64, 4, 8, 8><<<dim3(8, 8, 64), 256>>>(b1, dec_w2, dec_b2, b0, 256, 128, 64, 64, 1, 1);
    tconv_kernel<4, 2, 16, 32><<<dim3(4, 8, 32), 256>>>(b0, dec_w3, dec_b3, out, 128, 3, 128, 128, 0, 0);
}

// round 4
// speedup vs baseline: 2.2203x; 2.2203x over previous
#include <cuda_runtime.h>

typedef unsigned int u32;

__device__ float g_b0[32u * 128 * 128 * 128];
__device__ float g_b1[32u * 256 * 64 * 64];
__device__ float g_b2[32u * 512 * 32 * 32];
__device__ float g_b3[32u * 32 * 64 * 64];
__device__ float g_ze[32u * 64 * 32 * 32];
__device__ float g_zq[32u * 64 * 32 * 32];
__device__ float g_loss[1];
__device__ u32   g_wt[2097152];   // transposed tf32 weights [K][Co]

__device__ __forceinline__ u32 cvt_tf32(float f) {
    u32 r; asm("cvt.rna.tf32.f32 %0,%1;" : "=r"(r) : "f"(f)); return r;
}

// ===========================================================================
// fp32 kernels (round-2 proven versions)
// ===========================================================================

__global__ void __launch_bounds__(256) conv4s2_kernel(
    const float* __restrict__ in, const float* __restrict__ w,
    const float* __restrict__ bias, float* __restrict__ out,
    int Ci, int Co, int Hi, int Wi, int Ho, int Wo, int relu)
{
    __shared__ float w_s[2][16][128];
    __shared__ float x_s[2][6][66];
    const int tid = threadIdx.x;
    const int wx = tid & 7, cy = tid >> 3;
    const int w0 = blockIdx.x * 32, oh0 = blockIdx.y * 2;
    const int cot = Co >> 7;
    const int b = blockIdx.z / cot, c0 = (blockIdx.z % cot) << 7;
    const int ihb = 4 * (int)blockIdx.y - 1, iwb = 2 * w0 - 1;

    float acc[2][4][4];
#pragma unroll
    for (int r = 0; r < 2; r++)
#pragma unroll
        for (int i = 0; i < 4; i++)
#pragma unroll
            for (int j = 0; j < 4; j++) acc[r][i][j] = 0.f;

    for (int ci0 = 0; ci0 < Ci; ci0 += 2) {
        const int cik = min(2, Ci - ci0);
        for (int idx = tid; idx < cik * 6 * 66; idx += 256) {
            int lc = idx % 66, t = idx / 66, lr = t % 6, ci = t / 6;
            int ih = ihb + lr, iw = iwb + lc;
            float v = 0.f;
            if ((unsigned)ih < (unsigned)Hi && (unsigned)iw < (unsigned)Wi)
                v = in[((size_t)(b * Ci + ci0 + ci) * Hi + ih) * Wi + iw];
            x_s[ci][lr][lc] = v;
        }
        for (int idx = tid; idx < cik * 16 * 128; idx += 256) {
            int t = idx & 15, co = (idx >> 4) & 127, ci = idx >> 11;
            w_s[ci][t][co] = w[((size_t)(c0 + co) * Ci + ci0 + ci) * 16 + t];
        }
        __syncthreads();
        for (int ci = 0; ci < cik; ci++) {
#pragma unroll
            for (int kh = 0; kh < 4; kh++)
#pragma unroll
                for (int kw = 0; kw < 4; kw++) {
                    const float4 wv = *(const float4*)&w_s[ci][(kh << 2) + kw][cy << 2];
                    const float wvv[4] = {wv.x, wv.y, wv.z, wv.w};
#pragma unroll
                    for (int r = 0; r < 2; r++) {
                        const float* xr = &x_s[ci][2 * r + kh][(wx << 3) + kw];
                        const float xv[4] = {xr[0], xr[2], xr[4], xr[6]};
#pragma unroll
                        for (int i = 0; i < 4; i++)
#pragma unroll
                            for (int j = 0; j < 4; j++)
                                acc[r][i][j] = fmaf(wvv[i], xv[j], acc[r][i][j]);
                    }
                }
        }
        __syncthreads();
    }
#pragma unroll
    for (int i = 0; i < 4; i++) {
        const int co = c0 + (cy << 2) + i;
        const float bv = bias ? bias[co] : 0.f;
#pragma unroll
        for (int r = 0; r < 2; r++) {
            float4 o = {acc[r][i][0] + bv, acc[r][i][1] + bv,
                        acc[r][i][2] + bv, acc[r][i][3] + bv};
            if (relu) {
                o.x = fmaxf(o.x, 0.f); o.y = fmaxf(o.y, 0.f);
                o.z = fmaxf(o.z, 0.f); o.w = fmaxf(o.w, 0.f);
            }
            *(float4*)&out[((size_t)(b * Co + co) * Ho + oh0 + r) * Wo + w0 + (wx << 2)] = o;
        }
    }
}

__global__ void __launch_bounds__(256) conv3x3_kernel(
    const float* __restrict__ in, const float* __restrict__ w,
    float* __restrict__ out, int Ci, int HW)
{
    __shared__ float w_s[4][9][32];
    __shared__ float x_s[4][10][18];
    const int tid = threadIdx.x;
    const int s = tid & 31, g = tid >> 5;
    const int r = s >> 2, cb = (s & 3) << 2;
    const int ow0 = blockIdx.x * 16, oh0 = blockIdx.y * 8, b = blockIdx.z;

    float acc[4][4];
#pragma unroll
    for (int i = 0; i < 4; i++)
#pragma unroll
        for (int j = 0; j < 4; j++) acc[i][j] = 0.f;

    for (int ci0 = 0; ci0 < Ci; ci0 += 4) {
        for (int idx = tid; idx < 720; idx += 256) {
            int lc = idx % 18, t = idx / 18, lr = t % 10, ci = t / 10;
            int ih = oh0 - 1 + lr, iw = ow0 - 1 + lc;
            float v = 0.f;
            if ((unsigned)ih < (unsigned)HW && (unsigned)iw < (unsigned)HW)
                v = in[((size_t)(b * Ci + ci0 + ci) * HW + ih) * HW + iw];
            x_s[ci][lr][lc] = fmaxf(v, 0.f);
        }
        for (int idx = tid; idx < 1152; idx += 256) {
            int t = idx % 9, q = idx / 9, ci = q & 3, co = q >> 2;
            w_s[ci][t][co] = w[((size_t)co * Ci + ci0 + ci) * 9 + t];
        }
        __syncthreads();
#pragma unroll
        for (int ci = 0; ci < 4; ci++)
#pragma unroll
            for (int kh = 0; kh < 3; kh++)
#pragma unroll
                for (int kw = 0; kw < 3; kw++) {
                    const float4 wv = *(const float4*)&w_s[ci][kh * 3 + kw][g << 2];
                    const float wvv[4] = {wv.x, wv.y, wv.z, wv.w};
                    const float* xr = &x_s[ci][r + kh][cb + kw];
                    const float xv[4] = {xr[0], xr[1], xr[2], xr[3]};
#pragma unroll
                    for (int i = 0; i < 4; i++)
#pragma unroll
                        for (int j = 0; j < 4; j++)
                            acc[i][j] = fmaf(wvv[i], xv[j], acc[i][j]);
                }
        __syncthreads();
    }
#pragma unroll
    for (int i = 0; i < 4; i++) {
        float4 o = {acc[i][0], acc[i][1], acc[i][2], acc[i][3]};
        *(float4*)&out[(((size_t)b * 32 + (g << 2) + i) * HW + oh0 + r) * HW + ow0 + cb] = o;
    }
}

__global__ void __launch_bounds__(256) conv1x1_kernel(
    const float* __restrict__ in, const float* __restrict__ w,
    const float* __restrict__ bias, float* __restrict__ out,
    int Ci, int Co, int P, int relu_in, int add_res)
{
    __shared__ float w_s[16][64];
    __shared__ float x_s[16][64];
    const int tid = threadIdx.x;
    const int tx = tid & 15, ty = tid >> 4;
    const int p0 = blockIdx.x * 64, c0 = blockIdx.y * 64, b = blockIdx.z;

    float acc[4][4];
#pragma unroll
    for (int i = 0; i < 4; i++)
#pragma unroll
        for (int j = 0; j < 4; j++) acc[i][j] = 0.f;

    for (int ci0 = 0; ci0 < Ci; ci0 += 16) {
        for (int idx = tid; idx < 1024; idx += 256) {
            int p = idx & 63, ci = idx >> 6;
            float v = in[(size_t)(b * Ci + ci0 + ci) * P + p0 + p];
            x_s[ci][p] = relu_in ? fmaxf(v, 0.f) : v;
        }
        for (int idx = tid; idx < 1024; idx += 256) {
            int ci = idx & 15, co = idx >> 4;
            w_s[ci][co] = w[(size_t)(c0 + co) * Ci + ci0 + ci];
        }
        __syncthreads();
#pragma unroll
        for (int ci = 0; ci < 16; ci++) {
            const float4 wv = *(const float4*)&w_s[ci][ty << 2];
            const float4 xv = *(const float4*)&x_s[ci][tx << 2];
            const float wvv[4] = {wv.x, wv.y, wv.z, wv.w};
            const float xvv[4] = {xv.x, xv.y, xv.z, xv.w};
#pragma unroll
            for (int i = 0; i < 4; i++)
#pragma unroll
                for (int j = 0; j < 4; j++)
                    acc[i][j] = fmaf(wvv[i], xvv[j], acc[i][j]);
        }
        __syncthreads();
    }
#pragma unroll
    for (int i = 0; i < 4; i++) {
        const int co = c0 + (ty << 2) + i;
        const float bv = bias ? bias[co] : 0.f;
        const size_t base = (size_t)(b * Co + co) * P + p0 + (tx << 2);
        float4 o = {acc[i][0] + bv, acc[i][1] + bv, acc[i][2] + bv, acc[i][3] + bv};
        if (add_res) {
            float4 rr = *(const float4*)&out[base];
            o.x += rr.x; o.y += rr.y; o.z += rr.z; o.w += rr.w;
        }
        *(float4*)&out[base] = o;
    }
}

__global__ void __launch_bounds__(256) vq_kernel(
    const float* __restrict__ ze, const float* __restrict__ emb,
    float* __restrict__ zq, float* __restrict__ loss)
{
    __shared__ float e_s[128 * 64];
    __shared__ float n_s[128];
    const int tid = threadIdx.x;
    const int n = blockIdx.x * 256 + tid;
    const int b = n >> 10, hw = n & 1023;

    float xr[64];
#pragma unroll
    for (int d = 0; d < 64; d++)
        xr[d] = ze[((size_t)(b * 64 + d) << 10) + hw];

    float best = 3.4e38f;
    int bi = 0;
    for (int kb = 0; kb < 4; kb++) {
        __syncthreads();
        for (int i = tid; i < 128 * 64; i += 256) e_s[i] = emb[kb * 128 * 64 + i];
        __syncthreads();
        if (tid < 128) {
            float s = 0.f;
#pragma unroll 8
            for (int d = 0; d < 64; d++) { float v = e_s[tid * 64 + d]; s = fmaf(v, v, s); }
            n_s[tid] = s;
        }
        __syncthreads();
        for (int k = 0; k < 128; k++) {
            const float4* e4 = (const float4*)(e_s + k * 64);
            float dot = 0.f;
#pragma unroll
            for (int d4 = 0; d4 < 16; d4++) {
                float4 e = e4[d4];
                dot = fmaf(e.x, xr[d4 * 4 + 0], dot);
                dot = fmaf(e.y, xr[d4 * 4 + 1], dot);
                dot = fmaf(e.z, xr[d4 * 4 + 2], dot);
                dot = fmaf(e.w, xr[d4 * 4 + 3], dot);
            }
            float dist = n_s[k] - 2.f * dot;
            if (dist < best) { best = dist; bi = kb * 128 + k; }
        }
    }

    float ls = 0.f;
#pragma unroll
    for (int d = 0; d < 64; d++) {
        float e = emb[bi * 64 + d];
        zq[((size_t)(b * 64 + d) << 10) + hw] = e;
        float df = e - xr[d];
        ls = fmaf(df, df, ls);
    }
#pragma unroll
    for (int o = 16; o > 0; o >>= 1) ls += __shfl_down_sync(0xffffffffu, ls, o);
    if ((tid & 31) == 0) atomicAdd(loss, ls);
}

template <int CO_TILE, int CO_PT, int M_TILE, int N_TILE>
__global__ void __launch_bounds__(256) tconv_kernel(
    const float* __restrict__ in, const float* __restrict__ w,
    const float* __restrict__ bias, float* __restrict__ out,
    int Ci, int Co, int Hi, int Wi, int relu_in, int relu_out)
{
    constexpr int NSLOT = (M_TILE * N_TILE) / 4;
    constexpr int CG = CO_TILE / CO_PT;
    static_assert(NSLOT * CG == 256, "map");
    __shared__ float w_s[4][16][CO_TILE];
    __shared__ float x_s[4][M_TILE + 2][N_TILE + 2];

    const int tid = threadIdx.x;
    const int slot = tid % NSLOT, cg = tid / NSLOT;
    const int m_loc = slot / (N_TILE / 4);
    const int nb = (slot % (N_TILE / 4)) * 4;
    const int n0 = blockIdx.x * N_TILE, m0 = blockIdx.y * M_TILE;
    const int cot = (Co + CO_TILE - 1) / CO_TILE;
    const int b = blockIdx.z / cot, c0 = (blockIdx.z % cot) * CO_TILE;
    const int Ho = 2 * Hi, Wo2 = 2 * Wi;

    float acc[CO_PT][4][2][2];
#pragma unroll
    for (int i = 0; i < CO_PT; i++)
#pragma unroll
        for (int q = 0; q < 4; q++)
#pragma unroll
            for (int a = 0; a < 2; a++)
#pragma unroll
                for (int bb = 0; bb < 2; bb++) acc[i][q][a][bb] = 0.f;

    for (int ci0 = 0; ci0 < Ci; ci0 += 4) {
        for (int idx = tid; idx < 4 * (M_TILE + 2) * (N_TILE + 2); idx += 256) {
            int lc = idx % (N_TILE + 2);
            int t = idx / (N_TILE + 2);
            int lr = t % (M_TILE + 2), ci = t / (M_TILE + 2);
            int m = m0 - 1 + lr, nn = n0 - 1 + lc;
            float v = 0.f;
            if ((unsigned)m < (unsigned)Hi && (unsigned)nn < (unsigned)Wi)
                v = in[((size_t)(b * Ci + ci0 + ci) * Hi + m) * Wi + nn];
            if (relu_in) v = fmaxf(v, 0.f);
            x_s[ci][lr][lc] = v;
        }
        for (int idx = tid; idx < 4 * 16 * CO_TILE; idx += 256) {
            int t = idx & 15;
            int co = (idx >> 4) % CO_TILE;
            int ci = idx / (16 * CO_TILE);
            float v = 0.f;
            if (c0 + co < Co) v = w[((size_t)(ci0 + ci) * Co + c0 + co) * 16 + t];
            w_s[ci][t][co] = v;
        }
        __syncthreads();
#pragma unroll
        for (int ci = 0; ci < 4; ci++)
#pragma unroll
            for (int t = 0; t < 16; t++) {
                const int kh = t >> 2, kw = t & 3;
                const int a = 1 - (kh & 1);
                const int dm = (kh == 0) ? 1 : ((kh == 3) ? -1 : 0);
                const int bb = 1 - (kw & 1);
                const int dn = (kw == 0) ? 1 : ((kw == 3) ? -1 : 0);
                float wr[CO_PT];
#pragma unroll
                for (int i = 0; i < CO_PT; i++)
                    wr[i] = w_s[ci][t][cg * CO_PT + i];
                const float* xrow = &x_s[ci][m_loc + dm + 1][nb + dn + 1];
#pragma unroll
                for (int q = 0; q < 4; q++) {
                    const float xv = xrow[q];
#pragma unroll
                    for (int i = 0; i < CO_PT; i++)
                        acc[i][q][a][bb] = fmaf(wr[i], xv, acc[i][q][a][bb]);
                }
            }
        __syncthreads();
    }

    const int m = m0 + m_loc;
#pragma unroll
    for (int i = 0; i < CO_PT; i++) {
        const int co = c0 + cg * CO_PT + i;
        if (co < Co) {
            const float bv = bias[co];
#pragma unroll
            for (int q = 0; q < 4; q++) {
                const int nn = n0 + nb + q;
#pragma unroll
                for (int a = 0; a < 2; a++) {
                    float2 o = {acc[i][q][a][0] + bv, acc[i][q][a][1] + bv};
                    if (relu_out) { o.x = fmaxf(o.x, 0.f); o.y = fmaxf(o.y, 0.f); }
                    *(float2*)&out[((size_t)(b * Co + co) * Ho + 2 * m + a) * Wo2 + 2 * nn] = o;
                }
            }
        }
    }
}

__global__ void zero_loss_kernel(float* loss) { loss[0] = 0.f; }
__global__ void finish_loss_kernel(const float* __restrict__ loss, float* __restrict__ dst)
{
    dst[0] = 2.f * loss[0] / 2097152.f;
}

// ===========================================================================
// tf32 tensor-core path
// ===========================================================================

// transpose k4s2 weights: w[Co][Ci][16] -> wT[k=ci*16+t][Co] (tf32)
__global__ void wt4s2_kernel(const float* __restrict__ w, u32* __restrict__ wT,
                             int Ci, int Co)
{
    int idx = blockIdx.x * 256 + threadIdx.x;
    if (idx >= Ci * 16 * Co) return;
    int co = idx % Co, k = idx / Co;
    int ci = k >> 4, t = k & 15;
    wT[idx] = cvt_tf32(w[((size_t)co * Ci + ci) * 16 + t]);
}

// transpose tconv weights per parity: w[Ci][Co][4][4] ->
// wT[p=(a*2+b)][k=ci*4+j][Co], j=(jh*2+jw), kh=(1-a)+2jh, kw=(1-b)+2jw
__global__ void wtT_kernel(const float* __restrict__ w, u32* __restrict__ wT,
                           int Ci, int Co)
{
    int idx = blockIdx.x * 256 + threadIdx.x;
    int K = Ci * 4;
    if (idx >= 4 * K * Co) return;
    int co = idx % Co, kk = idx / Co;
    int p = kk / K, r = kk % K;
    int ci = r >> 2, j = r & 3;
    int a = p >> 1, bb = p & 1;
    int kh = (1 - a) + 2 * (j >> 1);
    int kw = (1 - bb) + 2 * (j & 1);
    wT[idx] = cvt_tf32(w[((size_t)ci * Co + co) * 16 + kh * 4 + kw]);
}

#define MMA_TF32(d, a0, a1, a2, a3, b0, b1)                                   \
    asm volatile("mma.sync.aligned.m16n8k8.row.col.f32.tf32.tf32.f32 "        \
                 "{%0,%1,%2,%3},{%4,%5,%6,%7},{%8,%9},{%0,%1,%2,%3};"         \
                 : "+f"(d[0]), "+f"(d[1]), "+f"(d[2]), "+f"(d[3])             \
                 : "r"(a0), "r"(a1), "r"(a2), "r"(a3), "r"(b0), "r"(b1))

// conv k4 s2 p1 as implicit GEMM. Block: 128 Co x 128 px, 256 thr (8 warps).
__global__ void __launch_bounds__(256) conv4s2_tc(
    const float* __restrict__ in, const u32* __restrict__ wT,
    const float* __restrict__ bias, float* __restrict__ out,
    int Ci, int Co, int Hi, int Wi, int Ho, int Wo, int owt_shift, int relu)
{
    __shared__ u32 A_s[32][136];
    __shared__ u32 B_s[32][136];
    const int tid = threadIdx.x;
    const int lane = tid & 31, warp = tid >> 5;
    const int gid = lane >> 2, tig = lane & 3;
    const int m0w = (warp & 3) * 32, n0w = (warp >> 2) * 64;
    const int OWT = 1 << owt_shift;
    const int OHT = 128 >> owt_shift;
    const int ow0 = blockIdx.x * OWT, oh0 = blockIdx.y * OHT;
    const int cot = Co >> 7;
    const int b = blockIdx.z / cot, c0 = (blockIdx.z % cot) << 7;
    const int K = Ci << 4;

    // B staging: thread covers k = tid>>3, n = (tid&7)*16 .. +15 (same row)
    const int sk = tid >> 3;
    const int sn0 = (tid & 7) << 4;
    const int s_ohl = sn0 >> owt_shift;
    const int s_owl = sn0 & (OWT - 1);

    float acc[2][8][4];
#pragma unroll
    for (int mi = 0; mi < 2; mi++)
#pragma unroll
        for (int ni = 0; ni < 8; ni++)
#pragma unroll
            for (int c = 0; c < 4; c++) acc[mi][ni][c] = 0.f;

    for (int k0g = 0; k0g < K; k0g += 32) {
        // A: coalesced uint4 from pre-transposed wT
        for (int idx = tid; idx < 1024; idx += 256) {
            int kk = idx >> 5, m4 = idx & 31;
            uint4 v = *(const uint4*)&wT[(size_t)(k0g + kk) * Co + c0 + (m4 << 2)];
            *(uint4*)&A_s[kk][m4 << 2] = v;
        }
        // B: im2col gather
        {
            const int kg = k0g + sk;
            const int ci = kg >> 4, t = kg & 15, kh = t >> 2, kw = t & 3;
            const int ih = 2 * (oh0 + s_ohl) - 1 + kh;
            const bool okr = (unsigned)ih < (unsigned)Hi;
            const float* row = in + ((size_t)(b * Ci + ci) * Hi + ih) * Wi;
            const int iwb = 2 * (ow0 + s_owl) - 1 + kw;
#pragma unroll
            for (int j = 0; j < 16; j++) {
                const int iw = iwb + 2 * j;
                float v = (okr && (unsigned)iw < (unsigned)Wi) ? row[iw] : 0.f;
                B_s[sk][sn0 + j] = cvt_tf32(v);
            }
        }
        __syncthreads();
#pragma unroll
        for (int s = 0; s < 4; s++) {
            const int kk = s * 8;
            u32 a[2][4], bf[8][2];
#pragma unroll
            for (int mi = 0; mi < 2; mi++) {
                a[mi][0] = A_s[kk + tig][m0w + mi * 16 + gid];
                a[mi][1] = A_s[kk + tig][m0w + mi * 16 + gid + 8];
                a[mi][2] = A_s[kk + tig + 4][m0w + mi * 16 + gid];
                a[mi][3] = A_s[kk + tig + 4][m0w + mi * 16 + gid + 8];
            }
#pragma unroll
            for (int ni = 0; ni < 8; ni++) {
                bf[ni][0] = B_s[kk + tig][n0w + ni * 8 + gid];
                bf[ni][1] = B_s[kk + tig + 4][n0w + ni * 8 + gid];
            }
#pragma unroll
            for (int mi = 0; mi < 2; mi++)
#pragma unroll
                for (int ni = 0; ni < 8; ni++)
                    MMA_TF32(acc[mi][ni], a[mi][0], a[mi][1], a[mi][2], a[mi][3],
                             bf[ni][0], bf[ni][1]);
        }
        __syncthreads();
    }

#pragma unroll
    for (int mi = 0; mi < 2; mi++)
#pragma unroll
        for (int h = 0; h < 2; h++) {
            const int co = c0 + m0w + mi * 16 + gid + h * 8;
            const float bv = bias[co];
#pragma unroll
            for (int ni = 0; ni < 8; ni++) {
                const int n = n0w + ni * 8 + 2 * tig;
                const int ohl = n >> owt_shift, owl = n & (OWT - 1);
                float2 o = {acc[mi][ni][h * 2] + bv, acc[mi][ni][h * 2 + 1] + bv};
                if (relu) { o.x = fmaxf(o.x, 0.f); o.y = fmaxf(o.y, 0.f); }
                *(float2*)&out[((size_t)(b * Co + co) * Ho + oh0 + ohl) * Wo + ow0 + owl] = o;
            }
        }
}

// conv-transpose k4 s2 p1, per-parity implicit GEMM (K = 4*Ci).
__global__ void __launch_bounds__(256) tconv_tc(
    const float* __restrict__ in, const u32* __restrict__ wT,
    const float* __restrict__ bias, float* __restrict__ out,
    int Ci, int Co, int Hi, int Wi, int owt_shift, int relu_in, int relu_out)
{
    __shared__ u32 A_s[32][136];
    __shared__ u32 B_s[32][136];
    const int tid = threadIdx.x;
    const int lane = tid & 31, warp = tid >> 5;
    const int gid = lane >> 2, tig = lane & 3;
    const int m0w = (warp & 3) * 32, n0w = (warp >> 2) * 64;
    const int OWT = 1 << owt_shift;
    const int OHT = 128 >> owt_shift;
    const int ow0 = blockIdx.x * OWT, oh0 = blockIdx.y * OHT;
    const int p = blockIdx.z & 3;
    const int rest = blockIdx.z >> 2;
    const int cot = Co >> 7;
    const int b = rest / cot, c0 = (rest % cot) << 7;
    const int pa = p >> 1, pb = p & 1;
    const int K = Ci << 2;
    const int Ho = 2 * Hi, Wo2 = 2 * Wi;
    const u32* wTp = wT + (size_t)p * K * Co;

    const int sk = tid >> 3;
    const int sn0 = (tid & 7) << 4;
    const int s_ohl = sn0 >> owt_shift;
    const int s_owl = sn0 & (OWT - 1);

    float acc[2][8][4];
#pragma unroll
    for (int mi = 0; mi < 2; mi++)
#pragma unroll
        for (int ni = 0; ni < 8; ni++)
#pragma unroll
            for (int c = 0; c < 4; c++) acc[mi][ni][c] = 0.f;

    for (int k0g = 0; k0g < K; k0g += 32) {
        for (int idx = tid; idx < 1024; idx += 256) {
            int kk = idx >> 5, m4 = idx & 31;
            uint4 v = *(const uint4*)&wTp[(size_t)(k0g + kk) * Co + c0 + (m4 << 2)];
            *(uint4*)&A_s[kk][m4 << 2] = v;
        }
        {
            const int kg = k0g + sk;
            const int ci = kg >> 2, j = kg & 3;
            const int kh = (1 - pa) + 2 * (j >> 1);
            const int kw = (1 - pb) + 2 * (j & 1);
            const int dm = (kh == 0) ? 1 : ((kh == 3) ? -1 : 0);
            const int dn = (kw == 0) ? 1 : ((kw == 3) ? -1 : 0);
            const int ih = oh0 + s_ohl + dm;
            const bool okr = (unsigned)ih < (unsigned)Hi;
            const float* row = in + ((size_t)(b * Ci + ci) * Hi + ih) * Wi;
            const int iwb = ow0 + s_owl + dn;
#pragma unroll
            for (int jj = 0; jj < 16; jj++) {
                const int iw = iwb + jj;
                float v = (okr && (unsigned)iw < (unsigned)Wi) ? row[iw] : 0.f;
                if (relu_in) v = fmaxf(v, 0.f);
                B_s[sk][sn0 + jj] = cvt_tf32(v);
            }
        }
        __syncthreads();
#pragma unroll
        for (int s = 0; s < 4; s++) {
            const int kk = s * 8;
            u32 a[2][4], bf[8][2];
#pragma unroll
            for (int mi = 0; mi < 2; mi++) {
                a[mi][0] = A_s[kk + tig][m0w + mi * 16 + gid];
                a[mi][1] = A_s[kk + tig][m0w + mi * 16 + gid + 8];
                a[mi][2] = A_s[kk + tig + 4][m0w + mi * 16 + gid];
                a[mi][3] = A_s[kk + tig + 4][m0w + mi * 16 + gid + 8];
            }
#pragma unroll
            for (int ni = 0; ni < 8; ni++) {
                bf[ni][0] = B_s[kk + tig][n0w + ni * 8 + gid];
                bf[ni][1] = B_s[kk + tig + 4][n0w + ni * 8 + gid];
            }
#pragma unroll
            for (int mi = 0; mi < 2; mi++)
#pragma unroll
                for (int ni = 0; ni < 8; ni++)
                    MMA_TF32(acc[mi][ni], a[mi][0], a[mi][1], a[mi][2], a[mi][3],
                             bf[ni][0], bf[ni][1]);
        }
        __syncthreads();
    }

#pragma unroll
    for (int mi = 0; mi < 2; mi++)
#pragma unroll
        for (int h = 0; h < 2; h++) {
            const int co = c0 + m0w + mi * 16 + gid + h * 8;
            const float bv = bias[co];
#pragma unroll
            for (int ni = 0; ni < 8; ni++) {
                const int n = n0w + ni * 8 + 2 * tig;
                const int mh = oh0 + (n >> owt_shift);
                const int mw = ow0 + (n & (OWT - 1));
                float v0 = acc[mi][ni][h * 2] + bv;
                float v1 = acc[mi][ni][h * 2 + 1] + bv;
                if (relu_out) { v0 = fmaxf(v0, 0.f); v1 = fmaxf(v1, 0.f); }
                float* orow = &out[((size_t)(b * Co + co) * Ho + 2 * mh + pa) * Wo2];
                orow[2 * mw + pb] = v0;
                orow[2 * (mw + 1) + pb] = v1;
            }
        }
}

// ===========================================================================
extern "C" void kernel_launch(void* const* d_in, const int* in_sizes, int n_in,
                              void* d_out, int out_size)
{
    (void)in_sizes; (void)n_in;
    const float* x       = (const float*)d_in[0];
    const float* enc_w1  = (const float*)d_in[1];
    const float* enc_b1  = (const float*)d_in[2];
    const float* enc_w2  = (const float*)d_in[3];
    const float* enc_b2  = (const float*)d_in[4];
    const float* enc_w3  = (const float*)d_in[5];
    const float* enc_b3  = (const float*)d_in[6];
    const float* enc_rw3 = (const float*)d_in[7];
    const float* enc_rw1 = (const float*)d_in[8];
    const float* prevq_w = (const float*)d_in[9];
    const float* prevq_b = (const float*)d_in[10];
    const float* emb     = (const float*)d_in[11];
    const float* dec_w1  = (const float*)d_in[12];
    const float* dec_b1  = (const float*)d_in[13];
    const float* dec_rw3 = (const float*)d_in[14];
    const float* dec_rw1 = (const float*)d_in[15];
    const float* dec_w2  = (const float*)d_in[16];
    const float* dec_b2  = (const float*)d_in[17];
    const float* dec_w3  = (const float*)d_in[18];
    const float* dec_b3  = (const float*)d_in[19];
    float* out = (float*)d_out;

    float *b0, *b1, *b2, *b3, *ze, *zq, *loss;
    u32* wt;
    cudaGetSymbolAddress((void**)&b0, g_b0);
    cudaGetSymbolAddress((void**)&b1, g_b1);
    cudaGetSymbolAddress((void**)&b2, g_b2);
    cudaGetSymbolAddress((void**)&b3, g_b3);
    cudaGetSymbolAddress((void**)&ze, g_ze);
    cudaGetSymbolAddress((void**)&zq, g_zq);
    cudaGetSymbolAddress((void**)&loss, g_loss);
    cudaGetSymbolAddress((void**)&wt, g_wt);

    // ---- encoder ----
    conv4s2_kernel<<<dim3(4, 64, 32), 256>>>(x, enc_w1, enc_b1, b0, 3, 128, 256, 256, 128, 128, 1);

    wt4s2_kernel<<<2048, 256>>>(enc_w2, wt, 128, 256);
    conv4s2_tc<<<dim3(1, 32, 64), 256>>>(b0, wt, enc_b2, b1, 128, 256, 128, 128, 64, 64, 6, 1);

    wt4s2_kernel<<<8192, 256>>>(enc_w3, wt, 256, 512);
    conv4s2_tc<<<dim3(1, 8, 128), 256>>>(b1, wt, enc_b3, b2, 256, 512, 64, 64, 32, 32, 5, 0);

    for (int l = 0; l < 2; l++) {
        conv3x3_kernel<<<dim3(2, 4, 32), 256>>>(b2, enc_rw3, b3, 512, 32);
        conv1x1_kernel<<<dim3(16, 8, 32), 256>>>(b3, enc_rw1, nullptr, b2, 32, 512, 1024, 1, 1);
    }
    conv1x1_kernel<<<dim3(16, 1, 32), 256>>>(b2, prevq_w, prevq_b, ze, 512, 64, 1024, 1, 0);

    // ---- VQ ----
    zero_loss_kernel<<<1, 1>>>(loss);
    vq_kernel<<<128, 256>>>(ze, emb, zq, loss);
    finish_loss_kernel<<<1, 1>>>(loss, out + (out_size - 1));

    // ---- decoder ----
    wtT_kernel<<<1024, 256>>>(dec_w1, wt, 64, 256);
    tconv_tc<<<dim3(1, 8, 256), 256>>>(zq, wt, dec_b1, b1, 64, 256, 32, 32, 5, 0, 0);

    for (int l = 0; l < 2; l++) {
        conv3x3_kernel<<<dim3(4, 8, 32), 256>>>(b1, dec_rw3, b3, 256, 64);
        conv1x1_kernel<<<dim3(64, 4, 32), 256>>>(b3, dec_rw1, nullptr, b1, 32, 256, 4096, 1, 1);
    }

    wtT_kernel<<<2048, 256>>>(dec_w2, wt, 256, 128);
    tconv_tc<<<dim3(1, 32, 128), 256>>>(b1, wt, dec_b2, b0, 256, 128, 64, 64, 6, 1, 1);

    tconv_kernel<4, 1, 16, 16><<<dim3(8, 8, 32), 256>>>(b0, dec_w3, dec_b3, out, 128, 3, 128, 128, 0, 0);
}

// round 5
// speedup vs baseline: 3.3178x; 1.4943x over previous
#include <cuda_runtime.h>

typedef unsigned int u32;

__device__ float g_b0[32u * 128 * 128 * 128];
__device__ float g_b1[32u * 256 * 64 * 64];
__device__ float g_b2[32u * 512 * 32 * 32];
__device__ float g_b3[32u * 32 * 64 * 64];
__device__ float g_ze[32u * 64 * 32 * 32];
__device__ float g_zq[32u * 64 * 32 * 32];
__device__ float g_loss[1];
__device__ u32   g_wt[2097152];   // packed fp16x2 weights [K/2][Co]

__device__ __forceinline__ u32 pack_f16x2(float lo, float hi) {
    u32 r; asm("cvt.rn.f16x2.f32 %0,%1,%2;" : "=r"(r) : "f"(hi), "f"(lo)); return r;
}

#define MMA_F16(d, a0, a1, a2, a3, b0, b1)                                    \
    asm volatile("mma.sync.aligned.m16n8k16.row.col.f32.f16.f16.f32 "         \
                 "{%0,%1,%2,%3},{%4,%5,%6,%7},{%8,%9},{%0,%1,%2,%3};"         \
                 : "+f"(d[0]), "+f"(d[1]), "+f"(d[2]), "+f"(d[3])             \
                 : "r"(a0), "r"(a1), "r"(a2), "r"(a3), "r"(b0), "r"(b1))

// ===========================================================================
// fp32 kernels (proven)
// ===========================================================================

__global__ void __launch_bounds__(256) conv4s2_kernel(
    const float* __restrict__ in, const float* __restrict__ w,
    const float* __restrict__ bias, float* __restrict__ out,
    int Ci, int Co, int Hi, int Wi, int Ho, int Wo, int relu)
{
    __shared__ float w_s[2][16][128];
    __shared__ float x_s[2][6][66];
    const int tid = threadIdx.x;
    const int wx = tid & 7, cy = tid >> 3;
    const int w0 = blockIdx.x * 32, oh0 = blockIdx.y * 2;
    const int cot = Co >> 7;
    const int b = blockIdx.z / cot, c0 = (blockIdx.z % cot) << 7;
    const int ihb = 4 * (int)blockIdx.y - 1, iwb = 2 * w0 - 1;

    float acc[2][4][4];
#pragma unroll
    for (int r = 0; r < 2; r++)
#pragma unroll
        for (int i = 0; i < 4; i++)
#pragma unroll
            for (int j = 0; j < 4; j++) acc[r][i][j] = 0.f;

    for (int ci0 = 0; ci0 < Ci; ci0 += 2) {
        const int cik = min(2, Ci - ci0);
        for (int idx = tid; idx < cik * 6 * 66; idx += 256) {
            int lc = idx % 66, t = idx / 66, lr = t % 6, ci = t / 6;
            int ih = ihb + lr, iw = iwb + lc;
            float v = 0.f;
            if ((unsigned)ih < (unsigned)Hi && (unsigned)iw < (unsigned)Wi)
                v = in[((size_t)(b * Ci + ci0 + ci) * Hi + ih) * Wi + iw];
            x_s[ci][lr][lc] = v;
        }
        for (int idx = tid; idx < cik * 16 * 128; idx += 256) {
            int t = idx & 15, co = (idx >> 4) & 127, ci = idx >> 11;
            w_s[ci][t][co] = w[((size_t)(c0 + co) * Ci + ci0 + ci) * 16 + t];
        }
        __syncthreads();
        for (int ci = 0; ci < cik; ci++) {
#pragma unroll
            for (int kh = 0; kh < 4; kh++)
#pragma unroll
                for (int kw = 0; kw < 4; kw++) {
                    const float4 wv = *(const float4*)&w_s[ci][(kh << 2) + kw][cy << 2];
                    const float wvv[4] = {wv.x, wv.y, wv.z, wv.w};
#pragma unroll
                    for (int r = 0; r < 2; r++) {
                        const float* xr = &x_s[ci][2 * r + kh][(wx << 3) + kw];
                        const float xv[4] = {xr[0], xr[2], xr[4], xr[6]};
#pragma unroll
                        for (int i = 0; i < 4; i++)
#pragma unroll
                            for (int j = 0; j < 4; j++)
                                acc[r][i][j] = fmaf(wvv[i], xv[j], acc[r][i][j]);
                    }
                }
        }
        __syncthreads();
    }
#pragma unroll
    for (int i = 0; i < 4; i++) {
        const int co = c0 + (cy << 2) + i;
        const float bv = bias ? bias[co] : 0.f;
#pragma unroll
        for (int r = 0; r < 2; r++) {
            float4 o = {acc[r][i][0] + bv, acc[r][i][1] + bv,
                        acc[r][i][2] + bv, acc[r][i][3] + bv};
            if (relu) {
                o.x = fmaxf(o.x, 0.f); o.y = fmaxf(o.y, 0.f);
                o.z = fmaxf(o.z, 0.f); o.w = fmaxf(o.w, 0.f);
            }
            *(float4*)&out[((size_t)(b * Co + co) * Ho + oh0 + r) * Wo + w0 + (wx << 2)] = o;
        }
    }
}

__global__ void __launch_bounds__(256) conv1x1_kernel(
    const float* __restrict__ in, const float* __restrict__ w,
    const float* __restrict__ bias, float* __restrict__ out,
    int Ci, int Co, int P, int relu_in, int add_res)
{
    __shared__ float w_s[16][64];
    __shared__ float x_s[16][64];
    const int tid = threadIdx.x;
    const int tx = tid & 15, ty = tid >> 4;
    const int p0 = blockIdx.x * 64, c0 = blockIdx.y * 64, b = blockIdx.z;

    float acc[4][4];
#pragma unroll
    for (int i = 0; i < 4; i++)
#pragma unroll
        for (int j = 0; j < 4; j++) acc[i][j] = 0.f;

    for (int ci0 = 0; ci0 < Ci; ci0 += 16) {
        for (int idx = tid; idx < 1024; idx += 256) {
            int p = idx & 63, ci = idx >> 6;
            float v = in[(size_t)(b * Ci + ci0 + ci) * P + p0 + p];
            x_s[ci][p] = relu_in ? fmaxf(v, 0.f) : v;
        }
        for (int idx = tid; idx < 1024; idx += 256) {
            int ci = idx & 15, co = idx >> 4;
            w_s[ci][co] = w[(size_t)(c0 + co) * Ci + ci0 + ci];
        }
        __syncthreads();
#pragma unroll
        for (int ci = 0; ci < 16; ci++) {
            const float4 wv = *(const float4*)&w_s[ci][ty << 2];
            const float4 xv = *(const float4*)&x_s[ci][tx << 2];
            const float wvv[4] = {wv.x, wv.y, wv.z, wv.w};
            const float xvv[4] = {xv.x, xv.y, xv.z, xv.w};
#pragma unroll
            for (int i = 0; i < 4; i++)
#pragma unroll
                for (int j = 0; j < 4; j++)
                    acc[i][j] = fmaf(wvv[i], xvv[j], acc[i][j]);
        }
        __syncthreads();
    }
#pragma unroll
    for (int i = 0; i < 4; i++) {
        const int co = c0 + (ty << 2) + i;
        const float bv = bias ? bias[co] : 0.f;
        const size_t base = (size_t)(b * Co + co) * P + p0 + (tx << 2);
        float4 o = {acc[i][0] + bv, acc[i][1] + bv, acc[i][2] + bv, acc[i][3] + bv};
        if (add_res) {
            float4 rr = *(const float4*)&out[base];
            o.x += rr.x; o.y += rr.y; o.z += rr.z; o.w += rr.w;
        }
        *(float4*)&out[base] = o;
    }
}

__global__ void __launch_bounds__(256) vq_kernel(
    const float* __restrict__ ze, const float* __restrict__ emb,
    float* __restrict__ zq, float* __restrict__ loss)
{
    __shared__ float e_s[128 * 64];
    __shared__ float n_s[128];
    const int tid = threadIdx.x;
    const int n = blockIdx.x * 256 + tid;
    const int b = n >> 10, hw = n & 1023;

    float xr[64];
#pragma unroll
    for (int d = 0; d < 64; d++)
        xr[d] = ze[((size_t)(b * 64 + d) << 10) + hw];

    float best = 3.4e38f;
    int bi = 0;
    for (int kb = 0; kb < 4; kb++) {
        __syncthreads();
        for (int i = tid; i < 128 * 64; i += 256) e_s[i] = emb[kb * 128 * 64 + i];
        __syncthreads();
        if (tid < 128) {
            float s = 0.f;
#pragma unroll 8
            for (int d = 0; d < 64; d++) { float v = e_s[tid * 64 + d]; s = fmaf(v, v, s); }
            n_s[tid] = s;
        }
        __syncthreads();
        for (int k = 0; k < 128; k++) {
            const float4* e4 = (const float4*)(e_s + k * 64);
            float dot = 0.f;
#pragma unroll
            for (int d4 = 0; d4 < 16; d4++) {
                float4 e = e4[d4];
                dot = fmaf(e.x, xr[d4 * 4 + 0], dot);
                dot = fmaf(e.y, xr[d4 * 4 + 1], dot);
                dot = fmaf(e.z, xr[d4 * 4 + 2], dot);
                dot = fmaf(e.w, xr[d4 * 4 + 3], dot);
            }
            float dist = n_s[k] - 2.f * dot;
            if (dist < best) { best = dist; bi = kb * 128 + k; }
        }
    }

    float ls = 0.f;
#pragma unroll
    for (int d = 0; d < 64; d++) {
        float e = emb[bi * 64 + d];
        zq[((size_t)(b * 64 + d) << 10) + hw] = e;
        float df = e - xr[d];
        ls = fmaf(df, df, ls);
    }
#pragma unroll
    for (int o = 16; o > 0; o >>= 1) ls += __shfl_down_sync(0xffffffffu, ls, o);
    if ((tid & 31) == 0) atomicAdd(loss, ls);
}

template <int CO_TILE, int CO_PT, int M_TILE, int N_TILE>
__global__ void __launch_bounds__(256) tconv_kernel(
    const float* __restrict__ in, const float* __restrict__ w,
    const float* __restrict__ bias, float* __restrict__ out,
    int Ci, int Co, int Hi, int Wi, int relu_in, int relu_out)
{
    constexpr int NSLOT = (M_TILE * N_TILE) / 4;
    constexpr int CG = CO_TILE / CO_PT;
    static_assert(NSLOT * CG == 256, "map");
    __shared__ float w_s[4][16][CO_TILE];
    __shared__ float x_s[4][M_TILE + 2][N_TILE + 2];

    const int tid = threadIdx.x;
    const int slot = tid % NSLOT, cg = tid / NSLOT;
    const int m_loc = slot / (N_TILE / 4);
    const int nb = (slot % (N_TILE / 4)) * 4;
    const int n0 = blockIdx.x * N_TILE, m0 = blockIdx.y * M_TILE;
    const int cot = (Co + CO_TILE - 1) / CO_TILE;
    const int b = blockIdx.z / cot, c0 = (blockIdx.z % cot) * CO_TILE;
    const int Ho = 2 * Hi, Wo2 = 2 * Wi;

    float acc[CO_PT][4][2][2];
#pragma unroll
    for (int i = 0; i < CO_PT; i++)
#pragma unroll
        for (int q = 0; q < 4; q++)
#pragma unroll
            for (int a = 0; a < 2; a++)
#pragma unroll
                for (int bb = 0; bb < 2; bb++) acc[i][q][a][bb] = 0.f;

    for (int ci0 = 0; ci0 < Ci; ci0 += 4) {
        for (int idx = tid; idx < 4 * (M_TILE + 2) * (N_TILE + 2); idx += 256) {
            int lc = idx % (N_TILE + 2);
            int t = idx / (N_TILE + 2);
            int lr = t % (M_TILE + 2), ci = t / (M_TILE + 2);
            int m = m0 - 1 + lr, nn = n0 - 1 + lc;
            float v = 0.f;
            if ((unsigned)m < (unsigned)Hi && (unsigned)nn < (unsigned)Wi)
                v = in[((size_t)(b * Ci + ci0 + ci) * Hi + m) * Wi + nn];
            if (relu_in) v = fmaxf(v, 0.f);
            x_s[ci][lr][lc] = v;
        }
        for (int idx = tid; idx < 4 * 16 * CO_TILE; idx += 256) {
            int t = idx & 15;
            int co = (idx >> 4) % CO_TILE;
            int ci = idx / (16 * CO_TILE);
            float v = 0.f;
            if (c0 + co < Co) v = w[((size_t)(ci0 + ci) * Co + c0 + co) * 16 + t];
            w_s[ci][t][co] = v;
        }
        __syncthreads();
#pragma unroll
        for (int ci = 0; ci < 4; ci++)
#pragma unroll
            for (int t = 0; t < 16; t++) {
                const int kh = t >> 2, kw = t & 3;
                const int a = 1 - (kh & 1);
                const int dm = (kh == 0) ? 1 : ((kh == 3) ? -1 : 0);
                const int bb = 1 - (kw & 1);
                const int dn = (kw == 0) ? 1 : ((kw == 3) ? -1 : 0);
                float wr[CO_PT];
#pragma unroll
                for (int i = 0; i < CO_PT; i++)
                    wr[i] = w_s[ci][t][cg * CO_PT + i];
                const float* xrow = &x_s[ci][m_loc + dm + 1][nb + dn + 1];
#pragma unroll
                for (int q = 0; q < 4; q++) {
                    const float xv = xrow[q];
#pragma unroll
                    for (int i = 0; i < CO_PT; i++)
                        acc[i][q][a][bb] = fmaf(wr[i], xv, acc[i][q][a][bb]);
                }
            }
        __syncthreads();
    }

    const int m = m0 + m_loc;
#pragma unroll
    for (int i = 0; i < CO_PT; i++) {
        const int co = c0 + cg * CO_PT + i;
        if (co < Co) {
            const float bv = bias[co];
#pragma unroll
            for (int q = 0; q < 4; q++) {
                const int nn = n0 + nb + q;
#pragma unroll
                for (int a = 0; a < 2; a++) {
                    float2 o = {acc[i][q][a][0] + bv, acc[i][q][a][1] + bv};
                    if (relu_out) { o.x = fmaxf(o.x, 0.f); o.y = fmaxf(o.y, 0.f); }
                    *(float2*)&out[((size_t)(b * Co + co) * Ho + 2 * m + a) * Wo2 + 2 * nn] = o;
                }
            }
        }
    }
}

__global__ void zero_loss_kernel(float* loss) { loss[0] = 0.f; }
__global__ void finish_loss_kernel(const float* __restrict__ loss, float* __restrict__ dst)
{
    dst[0] = 2.f * loss[0] / 2097152.f;
}

// ===========================================================================
// fp16 tensor-core path (m16n8k16, fp32 accum)
// ===========================================================================

// k4s2 weights: w[Co][Ci][16] -> wT2[k2][Co] half2 (k = ci*16+t, pairs along t)
__global__ void wt4s2_f16(const float* __restrict__ w, u32* __restrict__ wT2,
                          int Ci, int Co)
{
    int idx = blockIdx.x * 256 + threadIdx.x;
    if (idx >= Ci * 8 * Co) return;
    int co = idx % Co, k2 = idx / Co;
    int k = 2 * k2, ci = k >> 4, t = k & 15;
    const float* base = &w[((size_t)co * Ci + ci) * 16 + t];
    wT2[idx] = pack_f16x2(base[0], base[1]);
}

// tconv weights per parity: w[Ci][Co][4][4] -> wT2[p][k2][Co] (k = ci*4+j)
__global__ void wtT_f16(const float* __restrict__ w, u32* __restrict__ wT2,
                        int Ci, int Co)
{
    int K2 = Ci * 2;
    int idx = blockIdx.x * 256 + threadIdx.x;
    if (idx >= 4 * K2 * Co) return;
    int co = idx % Co, rr = idx / Co;
    int p = rr / K2, k2 = rr % K2;
    int k = 2 * k2, ci = k >> 2, j = k & 3;
    int a = p >> 1, bb = p & 1;
    int kh = (1 - a) + 2 * (j >> 1);
    int kw_lo = 1 - bb, kw_hi = 3 - bb;
    const float* base = &w[((size_t)ci * Co + co) * 16 + kh * 4];
    wT2[idx] = pack_f16x2(base[kw_lo], base[kw_hi]);
}

// 3x3 weights: w[32][Ci][9] -> wT2[k2][32] (k = ci*9+t; pairs may cross ci)
__global__ void wt3_f16(const float* __restrict__ w, u32* __restrict__ wT2, int Ci)
{
    int K = Ci * 9;
    int idx = blockIdx.x * 256 + threadIdx.x;
    if (idx >= (K / 2) * 32) return;
    int co = idx & 31, k2 = idx >> 5;
    int k0 = 2 * k2, k1 = k0 + 1;
    int ci0 = k0 / 9, t0 = k0 - ci0 * 9;
    int ci1 = k1 / 9, t1 = k1 - ci1 * 9;
    float v0 = w[((size_t)co * Ci + ci0) * 9 + t0];
    float v1 = w[((size_t)co * Ci + ci1) * 9 + t1];
    wT2[idx] = pack_f16x2(v0, v1);
}

// conv k4 s2 p1, fp16 implicit GEMM. 128 Co x 128 px, K-chunk 64.
__global__ void __launch_bounds__(256) conv4s2_tcf(
    const float* __restrict__ in, const u32* __restrict__ wT2,
    const float* __restrict__ bias, float* __restrict__ out,
    int Ci, int Co, int Hi, int Wi, int Ho, int Wo, int owt_shift, int relu)
{
    __shared__ u32 A_s[32][136];
    __shared__ u32 B_s[32][136];
    const int tid = threadIdx.x;
    const int lane = tid & 31, warp = tid >> 5;
    const int gid = lane >> 2, tig = lane & 3;
    const int m0w = (warp & 3) * 32, n0w = (warp >> 2) * 64;
    const int OWT = 1 << owt_shift;
    const int ow0 = blockIdx.x * OWT, oh0 = blockIdx.y * (128 >> owt_shift);
    const int cot = Co >> 7;
    const int b = blockIdx.z / cot, c0 = (blockIdx.z % cot) << 7;
    const int K = Ci << 4;

    const int sk = tid >> 3;                 // k2-row 0..31
    const int sn0 = (tid & 7) << 4;          // 16 n per thread
    const int s_ohl = sn0 >> owt_shift;
    const int s_owl = sn0 & (OWT - 1);

    float acc[2][8][4];
#pragma unroll
    for (int mi = 0; mi < 2; mi++)
#pragma unroll
        for (int ni = 0; ni < 8; ni++)
#pragma unroll
            for (int c = 0; c < 4; c++) acc[mi][ni][c] = 0.f;

    for (int k0 = 0; k0 < K; k0 += 64) {
        const int k02 = k0 >> 1;
        for (int idx = tid; idx < 1024; idx += 256) {
            int kk = idx >> 5, m4 = idx & 31;
            uint4 v = *(const uint4*)&wT2[(size_t)(k02 + kk) * Co + c0 + (m4 << 2)];
            *(uint4*)&A_s[kk][m4 << 2] = v;
        }
        {
            const int kg = k0 + 2 * sk;
            const int ci = kg >> 4, t = kg & 15, kh = t >> 2, kw = t & 3;
            const int ih = 2 * (oh0 + s_ohl) - 1 + kh;
            const bool okr = (unsigned)ih < (unsigned)Hi;
            const float* row = in + ((size_t)(b * Ci + ci) * Hi + ih) * Wi;
            const int iwb = 2 * (ow0 + s_owl) - 1 + kw;
#pragma unroll
            for (int j = 0; j < 16; j++) {
                const int iw = iwb + 2 * j;
                float v0 = (okr && (unsigned)iw < (unsigned)Wi) ? row[iw] : 0.f;
                float v1 = (okr && (unsigned)(iw + 1) < (unsigned)Wi) ? row[iw + 1] : 0.f;
                B_s[sk][sn0 + j] = pack_f16x2(v0, v1);
            }
        }
        __syncthreads();
#pragma unroll
        for (int s = 0; s < 4; s++) {
            const int k2b = s * 8;
            u32 a[2][4], bf[8][2];
#pragma unroll
            for (int mi = 0; mi < 2; mi++) {
                a[mi][0] = A_s[k2b + tig][m0w + mi * 16 + gid];
                a[mi][1] = A_s[k2b + tig][m0w + mi * 16 + gid + 8];
                a[mi][2] = A_s[k2b + tig + 4][m0w + mi * 16 + gid];
                a[mi][3] = A_s[k2b + tig + 4][m0w + mi * 16 + gid + 8];
            }
#pragma unroll
            for (int ni = 0; ni < 8; ni++) {
                bf[ni][0] = B_s[k2b + tig][n0w + ni * 8 + gid];
                bf[ni][1] = B_s[k2b + tig + 4][n0w + ni * 8 + gid];
            }
#pragma unroll
            for (int mi = 0; mi < 2; mi++)
#pragma unroll
                for (int ni = 0; ni < 8; ni++)
                    MMA_F16(acc[mi][ni], a[mi][0], a[mi][1], a[mi][2], a[mi][3],
                            bf[ni][0], bf[ni][1]);
        }
        __syncthreads();
    }

#pragma unroll
    for (int mi = 0; mi < 2; mi++)
#pragma unroll
        for (int h = 0; h < 2; h++) {
            const int co = c0 + m0w + mi * 16 + gid + h * 8;
            const float bv = bias[co];
#pragma unroll
            for (int ni = 0; ni < 8; ni++) {
                const int n = n0w + ni * 8 + 2 * tig;
                const int ohl = n >> owt_shift, owl = n & (OWT - 1);
                float2 o = {acc[mi][ni][h * 2] + bv, acc[mi][ni][h * 2 + 1] + bv};
                if (relu) { o.x = fmaxf(o.x, 0.f); o.y = fmaxf(o.y, 0.f); }
                *(float2*)&out[((size_t)(b * Co + co) * Ho + oh0 + ohl) * Wo + ow0 + owl] = o;
            }
        }
}

// conv-transpose k4 s2 p1, per-parity fp16 implicit GEMM (K = 4*Ci).
__global__ void __launch_bounds__(256) tconv_tcf(
    const float* __restrict__ in, const u32* __restrict__ wT2,
    const float* __restrict__ bias, float* __restrict__ out,
    int Ci, int Co, int Hi, int Wi, int owt_shift, int relu_in, int relu_out)
{
    __shared__ u32 A_s[32][136];
    __shared__ u32 B_s[32][136];
    const int tid = threadIdx.x;
    const int lane = tid & 31, warp = tid >> 5;
    const int gid = lane >> 2, tig = lane & 3;
    const int m0w = (warp & 3) * 32, n0w = (warp >> 2) * 64;
    const int OWT = 1 << owt_shift;
    const int ow0 = blockIdx.x * OWT, oh0 = blockIdx.y * (128 >> owt_shift);
    const int p = blockIdx.z & 3;
    const int rest = blockIdx.z >> 2;
    const int cot = Co >> 7;
    const int b = rest / cot, c0 = (rest % cot) << 7;
    const int pa = p >> 1, pb = p & 1;
    const int K = Ci << 2;
    const int K2 = Ci << 1;
    const int Ho = 2 * Hi, Wo2 = 2 * Wi;
    const u32* wTp = wT2 + (size_t)p * K2 * Co;

    const int sk = tid >> 3;
    const int sn0 = (tid & 7) << 4;
    const int s_ohl = sn0 >> owt_shift;
    const int s_owl = sn0 & (OWT - 1);

    const int kw_lo = 1 - pb, kw_hi = 3 - pb;
    const int dn_lo = (kw_lo == 0) ? 1 : 0;             // kw_lo in {0,1}
    const int dn_hi = (kw_hi == 3) ? -1 : 0;            // kw_hi in {2,3}

    float acc[2][8][4];
#pragma unroll
    for (int mi = 0; mi < 2; mi++)
#pragma unroll
        for (int ni = 0; ni < 8; ni++)
#pragma unroll
            for (int c = 0; c < 4; c++) acc[mi][ni][c] = 0.f;

    for (int k0 = 0; k0 < K; k0 += 64) {
        const int k02 = k0 >> 1;
        for (int idx = tid; idx < 1024; idx += 256) {
            int kk = idx >> 5, m4 = idx & 31;
            uint4 v = *(const uint4*)&wTp[(size_t)(k02 + kk) * Co + c0 + (m4 << 2)];
            *(uint4*)&A_s[kk][m4 << 2] = v;
        }
        {
            const int kg = k0 + 2 * sk;
            const int ci = kg >> 2, j = kg & 3;   // j in {0,2}
            const int kh = (1 - pa) + 2 * (j >> 1);
            const int dm = (kh == 0) ? 1 : ((kh == 3) ? -1 : 0);
            const int ih = oh0 + s_ohl + dm;
            const bool okr = (unsigned)ih < (unsigned)Hi;
            const float* row = in + ((size_t)(b * Ci + ci) * Hi + ih) * Wi;
            const int iwb = ow0 + s_owl;
#pragma unroll
            for (int jj = 0; jj < 16; jj++) {
                const int iw0 = iwb + jj + dn_lo;
                const int iw1 = iwb + jj + dn_hi;
                float v0 = (okr && (unsigned)iw0 < (unsigned)Wi) ? row[iw0] : 0.f;
                float v1 = (okr && (unsigned)iw1 < (unsigned)Wi) ? row[iw1] : 0.f;
                if (relu_in) { v0 = fmaxf(v0, 0.f); v1 = fmaxf(v1, 0.f); }
                B_s[sk][sn0 + jj] = pack_f16x2(v0, v1);
            }
        }
        __syncthreads();
#pragma unroll
        for (int s = 0; s < 4; s++) {
            const int k2b = s * 8;
            u32 a[2][4], bf[8][2];
#pragma unroll
            for (int mi = 0; mi < 2; mi++) {
                a[mi][0] = A_s[k2b + tig][m0w + mi * 16 + gid];
                a[mi][1] = A_s[k2b + tig][m0w + mi * 16 + gid + 8];
                a[mi][2] = A_s[k2b + tig + 4][m0w + mi * 16 + gid];
                a[mi][3] = A_s[k2b + tig + 4][m0w + mi * 16 + gid + 8];
            }
#pragma unroll
            for (int ni = 0; ni < 8; ni++) {
                bf[ni][0] = B_s[k2b + tig][n0w + ni * 8 + gid];
                bf[ni][1] = B_s[k2b + tig + 4][n0w + ni * 8 + gid];
            }
#pragma unroll
            for (int mi = 0; mi < 2; mi++)
#pragma unroll
                for (int ni = 0; ni < 8; ni++)
                    MMA_F16(acc[mi][ni], a[mi][0], a[mi][1], a[mi][2], a[mi][3],
                            bf[ni][0], bf[ni][1]);
        }
        __syncthreads();
    }

#pragma unroll
    for (int mi = 0; mi < 2; mi++)
#pragma unroll
        for (int h = 0; h < 2; h++) {
            const int co = c0 + m0w + mi * 16 + gid + h * 8;
            const float bv = bias[co];
#pragma unroll
            for (int ni = 0; ni < 8; ni++) {
                const int n = n0w + ni * 8 + 2 * tig;
                const int mh = oh0 + (n >> owt_shift);
                const int mw = ow0 + (n & (OWT - 1));
                float v0 = acc[mi][ni][h * 2] + bv;
                float v1 = acc[mi][ni][h * 2 + 1] + bv;
                if (relu_out) { v0 = fmaxf(v0, 0.f); v1 = fmaxf(v1, 0.f); }
                float* orow = &out[((size_t)(b * Co + co) * Ho + 2 * mh + pa) * Wo2];
                orow[2 * mw + pb] = v0;
                orow[2 * (mw + 1) + pb] = v1;
            }
        }
}

// 3x3 conv pad1, Co=32, fp16 TC, fused input relu. 32 co x 256 px tile.
__global__ void __launch_bounds__(256) conv3x3_tcf(
    const float* __restrict__ in, const u32* __restrict__ wT2,
    float* __restrict__ out, int Ci, int HW, int hw_shift)
{
    __shared__ u32 A_s[32][40];
    __shared__ u32 B_s[32][264];
    const int tid = threadIdx.x;
    const int lane = tid & 31, warp = tid >> 5;
    const int gid = lane >> 2, tig = lane & 3;
    const int n0w = warp * 32;
    const int p0 = blockIdx.x * 256;
    const int b = blockIdx.z;
    const int K = Ci * 9;

    const int sk = tid >> 3;
    const int sn0 = (tid & 7) << 5;          // 32 n per thread
    const int ng0 = p0 + sn0;
    const int s_oh = ng0 >> hw_shift;
    const int s_ow = ng0 & (HW - 1);

    float acc[2][4][4];
#pragma unroll
    for (int mi = 0; mi < 2; mi++)
#pragma unroll
        for (int ni = 0; ni < 4; ni++)
#pragma unroll
            for (int c = 0; c < 4; c++) acc[mi][ni][c] = 0.f;

    for (int k0 = 0; k0 < K; k0 += 64) {
        const int k02 = k0 >> 1;
        for (int idx = tid; idx < 1024; idx += 256) {
            int kk = idx >> 5, m = idx & 31;
            A_s[kk][m] = wT2[(size_t)(k02 + kk) * 32 + m];
        }
        {
            const int klo = k0 + 2 * sk, khi = klo + 1;
            const int ci0 = klo / 9, t0 = klo - ci0 * 9;
            const int ci1 = khi / 9, t1 = khi - ci1 * 9;
            const int kh0 = t0 / 3, kw0 = t0 - 3 * kh0;
            const int kh1 = t1 / 3, kw1 = t1 - 3 * kh1;
            const int ih0 = s_oh - 1 + kh0, ih1 = s_oh - 1 + kh1;
            const bool ok0 = (unsigned)ih0 < (unsigned)HW;
            const bool ok1 = (unsigned)ih1 < (unsigned)HW;
            const float* r0 = in + ((size_t)(b * Ci + ci0) * HW + ih0) * HW;
            const float* r1 = in + ((size_t)(b * Ci + ci1) * HW + ih1) * HW;
            const int iwb0 = s_ow - 1 + kw0, iwb1 = s_ow - 1 + kw1;
#pragma unroll
            for (int jj = 0; jj < 32; jj++) {
                const int iw0 = iwb0 + jj, iw1 = iwb1 + jj;
                float v0 = (ok0 && (unsigned)iw0 < (unsigned)HW) ? fmaxf(r0[iw0], 0.f) : 0.f;
                float v1 = (ok1 && (unsigned)iw1 < (unsigned)HW) ? fmaxf(r1[iw1], 0.f) : 0.f;
                B_s[sk][sn0 + jj] = pack_f16x2(v0, v1);
            }
        }
        __syncthreads();
#pragma unroll
        for (int s = 0; s < 4; s++) {
            const int k2b = s * 8;
            u32 a[2][4], bf[4][2];
#pragma unroll
            for (int mi = 0; mi < 2; mi++) {
                a[mi][0] = A_s[k2b + tig][mi * 16 + gid];
                a[mi][1] = A_s[k2b + tig][mi * 16 + gid + 8];
                a[mi][2] = A_s[k2b + tig + 4][mi * 16 + gid];
                a[mi][3] = A_s[k2b + tig + 4][mi * 16 + gid + 8];
            }
#pragma unroll
            for (int ni = 0; ni < 4; ni++) {
                bf[ni][0] = B_s[k2b + tig][n0w + ni * 8 + gid];
                bf[ni][1] = B_s[k2b + tig + 4][n0w + ni * 8 + gid];
            }
#pragma unroll
            for (int mi = 0; mi < 2; mi++)
#pragma unroll
                for (int ni = 0; ni < 4; ni++)
                    MMA_F16(acc[mi][ni], a[mi][0], a[mi][1], a[mi][2], a[mi][3],
                            bf[ni][0], bf[ni][1]);
        }
        __syncthreads();
    }

#pragma unroll
    for (int mi = 0; mi < 2; mi++)
#pragma unroll
        for (int h = 0; h < 2; h++) {
            const int co = mi * 16 + gid + h * 8;
#pragma unroll
            for (int ni = 0; ni < 4; ni++) {
                const int ng = p0 + n0w + ni * 8 + 2 * tig;
                const int oh = ng >> hw_shift, ow = ng & (HW - 1);
                float2 o = {acc[mi][ni][h * 2], acc[mi][ni][h * 2 + 1]};
                *(float2*)&out[((size_t)(b * 32 + co) * HW + oh) * HW + ow] = o;
            }
        }
}

// ===========================================================================
extern "C" void kernel_launch(void* const* d_in, const int* in_sizes, int n_in,
                              void* d_out, int out_size)
{
    (void)in_sizes; (void)n_in;
    const float* x       = (const float*)d_in[0];
    const float* enc_w1  = (const float*)d_in[1];
    const float* enc_b1  = (const float*)d_in[2];
    const float* enc_w2  = (const float*)d_in[3];
    const float* enc_b2  = (const float*)d_in[4];
    const float* enc_w3  = (const float*)d_in[5];
    const float* enc_b3  = (const float*)d_in[6];
    const float* enc_rw3 = (const float*)d_in[7];
    const float* enc_rw1 = (const float*)d_in[8];
    const float* prevq_w = (const float*)d_in[9];
    const float* prevq_b = (const float*)d_in[10];
    const float* emb     = (const float*)d_in[11];
    const float* dec_w1  = (const float*)d_in[12];
    const float* dec_b1  = (const float*)d_in[13];
    const float* dec_rw3 = (const float*)d_in[14];
    const float* dec_rw1 = (const float*)d_in[15];
    const float* dec_w2  = (const float*)d_in[16];
    const float* dec_b2  = (const float*)d_in[17];
    const float* dec_w3  = (const float*)d_in[18];
    const float* dec_b3  = (const float*)d_in[19];
    float* out = (float*)d_out;

    float *b0, *b1, *b2, *b3, *ze, *zq, *loss;
    u32* wt;
    cudaGetSymbolAddress((void**)&b0, g_b0);
    cudaGetSymbolAddress((void**)&b1, g_b1);
    cudaGetSymbolAddress((void**)&b2, g_b2);
    cudaGetSymbolAddress((void**)&b3, g_b3);
    cudaGetSymbolAddress((void**)&ze, g_ze);
    cudaGetSymbolAddress((void**)&zq, g_zq);
    cudaGetSymbolAddress((void**)&loss, g_loss);
    cudaGetSymbolAddress((void**)&wt, g_wt);

    // ---- encoder ----
    conv4s2_kernel<<<dim3(4, 64, 32), 256>>>(x, enc_w1, enc_b1, b0, 3, 128, 256, 256, 128, 128, 1);

    wt4s2_f16<<<1024, 256>>>(enc_w2, wt, 128, 256);
    conv4s2_tcf<<<dim3(1, 32, 64), 256>>>(b0, wt, enc_b2, b1, 128, 256, 128, 128, 64, 64, 6, 1);

    wt4s2_f16<<<4096, 256>>>(enc_w3, wt, 256, 512);
    conv4s2_tcf<<<dim3(1, 8, 128), 256>>>(b1, wt, enc_b3, b2, 256, 512, 64, 64, 32, 32, 5, 0);

    wt3_f16<<<288, 256>>>(enc_rw3, wt, 512);
    for (int l = 0; l < 2; l++) {
        conv3x3_tcf<<<dim3(4, 1, 32), 256>>>(b2, wt, b3, 512, 32, 5);
        conv1x1_kernel<<<dim3(16, 8, 32), 256>>>(b3, enc_rw1, nullptr, b2, 32, 512, 1024, 1, 1);
    }
    conv1x1_kernel<<<dim3(16, 1, 32), 256>>>(b2, prevq_w, prevq_b, ze, 512, 64, 1024, 1, 0);

    // ---- VQ ----
    zero_loss_kernel<<<1, 1>>>(loss);
    vq_kernel<<<128, 256>>>(ze, emb, zq, loss);
    finish_loss_kernel<<<1, 1>>>(loss, out + (out_size - 1));

    // ---- decoder ----
    wtT_f16<<<512, 256>>>(dec_w1, wt, 64, 256);
    tconv_tcf<<<dim3(1, 8, 256), 256>>>(zq, wt, dec_b1, b1, 64, 256, 32, 32, 5, 0, 0);

    wt3_f16<<<144, 256>>>(dec_rw3, wt, 256);
    for (int l = 0; l < 2; l++) {
        conv3x3_tcf<<<dim3(16, 1, 32), 256>>>(b1, wt, b3, 256, 64, 6);
        conv1x1_kernel<<<dim3(64, 4, 32), 256>>>(b3, dec_rw1, nullptr, b1, 32, 256, 4096, 1, 1);
    }

    wtT_f16<<<1024, 256>>>(dec_w2, wt, 256, 128);
    tconv_tcf<<<dim3(1, 32, 128), 256>>>(b1, wt, dec_b2, b0, 256, 128, 64, 64, 6, 1, 1);

    tconv_kernel<4, 1, 16, 16><<<dim3(8, 8, 32), 256>>>(b0, dec_w3, dec_b3, out, 128, 3, 128, 128, 0, 0);
}

// round 8
// speedup vs baseline: 4.6723x; 1.4083x over previous
#include <cuda_runtime.h>

typedef unsigned int u32;

__device__ float g_b0[32u * 128 * 128 * 128];
__device__ float g_b1[32u * 256 * 64 * 64];
__device__ float g_b2[32u * 512 * 32 * 32];
__device__ float g_b3[32u * 32 * 64 * 64];
__device__ float g_ze[32u * 64 * 32 * 32];
__device__ float g_zq[32u * 64 * 32 * 32];
__device__ float g_loss[1];
__device__ u32   g_wt[2097152];
__device__ u32   g_m0[35143680];   // enc2 mirror: 4096 x 130 x 132 halfs
__device__ u32   g_m1[18382848];   // enc3/dec2 mirror: 8192 x 66 x 68 halfs
__device__ u32   g_mq[1253376];    // dec1 mirror: 2048 x 34 x 36 halfs

__device__ __forceinline__ u32 pack_f16x2(float lo, float hi) {
    u32 r; asm("cvt.rn.f16x2.f32 %0,%1,%2;" : "=r"(r) : "f"(hi), "f"(lo)); return r;
}
__device__ __forceinline__ u32 prmt(u32 a, u32 b, u32 s) {
    u32 r; asm("prmt.b32 %0,%1,%2,%3;" : "=r"(r) : "r"(a), "r"(b), "r"(s)); return r;
}

#define MMA_F16(d, a0, a1, a2, a3, b0, b1)                                    \
    asm volatile("mma.sync.aligned.m16n8k16.row.col.f32.f16.f16.f32 "         \
                 "{%0,%1,%2,%3},{%4,%5,%6,%7},{%8,%9},{%0,%1,%2,%3};"         \
                 : "+f"(d[0]), "+f"(d[1]), "+f"(d[2]), "+f"(d[3])             \
                 : "r"(a0), "r"(a1), "r"(a2), "r"(a3), "r"(b0), "r"(b1))

// ---------------- mirror build: fp32 NCHW -> padded fp16 (pad=1 top/left) --
__global__ void cvt_mirror(const float* __restrict__ src, u32* __restrict__ dst,
                           int C, int Hi, int Wi, int Hp, int Wp2, int relu)
{
    int idx = blockIdx.x * 256 + threadIdx.x;
    if (idx >= C * Hp * Wp2) return;
    int wp2 = idx % Wp2, t = idx / Wp2;
    int ph = t % Hp, c = t / Hp;
    int ih = ph - 1;
    int iw0 = 2 * wp2 - 1, iw1 = iw0 + 1;
    float v0 = 0.f, v1 = 0.f;
    if ((unsigned)ih < (unsigned)Hi) {
        const float* r = src + ((size_t)c * Hi + ih) * Wi;
        if ((unsigned)iw0 < (unsigned)Wi) v0 = r[iw0];
        if ((unsigned)iw1 < (unsigned)Wi) v1 = r[iw1];
    }
    if (relu) { v0 = fmaxf(v0, 0.f); v1 = fmaxf(v1, 0.f); }
    dst[idx] = pack_f16x2(v0, v1);
}

// ===========================================================================
// fp32 kernels (proven)
// ===========================================================================

__global__ void __launch_bounds__(256) conv4s2_kernel(
    const float* __restrict__ in, const float* __restrict__ w,
    const float* __restrict__ bias, float* __restrict__ out,
    int Ci, int Co, int Hi, int Wi, int Ho, int Wo, int relu)
{
    __shared__ float w_s[2][16][128];
    __shared__ float x_s[2][6][66];
    const int tid = threadIdx.x;
    const int wx = tid & 7, cy = tid >> 3;
    const int w0 = blockIdx.x * 32, oh0 = blockIdx.y * 2;
    const int cot = Co >> 7;
    const int b = blockIdx.z / cot, c0 = (blockIdx.z % cot) << 7;
    const int ihb = 4 * (int)blockIdx.y - 1, iwb = 2 * w0 - 1;

    float acc[2][4][4];
#pragma unroll
    for (int r = 0; r < 2; r++)
#pragma unroll
        for (int i = 0; i < 4; i++)
#pragma unroll
            for (int j = 0; j < 4; j++) acc[r][i][j] = 0.f;

    for (int ci0 = 0; ci0 < Ci; ci0 += 2) {
        const int cik = min(2, Ci - ci0);
        for (int idx = tid; idx < cik * 6 * 66; idx += 256) {
            int lc = idx % 66, t = idx / 66, lr = t % 6, ci = t / 6;
            int ih = ihb + lr, iw = iwb + lc;
            float v = 0.f;
            if ((unsigned)ih < (unsigned)Hi && (unsigned)iw < (unsigned)Wi)
                v = in[((size_t)(b * Ci + ci0 + ci) * Hi + ih) * Wi + iw];
            x_s[ci][lr][lc] = v;
        }
        for (int idx = tid; idx < cik * 16 * 128; idx += 256) {
            int t = idx & 15, co = (idx >> 4) & 127, ci = idx >> 11;
            w_s[ci][t][co] = w[((size_t)(c0 + co) * Ci + ci0 + ci) * 16 + t];
        }
        __syncthreads();
        for (int ci = 0; ci < cik; ci++) {
#pragma unroll
            for (int kh = 0; kh < 4; kh++)
#pragma unroll
                for (int kw = 0; kw < 4; kw++) {
                    const float4 wv = *(const float4*)&w_s[ci][(kh << 2) + kw][cy << 2];
                    const float wvv[4] = {wv.x, wv.y, wv.z, wv.w};
#pragma unroll
                    for (int r = 0; r < 2; r++) {
                        const float* xr = &x_s[ci][2 * r + kh][(wx << 3) + kw];
                        const float xv[4] = {xr[0], xr[2], xr[4], xr[6]};
#pragma unroll
                        for (int i = 0; i < 4; i++)
#pragma unroll
                            for (int j = 0; j < 4; j++)
                                acc[r][i][j] = fmaf(wvv[i], xv[j], acc[r][i][j]);
                    }
                }
        }
        __syncthreads();
    }
#pragma unroll
    for (int i = 0; i < 4; i++) {
        const int co = c0 + (cy << 2) + i;
        const float bv = bias ? bias[co] : 0.f;
#pragma unroll
        for (int r = 0; r < 2; r++) {
            float4 o = {acc[r][i][0] + bv, acc[r][i][1] + bv,
                        acc[r][i][2] + bv, acc[r][i][3] + bv};
            if (relu) {
                o.x = fmaxf(o.x, 0.f); o.y = fmaxf(o.y, 0.f);
                o.z = fmaxf(o.z, 0.f); o.w = fmaxf(o.w, 0.f);
            }
            *(float4*)&out[((size_t)(b * Co + co) * Ho + oh0 + r) * Wo + w0 + (wx << 2)] = o;
        }
    }
}

__global__ void __launch_bounds__(256) conv1x1_kernel(
    const float* __restrict__ in, const float* __restrict__ w,
    const float* __restrict__ bias, float* __restrict__ out,
    int Ci, int Co, int P, int relu_in, int add_res)
{
    __shared__ float w_s[16][64];
    __shared__ float x_s[16][64];
    const int tid = threadIdx.x;
    const int tx = tid & 15, ty = tid >> 4;
    const int p0 = blockIdx.x * 64, c0 = blockIdx.y * 64, b = blockIdx.z;

    float acc[4][4];
#pragma unroll
    for (int i = 0; i < 4; i++)
#pragma unroll
        for (int j = 0; j < 4; j++) acc[i][j] = 0.f;

    for (int ci0 = 0; ci0 < Ci; ci0 += 16) {
        for (int idx = tid; idx < 1024; idx += 256) {
            int p = idx & 63, ci = idx >> 6;
            float v = in[(size_t)(b * Ci + ci0 + ci) * P + p0 + p];
            x_s[ci][p] = relu_in ? fmaxf(v, 0.f) : v;
        }
        for (int idx = tid; idx < 1024; idx += 256) {
            int ci = idx & 15, co = idx >> 4;
            w_s[ci][co] = w[(size_t)(c0 + co) * Ci + ci0 + ci];
        }
        __syncthreads();
#pragma unroll
        for (int ci = 0; ci < 16; ci++) {
            const float4 wv = *(const float4*)&w_s[ci][ty << 2];
            const float4 xv = *(const float4*)&x_s[ci][tx << 2];
            const float wvv[4] = {wv.x, wv.y, wv.z, wv.w};
            const float xvv[4] = {xv.x, xv.y, xv.z, xv.w};
#pragma unroll
            for (int i = 0; i < 4; i++)
#pragma unroll
                for (int j = 0; j < 4; j++)
                    acc[i][j] = fmaf(wvv[i], xvv[j], acc[i][j]);
        }
        __syncthreads();
    }
#pragma unroll
    for (int i = 0; i < 4; i++) {
        const int co = c0 + (ty << 2) + i;
        const float bv = bias ? bias[co] : 0.f;
        const size_t base = (size_t)(b * Co + co) * P + p0 + (tx << 2);
        float4 o = {acc[i][0] + bv, acc[i][1] + bv, acc[i][2] + bv, acc[i][3] + bv};
        if (add_res) {
            float4 rr = *(const float4*)&out[base];
            o.x += rr.x; o.y += rr.y; o.z += rr.z; o.w += rr.w;
        }
        *(float4*)&out[base] = o;
    }
}

__global__ void __launch_bounds__(256) vq_kernel(
    const float* __restrict__ ze, const float* __restrict__ emb,
    float* __restrict__ zq, float* __restrict__ loss)
{
    __shared__ float e_s[128 * 64];
    __shared__ float n_s[128];
    const int tid = threadIdx.x;
    const int n = blockIdx.x * 256 + tid;
    const int b = n >> 10, hw = n & 1023;

    float xr[64];
#pragma unroll
    for (int d = 0; d < 64; d++)
        xr[d] = ze[((size_t)(b * 64 + d) << 10) + hw];

    float best = 3.4e38f;
    int bi = 0;
    for (int kb = 0; kb < 4; kb++) {
        __syncthreads();
        for (int i = tid; i < 128 * 64; i += 256) e_s[i] = emb[kb * 128 * 64 + i];
        __syncthreads();
        if (tid < 128) {
            float s = 0.f;
#pragma unroll 8
            for (int d = 0; d < 64; d++) { float v = e_s[tid * 64 + d]; s = fmaf(v, v, s); }
            n_s[tid] = s;
        }
        __syncthreads();
        for (int k = 0; k < 128; k++) {
            const float4* e4 = (const float4*)(e_s + k * 64);
            float dot = 0.f;
#pragma unroll
            for (int d4 = 0; d4 < 16; d4++) {
                float4 e = e4[d4];
                dot = fmaf(e.x, xr[d4 * 4 + 0], dot);
                dot = fmaf(e.y, xr[d4 * 4 + 1], dot);
                dot = fmaf(e.z, xr[d4 * 4 + 2], dot);
                dot = fmaf(e.w, xr[d4 * 4 + 3], dot);
            }
            float dist = n_s[k] - 2.f * dot;
            if (dist < best) { best = dist; bi = kb * 128 + k; }
        }
    }

    float ls = 0.f;
#pragma unroll
    for (int d = 0; d < 64; d++) {
        float e = emb[bi * 64 + d];
        zq[((size_t)(b * 64 + d) << 10) + hw] = e;
        float df = e - xr[d];
        ls = fmaf(df, df, ls);
    }
#pragma unroll
    for (int o = 16; o > 0; o >>= 1) ls += __shfl_down_sync(0xffffffffu, ls, o);
    if ((tid & 31) == 0) atomicAdd(loss, ls);
}

template <int CO_TILE, int CO_PT, int M_TILE, int N_TILE>
__global__ void __launch_bounds__(256) tconv_kernel(
    const float* __restrict__ in, const float* __restrict__ w,
    const float* __restrict__ bias, float* __restrict__ out,
    int Ci, int Co, int Hi, int Wi, int relu_in, int relu_out)
{
    constexpr int NSLOT = (M_TILE * N_TILE) / 4;
    constexpr int CG = CO_TILE / CO_PT;
    static_assert(NSLOT * CG == 256, "map");
    __shared__ float w_s[4][16][CO_TILE];
    __shared__ float x_s[4][M_TILE + 2][N_TILE + 2];

    const int tid = threadIdx.x;
    const int slot = tid % NSLOT, cg = tid / NSLOT;
    const int m_loc = slot / (N_TILE / 4);
    const int nb = (slot % (N_TILE / 4)) * 4;
    const int n0 = blockIdx.x * N_TILE, m0 = blockIdx.y * M_TILE;
    const int cot = (Co + CO_TILE - 1) / CO_TILE;
    const int b = blockIdx.z / cot, c0 = (blockIdx.z % cot) * CO_TILE;
    const int Ho = 2 * Hi, Wo2 = 2 * Wi;

    float acc[CO_PT][4][2][2];
#pragma unroll
    for (int i = 0; i < CO_PT; i++)
#pragma unroll
        for (int q = 0; q < 4; q++)
#pragma unroll
            for (int a = 0; a < 2; a++)
#pragma unroll
                for (int bb = 0; bb < 2; bb++) acc[i][q][a][bb] = 0.f;

    for (int ci0 = 0; ci0 < Ci; ci0 += 4) {
        for (int idx = tid; idx < 4 * (M_TILE + 2) * (N_TILE + 2); idx += 256) {
            int lc = idx % (N_TILE + 2);
            int t = idx / (N_TILE + 2);
            int lr = t % (M_TILE + 2), ci = t / (M_TILE + 2);
            int m = m0 - 1 + lr, nn = n0 - 1 + lc;
            float v = 0.f;
            if ((unsigned)m < (unsigned)Hi && (unsigned)nn < (unsigned)Wi)
                v = in[((size_t)(b * Ci + ci0 + ci) * Hi + m) * Wi + nn];
            if (relu_in) v = fmaxf(v, 0.f);
            x_s[ci][lr][lc] = v;
        }
        for (int idx = tid; idx < 4 * 16 * CO_TILE; idx += 256) {
            int t = idx & 15;
            int co = (idx >> 4) % CO_TILE;
            int ci = idx / (16 * CO_TILE);
            float v = 0.f;
            if (c0 + co < Co) v = w[((size_t)(ci0 + ci) * Co + c0 + co) * 16 + t];
            w_s[ci][t][co] = v;
        }
        __syncthreads();
#pragma unroll
        for (int ci = 0; ci < 4; ci++)
#pragma unroll
            for (int t = 0; t < 16; t++) {
                const int kh = t >> 2, kw = t & 3;
                const int a = 1 - (kh & 1);
                const int dm = (kh == 0) ? 1 : ((kh == 3) ? -1 : 0);
                const int bb = 1 - (kw & 1);
                const int dn = (kw == 0) ? 1 : ((kw == 3) ? -1 : 0);
                float wr[CO_PT];
#pragma unroll
                for (int i = 0; i < CO_PT; i++)
                    wr[i] = w_s[ci][t][cg * CO_PT + i];
                const float* xrow = &x_s[ci][m_loc + dm + 1][nb + dn + 1];
#pragma unroll
                for (int q = 0; q < 4; q++) {
                    const float xv = xrow[q];
#pragma unroll
                    for (int i = 0; i < CO_PT; i++)
                        acc[i][q][a][bb] = fmaf(wr[i], xv, acc[i][q][a][bb]);
                }
            }
        __syncthreads();
    }

    const int m = m0 + m_loc;
#pragma unroll
    for (int i = 0; i < CO_PT; i++) {
        const int co = c0 + cg * CO_PT + i;
        if (co < Co) {
            const float bv = bias[co];
#pragma unroll
            for (int q = 0; q < 4; q++) {
                const int nn = n0 + nb + q;
#pragma unroll
                for (int a = 0; a < 2; a++) {
                    float2 o = {acc[i][q][a][0] + bv, acc[i][q][a][1] + bv};
                    if (relu_out) { o.x = fmaxf(o.x, 0.f); o.y = fmaxf(o.y, 0.f); }
                    *(float2*)&out[((size_t)(b * Co + co) * Ho + 2 * m + a) * Wo2 + 2 * nn] = o;
                }
            }
        }
    }
}

__global__ void zero_loss_kernel(float* loss) { loss[0] = 0.f; }
__global__ void finish_loss_kernel(const float* __restrict__ loss, float* __restrict__ dst)
{
    dst[0] = 2.f * loss[0] / 2097152.f;
}

// ===========================================================================
// weight prepacks (fp16)
// ===========================================================================

__global__ void wt4s2_f16(const float* __restrict__ w, u32* __restrict__ wT2,
                          int Ci, int Co)
{
    int idx = blockIdx.x * 256 + threadIdx.x;
    if (idx >= Ci * 8 * Co) return;
    int co = idx % Co, k2 = idx / Co;
    int k = 2 * k2, ci = k >> 4, t = k & 15;
    const float* base = &w[((size_t)co * Ci + ci) * 16 + t];
    wT2[idx] = pack_f16x2(base[0], base[1]);
}

__global__ void wtT_f16(const float* __restrict__ w, u32* __restrict__ wT2,
                        int Ci, int Co)
{
    int K2 = Ci * 2;
    int idx = blockIdx.x * 256 + threadIdx.x;
    if (idx >= 4 * K2 * Co) return;
    int co = idx % Co, rr = idx / Co;
    int p = rr / K2, k2 = rr % K2;
    int k = 2 * k2, ci = k >> 2, j = k & 3;
    int a = p >> 1, bb = p & 1;
    int kh = (1 - a) + 2 * (j >> 1);
    const float* base = &w[((size_t)ci * Co + co) * 16 + kh * 4];
    wT2[idx] = pack_f16x2(base[1 - bb], base[3 - bb]);
}

__global__ void wt3_f16(const float* __restrict__ w, u32* __restrict__ wT2, int Ci)
{
    int K = Ci * 9;
    int idx = blockIdx.x * 256 + threadIdx.x;
    if (idx >= (K / 2) * 32) return;
    int co = idx & 31, k2 = idx >> 5;
    int k0 = 2 * k2, k1 = k0 + 1;
    int ci0 = k0 / 9, t0 = k0 - ci0 * 9;
    int ci1 = k1 / 9, t1 = k1 - ci1 * 9;
    wT2[idx] = pack_f16x2(w[((size_t)co * Ci + ci0) * 9 + t0],
                          w[((size_t)co * Ci + ci1) * 9 + t1]);
}

// ===========================================================================
// HMMA conv k4 s2 p1 (mirror input). 128 Co x 128 px, K-chunks of 64.
// ===========================================================================

__global__ void __launch_bounds__(256) conv4s2_tcf(
    const u32* __restrict__ mir, const u32* __restrict__ wT2,
    const float* __restrict__ bias, float* __restrict__ out,
    int Ci, int Co, int Hp, int Wp, int Ho, int Wo, int w_shift, int relu)
{
    __shared__ u32 A_s[32][136];
    __shared__ u32 B_s[32][136];
    const int tid = threadIdx.x;
    const int lane = tid & 31, warp = tid >> 5;
    const int gid = lane >> 2, tig = lane & 3;
    const int m0w = (warp & 3) * 32, n0w = (warp >> 2) * 64;
    const int OWT = 1 << w_shift;
    const int ow0 = blockIdx.x * OWT, oh0 = blockIdx.y * (128 >> w_shift);
    const int cot = Co >> 7;
    const int b = blockIdx.z / cot, c0 = (blockIdx.z % cot) << 7;
    const int K = Ci << 4;

    const int sk = tid >> 3;
    const int sn0 = (tid & 7) << 4;
    const int oh = oh0 + (sn0 >> w_shift);
    const int ow = ow0 + (sn0 & (OWT - 1));

    float acc[2][8][4];
#pragma unroll
    for (int mi = 0; mi < 2; mi++)
#pragma unroll
        for (int ni = 0; ni < 8; ni++)
#pragma unroll
            for (int c = 0; c < 4; c++) acc[mi][ni][c] = 0.f;

    for (int k0 = 0; k0 < K; k0 += 64) {
        const int k02 = k0 >> 1;
        for (int idx = tid; idx < 1024; idx += 256) {
            int kk = idx >> 5, m4 = idx & 31;
            uint4 v = *(const uint4*)&wT2[(size_t)(k02 + kk) * Co + c0 + (m4 << 2)];
            *(uint4*)&A_s[kk][m4 << 2] = v;
        }
        {
            const int k = k0 + 2 * sk;
            const int ci = k >> 4, t = k & 15, kh = t >> 2, kw = t & 3;
            const u32* u = mir +
                ((((size_t)(b * Ci + ci) * Hp + 2 * oh + kh) * Wp + 2 * ow + kw) >> 1);
            u32* dst = &B_s[sk][sn0];
            if (!(kw & 1)) {
#pragma unroll
                for (int j = 0; j < 16; j++) dst[j] = u[j];
            } else {
                u32 a = u[0];
#pragma unroll
                for (int j = 0; j < 16; j++) {
                    u32 bb = u[j + 1];
                    dst[j] = prmt(a, bb, 0x5432);
                    a = bb;
                }
            }
        }
        __syncthreads();
#pragma unroll
        for (int s = 0; s < 4; s++) {
            const int k2b = s * 8;
            u32 a[2][4], bf[8][2];
#pragma unroll
            for (int mi = 0; mi < 2; mi++) {
                a[mi][0] = A_s[k2b + tig][m0w + mi * 16 + gid];
                a[mi][1] = A_s[k2b + tig][m0w + mi * 16 + gid + 8];
                a[mi][2] = A_s[k2b + tig + 4][m0w + mi * 16 + gid];
                a[mi][3] = A_s[k2b + tig + 4][m0w + mi * 16 + gid + 8];
            }
#pragma unroll
            for (int ni = 0; ni < 8; ni++) {
                bf[ni][0] = B_s[k2b + tig][n0w + ni * 8 + gid];
                bf[ni][1] = B_s[k2b + tig + 4][n0w + ni * 8 + gid];
            }
#pragma unroll
            for (int mi = 0; mi < 2; mi++)
#pragma unroll
                for (int ni = 0; ni < 8; ni++)
                    MMA_F16(acc[mi][ni], a[mi][0], a[mi][1], a[mi][2], a[mi][3],
                            bf[ni][0], bf[ni][1]);
        }
        __syncthreads();
    }

#pragma unroll
    for (int mi = 0; mi < 2; mi++)
#pragma unroll
        for (int h = 0; h < 2; h++) {
            const int co = c0 + m0w + mi * 16 + gid + h * 8;
            const float bv = bias[co];
#pragma unroll
            for (int ni = 0; ni < 8; ni++) {
                const int n = n0w + ni * 8 + 2 * tig;
                const int ohl = n >> w_shift, owl = n & (OWT - 1);
                float2 o = {acc[mi][ni][h * 2] + bv, acc[mi][ni][h * 2 + 1] + bv};
                if (relu) { o.x = fmaxf(o.x, 0.f); o.y = fmaxf(o.y, 0.f); }
                *(float2*)&out[((size_t)(b * Co + co) * Ho + oh0 + ohl) * Wo + ow0 + owl] = o;
            }
        }
}

// ===========================================================================
// HMMA conv-transpose k4 s2 p1 per-parity (mirror input).
// ===========================================================================

__global__ void __launch_bounds__(256) tconv_tcf(
    const u32* __restrict__ mir, const u32* __restrict__ wT2,
    const float* __restrict__ bias, float* __restrict__ out,
    int Ci, int Co, int Hi, int Wi, int Hp, int Wp, int w_shift, int relu_out)
{
    __shared__ u32 A_s[32][136];
    __shared__ u32 B_s[32][136];
    const int tid = threadIdx.x;
    const int lane = tid & 31, warp = tid >> 5;
    const int gid = lane >> 2, tig = lane & 3;
    const int m0w = (warp & 3) * 32, n0w = (warp >> 2) * 64;
    const int OWT = 1 << w_shift;
    const int ow0 = blockIdx.x * OWT, oh0 = blockIdx.y * (128 >> w_shift);
    const int p = blockIdx.z & 3;
    const int rest = blockIdx.z >> 2;
    const int cot = Co >> 7;
    const int b = rest / cot, c0 = (rest % cot) << 7;
    const int pa = p >> 1, pb = p & 1;
    const int K = Ci << 2, K2 = Ci << 1;
    const int Ho = 2 * Hi, Wo2 = 2 * Wi;
    const u32* wTp = wT2 + (size_t)p * K2 * Co;

    const int sk = tid >> 3;
    const int sn0 = (tid & 7) << 4;
    const int mh = oh0 + (sn0 >> w_shift);
    const int mw = ow0 + (sn0 & (OWT - 1));

    float acc[2][8][4];
#pragma unroll
    for (int mi = 0; mi < 2; mi++)
#pragma unroll
        for (int ni = 0; ni < 8; ni++)
#pragma unroll
            for (int c = 0; c < 4; c++) acc[mi][ni][c] = 0.f;

    for (int k0 = 0; k0 < K; k0 += 64) {
        const int k02 = k0 >> 1;
        for (int idx = tid; idx < 1024; idx += 256) {
            int kk = idx >> 5, m4 = idx & 31;
            uint4 v = *(const uint4*)&wTp[(size_t)(k02 + kk) * Co + c0 + (m4 << 2)];
            *(uint4*)&A_s[kk][m4 << 2] = v;
        }
        {
            const int k = k0 + 2 * sk;
            const int ci = k >> 2, j2 = k & 3;
            const int kh = (1 - pa) + 2 * (j2 >> 1);
            const int dm = (kh == 0) ? 1 : ((kh == 3) ? -1 : 0);
            const int mb = (int)(((size_t)(b * Ci + ci) * Hp + mh + dm + 1) * Wp) + mw + pb + 1;
            const u32* u = mir + ((mb - 1) >> 1);
            u32* dst = &B_s[sk][sn0];
            if (pb == 0) {          // mb odd
                u32 a = u[0];
#pragma unroll
                for (int q = 0; q < 8; q++) {
                    u32 bb = u[q + 1];
                    dst[2 * q]     = prmt(a, a, 0x1032);
                    dst[2 * q + 1] = prmt(a, bb, 0x3254);
                    a = bb;
                }
            } else {                // mb even
                u32 a = u[0];
#pragma unroll
                for (int q = 0; q < 8; q++) {
                    u32 bb = u[q + 1];
                    dst[2 * q]     = prmt(a, bb, 0x3254);
                    dst[2 * q + 1] = prmt(bb, bb, 0x1032);
                    a = bb;
                }
            }
        }
        __syncthreads();
#pragma unroll
        for (int s = 0; s < 4; s++) {
            const int k2b = s * 8;
            u32 a[2][4], bf[8][2];
#pragma unroll
            for (int mi = 0; mi < 2; mi++) {
                a[mi][0] = A_s[k2b + tig][m0w + mi * 16 + gid];
                a[mi][1] = A_s[k2b + tig][m0w + mi * 16 + gid + 8];
                a[mi][2] = A_s[k2b + tig + 4][m0w + mi * 16 + gid];
                a[mi][3] = A_s[k2b + tig + 4][m0w + mi * 16 + gid + 8];
            }
#pragma unroll
            for (int ni = 0; ni < 8; ni++) {
                bf[ni][0] = B_s[k2b + tig][n0w + ni * 8 + gid];
                bf[ni][1] = B_s[k2b + tig + 4][n0w + ni * 8 + gid];
            }
#pragma unroll
            for (int mi = 0; mi < 2; mi++)
#pragma unroll
                for (int ni = 0; ni < 8; ni++)
                    MMA_F16(acc[mi][ni], a[mi][0], a[mi][1], a[mi][2], a[mi][3],
                            bf[ni][0], bf[ni][1]);
        }
        __syncthreads();
    }

#pragma unroll
    for (int mi = 0; mi < 2; mi++)
#pragma unroll
        for (int h = 0; h < 2; h++) {
            const int co = c0 + m0w + mi * 16 + gid + h * 8;
            const float bv = bias[co];
#pragma unroll
            for (int ni = 0; ni < 8; ni++) {
                const int n = n0w + ni * 8 + 2 * tig;
                const int mhh = oh0 + (n >> w_shift);
                const int mww = ow0 + (n & (OWT - 1));
                float v0 = acc[mi][ni][h * 2] + bv;
                float v1 = acc[mi][ni][h * 2 + 1] + bv;
                if (relu_out) { v0 = fmaxf(v0, 0.f); v1 = fmaxf(v1, 0.f); }
                float* orow = &out[((size_t)(b * Co + co) * Ho + 2 * mhh + pa) * Wo2];
                orow[2 * mww + pb] = v0;
                orow[2 * (mww + 1) + pb] = v1;
            }
        }
}

// ===========================================================================
// HMMA 3x3 res conv (proven round-5)
// ===========================================================================

__global__ void __launch_bounds__(256) conv3x3_tcf(
    const float* __restrict__ in, const u32* __restrict__ wT2,
    float* __restrict__ out, int Ci, int HW, int hw_shift)
{
    __shared__ u32 A_s[32][40];
    __shared__ u32 B_s[32][264];
    const int tid = threadIdx.x;
    const int lane = tid & 31, warp = tid >> 5;
    const int gid = lane >> 2, tig = lane & 3;
    const int n0w = warp * 32;
    const int p0 = blockIdx.x * 256;
    const int b = blockIdx.z;
    const int K = Ci * 9;

    const int sk = tid >> 3;
    const int sn0 = (tid & 7) << 5;
    const int ng0 = p0 + sn0;
    const int s_oh = ng0 >> hw_shift;
    const int s_ow = ng0 & (HW - 1);

    float acc[2][4][4];
#pragma unroll
    for (int mi = 0; mi < 2; mi++)
#pragma unroll
        for (int ni = 0; ni < 4; ni++)
#pragma unroll
            for (int c = 0; c < 4; c++) acc[mi][ni][c] = 0.f;

    for (int k0 = 0; k0 < K; k0 += 64) {
        const int k02 = k0 >> 1;
        for (int idx = tid; idx < 1024; idx += 256) {
            int kk = idx >> 5, m = idx & 31;
            A_s[kk][m] = wT2[(size_t)(k02 + kk) * 32 + m];
        }
        {
            const int klo = k0 + 2 * sk, khi = klo + 1;
            const int ci0 = klo / 9, t0 = klo - ci0 * 9;
            const int ci1 = khi / 9, t1 = khi - ci1 * 9;
            const int kh0 = t0 / 3, kw0 = t0 - 3 * kh0;
            const int kh1 = t1 / 3, kw1 = t1 - 3 * kh1;
            const int ih0 = s_oh - 1 + kh0, ih1 = s_oh - 1 + kh1;
            const bool ok0 = (unsigned)ih0 < (unsigned)HW;
            const bool ok1 = (unsigned)ih1 < (unsigned)HW;
            const float* r0 = in + ((size_t)(b * Ci + ci0) * HW + ih0) * HW;
            const float* r1 = in + ((size_t)(b * Ci + ci1) * HW + ih1) * HW;
            const int iwb0 = s_ow - 1 + kw0, iwb1 = s_ow - 1 + kw1;
#pragma unroll
            for (int jj = 0; jj < 32; jj++) {
                const int iw0 = iwb0 + jj, iw1 = iwb1 + jj;
                float v0 = (ok0 && (unsigned)iw0 < (unsigned)HW) ? fmaxf(r0[iw0], 0.f) : 0.f;
                float v1 = (ok1 && (unsigned)iw1 < (unsigned)HW) ? fmaxf(r1[iw1], 0.f) : 0.f;
                B_s[sk][sn0 + jj] = pack_f16x2(v0, v1);
            }
        }
        __syncthreads();
#pragma unroll
        for (int s = 0; s < 4; s++) {
            const int k2b = s * 8;
            u32 a[2][4], bf[4][2];
#pragma unroll
            for (int mi = 0; mi < 2; mi++) {
                a[mi][0] = A_s[k2b + tig][mi * 16 + gid];
                a[mi][1] = A_s[k2b + tig][mi * 16 + gid + 8];
                a[mi][2] = A_s[k2b + tig + 4][mi * 16 + gid];
                a[mi][3] = A_s[k2b + tig + 4][mi * 16 + gid + 8];
            }
#pragma unroll
            for (int ni = 0; ni < 4; ni++) {
                bf[ni][0] = B_s[k2b + tig][n0w + ni * 8 + gid];
                bf[ni][1] = B_s[k2b + tig + 4][n0w + ni * 8 + gid];
            }
#pragma unroll
            for (int mi = 0; mi < 2; mi++)
#pragma unroll
                for (int ni = 0; ni < 4; ni++)
                    MMA_F16(acc[mi][ni], a[mi][0], a[mi][1], a[mi][2], a[mi][3],
                            bf[ni][0], bf[ni][1]);
        }
        __syncthreads();
    }

#pragma unroll
    for (int mi = 0; mi < 2; mi++)
#pragma unroll
        for (int h = 0; h < 2; h++) {
            const int co = mi * 16 + gid + h * 8;
#pragma unroll
            for (int ni = 0; ni < 4; ni++) {
                const int ng = p0 + n0w + ni * 8 + 2 * tig;
                const int oh = ng >> hw_shift, ow = ng & (HW - 1);
                float2 o = {acc[mi][ni][h * 2], acc[mi][ni][h * 2 + 1]};
                *(float2*)&out[((size_t)(b * 32 + co) * HW + oh) * HW + ow] = o;
            }
        }
}

// ===========================================================================
extern "C" void kernel_launch(void* const* d_in, const int* in_sizes, int n_in,
                              void* d_out, int out_size)
{
    (void)in_sizes; (void)n_in;
    const float* x       = (const float*)d_in[0];
    const float* enc_w1  = (const float*)d_in[1];
    const float* enc_b1  = (const float*)d_in[2];
    const float* enc_w2  = (const float*)d_in[3];
    const float* enc_b2  = (const float*)d_in[4];
    const float* enc_w3  = (const float*)d_in[5];
    const float* enc_b3  = (const float*)d_in[6];
    const float* enc_rw3 = (const float*)d_in[7];
    const float* enc_rw1 = (const float*)d_in[8];
    const float* prevq_w = (const float*)d_in[9];
    const float* prevq_b = (const float*)d_in[10];
    const float* emb     = (const float*)d_in[11];
    const float* dec_w1  = (const float*)d_in[12];
    const float* dec_b1  = (const float*)d_in[13];
    const float* dec_rw3 = (const float*)d_in[14];
    const float* dec_rw1 = (const float*)d_in[15];
    const float* dec_w2  = (const float*)d_in[16];
    const float* dec_b2  = (const float*)d_in[17];
    const float* dec_w3  = (const float*)d_in[18];
    const float* dec_b3  = (const float*)d_in[19];
    float* out = (float*)d_out;

    float *b0, *b1, *b2, *b3, *ze, *zq, *loss;
    u32 *wt, *m0, *m1, *mq;
    cudaGetSymbolAddress((void**)&b0, g_b0);
    cudaGetSymbolAddress((void**)&b1, g_b1);
    cudaGetSymbolAddress((void**)&b2, g_b2);
    cudaGetSymbolAddress((void**)&b3, g_b3);
    cudaGetSymbolAddress((void**)&ze, g_ze);
    cudaGetSymbolAddress((void**)&zq, g_zq);
    cudaGetSymbolAddress((void**)&loss, g_loss);
    cudaGetSymbolAddress((void**)&wt, g_wt);
    cudaGetSymbolAddress((void**)&m0, g_m0);
    cudaGetSymbolAddress((void**)&m1, g_m1);
    cudaGetSymbolAddress((void**)&mq, g_mq);

    // ---- encoder ----
    conv4s2_kernel<<<dim3(4, 64, 32), 256>>>(x, enc_w1, enc_b1, b0, 3, 128, 256, 256, 128, 128, 1);

    cvt_mirror<<<137280, 256>>>(b0, m0, 4096, 128, 128, 130, 66, 0);
    wt4s2_f16<<<1024, 256>>>(enc_w2, wt, 128, 256);
    conv4s2_tcf<<<dim3(1, 32, 64), 256>>>(m0, wt, enc_b2, b1, 128, 256, 130, 132, 64, 64, 6, 1);

    cvt_mirror<<<71808, 256>>>(b1, m1, 8192, 64, 64, 66, 34, 0);
    wt4s2_f16<<<4096, 256>>>(enc_w3, wt, 256, 512);
    conv4s2_tcf<<<dim3(1, 8, 128), 256>>>(m1, wt, enc_b3, b2, 256, 512, 66, 68, 32, 32, 5, 0);

    wt3_f16<<<288, 256>>>(enc_rw3, wt, 512);
    for (int l = 0; l < 2; l++) {
        conv3x3_tcf<<<dim3(4, 1, 32), 256>>>(b2, wt, b3, 512, 32, 5);
        conv1x1_kernel<<<dim3(16, 8, 32), 256>>>(b3, enc_rw1, nullptr, b2, 32, 512, 1024, 1, 1);
    }
    conv1x1_kernel<<<dim3(16, 1, 32), 256>>>(b2, prevq_w, prevq_b, ze, 512, 64, 1024, 1, 0);

    // ---- VQ ----
    zero_loss_kernel<<<1, 1>>>(loss);
    vq_kernel<<<128, 256>>>(ze, emb, zq, loss);
    finish_loss_kernel<<<1, 1>>>(loss, out + (out_size - 1));

    // ---- decoder ----
    cvt_mirror<<<4896, 256>>>(zq, mq, 2048, 32, 32, 34, 18, 0);
    wtT_f16<<<512, 256>>>(dec_w1, wt, 64, 256);
    tconv_tcf<<<dim3(1, 8, 256), 256>>>(mq, wt, dec_b1, b1, 64, 256, 32, 32, 34, 36, 5, 0);

    wt3_f16<<<144, 256>>>(dec_rw3, wt, 256);
    for (int l = 0; l < 2; l++) {
        conv3x3_tcf<<<dim3(16, 1, 32), 256>>>(b1, wt, b3, 256, 64, 6);
        conv1x1_kernel<<<dim3(64, 4, 32), 256>>>(b3, dec_rw1, nullptr, b1, 32, 256, 4096, 1, 1);
    }

    cvt_mirror<<<71808, 256>>>(b1, m1, 8192, 64, 64, 66, 34, 1);
    wtT_f16<<<1024, 256>>>(dec_w2, wt, 256, 128);
    tconv_tcf<<<dim3(1, 32, 128), 256>>>(m1, wt, dec_b2, b0, 256, 128, 64, 64, 66, 68, 6, 1);

    tconv_kernel<4, 1, 16, 16><<<dim3(8, 8, 32), 256>>>(b0, dec_w3, dec_b3, out, 128, 3, 128, 128, 0, 0);
}

// round 9
// speedup vs baseline: 4.8616x; 1.0405x over previous
#include <cuda_runtime.h>

typedef unsigned int u32;

__device__ float g_b0[32u * 128 * 128 * 128];
__device__ float g_b1[32u * 256 * 64 * 64];
__device__ float g_b2[32u * 512 * 32 * 32];
__device__ float g_b3[32u * 32 * 64 * 64];
__device__ float g_ze[32u * 64 * 32 * 32];
__device__ float g_zq[32u * 64 * 32 * 32];
__device__ float g_loss[1];
__device__ u32   g_wt[2097152];
__device__ u32   g_mx[4359168];    // enc1 mirror: 128 x 258 x 132 u32
__device__ u32   g_m0[36218880];   // enc2 mirror: 4096 x 130 x 68 u32
__device__ u32   g_m1[19464192];   // enc3/dec2 mirror: 8192 x 66 x 36 u32
__device__ u32   g_mq[1392640];    // dec1 mirror: 2048 x 34 x 20 u32

__device__ __forceinline__ u32 pack_f16x2(float lo, float hi) {
    u32 r; asm("cvt.rn.f16x2.f32 %0,%1,%2;" : "=r"(r) : "f"(hi), "f"(lo)); return r;
}
__device__ __forceinline__ u32 prmt(u32 a, u32 b, u32 s) {
    u32 r; asm("prmt.b32 %0,%1,%2,%3;" : "=r"(r) : "r"(a), "r"(b), "r"(s)); return r;
}

#define MMA_F16(d, a0, a1, a2, a3, b0, b1)                                    \
    asm volatile("mma.sync.aligned.m16n8k16.row.col.f32.f16.f16.f32 "         \
                 "{%0,%1,%2,%3},{%4,%5,%6,%7},{%8,%9},{%0,%1,%2,%3};"         \
                 : "+f"(d[0]), "+f"(d[1]), "+f"(d[2]), "+f"(d[3])             \
                 : "r"(a0), "r"(a1), "r"(a2), "r"(a3), "r"(b0), "r"(b1))

// ---- mirror build: fp32 NCHW -> padded fp16 rows (pad 1 top/left, zeros) --
// dst channel c of batch b maps to src channel c if c < scpb else zeros.
__global__ void cvt_mirror(const float* __restrict__ src, u32* __restrict__ dst,
                           int Cdst, int Hi, int Wi, int Hp, int Wp2, int relu,
                           int scpb, int dcpb)
{
    int idx = blockIdx.x * 256 + threadIdx.x;
    if (idx >= Cdst * Hp * Wp2) return;
    int wp2 = idx % Wp2, t = idx / Wp2;
    int ph = t % Hp, cm = t / Hp;
    int b = cm / dcpb, c = cm % dcpb;
    int ih = ph - 1;
    int iw0 = 2 * wp2 - 1, iw1 = iw0 + 1;
    float v0 = 0.f, v1 = 0.f;
    if (c < scpb && (unsigned)ih < (unsigned)Hi) {
        const float* r = src + ((size_t)(b * scpb + c) * Hi + ih) * Wi;
        if ((unsigned)iw0 < (unsigned)Wi) v0 = r[iw0];
        if ((unsigned)iw1 < (unsigned)Wi) v1 = r[iw1];
    }
    if (relu) { v0 = fmaxf(v0, 0.f); v1 = fmaxf(v1, 0.f); }
    dst[idx] = pack_f16x2(v0, v1);
}

// ===========================================================================
// fp32 kernels (proven)
// ===========================================================================

__global__ void __launch_bounds__(256) conv1x1_kernel(
    const float* __restrict__ in, const float* __restrict__ w,
    const float* __restrict__ bias, float* __restrict__ out,
    int Ci, int Co, int P, int relu_in, int add_res)
{
    __shared__ float w_s[16][64];
    __shared__ float x_s[16][64];
    const int tid = threadIdx.x;
    const int tx = tid & 15, ty = tid >> 4;
    const int p0 = blockIdx.x * 64, c0 = blockIdx.y * 64, b = blockIdx.z;

    float acc[4][4];
#pragma unroll
    for (int i = 0; i < 4; i++)
#pragma unroll
        for (int j = 0; j < 4; j++) acc[i][j] = 0.f;

    for (int ci0 = 0; ci0 < Ci; ci0 += 16) {
        for (int idx = tid; idx < 1024; idx += 256) {
            int p = idx & 63, ci = idx >> 6;
            float v = in[(size_t)(b * Ci + ci0 + ci) * P + p0 + p];
            x_s[ci][p] = relu_in ? fmaxf(v, 0.f) : v;
        }
        for (int idx = tid; idx < 1024; idx += 256) {
            int ci = idx & 15, co = idx >> 4;
            w_s[ci][co] = w[(size_t)(c0 + co) * Ci + ci0 + ci];
        }
        __syncthreads();
#pragma unroll
        for (int ci = 0; ci < 16; ci++) {
            const float4 wv = *(const float4*)&w_s[ci][ty << 2];
            const float4 xv = *(const float4*)&x_s[ci][tx << 2];
            const float wvv[4] = {wv.x, wv.y, wv.z, wv.w};
            const float xvv[4] = {xv.x, xv.y, xv.z, xv.w};
#pragma unroll
            for (int i = 0; i < 4; i++)
#pragma unroll
                for (int j = 0; j < 4; j++)
                    acc[i][j] = fmaf(wvv[i], xvv[j], acc[i][j]);
        }
        __syncthreads();
    }
#pragma unroll
    for (int i = 0; i < 4; i++) {
        const int co = c0 + (ty << 2) + i;
        const float bv = bias ? bias[co] : 0.f;
        const size_t base = (size_t)(b * Co + co) * P + p0 + (tx << 2);
        float4 o = {acc[i][0] + bv, acc[i][1] + bv, acc[i][2] + bv, acc[i][3] + bv};
        if (add_res) {
            float4 rr = *(const float4*)&out[base];
            o.x += rr.x; o.y += rr.y; o.z += rr.z; o.w += rr.w;
        }
        *(float4*)&out[base] = o;
    }
}

__global__ void __launch_bounds__(256) vq_kernel(
    const float* __restrict__ ze, const float* __restrict__ emb,
    float* __restrict__ zq, float* __restrict__ loss)
{
    __shared__ float e_s[128 * 64];
    __shared__ float n_s[128];
    const int tid = threadIdx.x;
    const int n = blockIdx.x * 256 + tid;
    const int b = n >> 10, hw = n & 1023;

    float xr[64];
#pragma unroll
    for (int d = 0; d < 64; d++)
        xr[d] = ze[((size_t)(b * 64 + d) << 10) + hw];

    float best = 3.4e38f;
    int bi = 0;
    for (int kb = 0; kb < 4; kb++) {
        __syncthreads();
        for (int i = tid; i < 128 * 64; i += 256) e_s[i] = emb[kb * 128 * 64 + i];
        __syncthreads();
        if (tid < 128) {
            float s = 0.f;
#pragma unroll 8
            for (int d = 0; d < 64; d++) { float v = e_s[tid * 64 + d]; s = fmaf(v, v, s); }
            n_s[tid] = s;
        }
        __syncthreads();
        for (int k = 0; k < 128; k++) {
            const float4* e4 = (const float4*)(e_s + k * 64);
            float dot = 0.f;
#pragma unroll
            for (int d4 = 0; d4 < 16; d4++) {
                float4 e = e4[d4];
                dot = fmaf(e.x, xr[d4 * 4 + 0], dot);
                dot = fmaf(e.y, xr[d4 * 4 + 1], dot);
                dot = fmaf(e.z, xr[d4 * 4 + 2], dot);
                dot = fmaf(e.w, xr[d4 * 4 + 3], dot);
            }
            float dist = n_s[k] - 2.f * dot;
            if (dist < best) { best = dist; bi = kb * 128 + k; }
        }
    }

    float ls = 0.f;
#pragma unroll
    for (int d = 0; d < 64; d++) {
        float e = emb[bi * 64 + d];
        zq[((size_t)(b * 64 + d) << 10) + hw] = e;
        float df = e - xr[d];
        ls = fmaf(df, df, ls);
    }
#pragma unroll
    for (int o = 16; o > 0; o >>= 1) ls += __shfl_down_sync(0xffffffffu, ls, o);
    if ((tid & 31) == 0) atomicAdd(loss, ls);
}

template <int CO_TILE, int CO_PT, int M_TILE, int N_TILE>
__global__ void __launch_bounds__(256) tconv_kernel(
    const float* __restrict__ in, const float* __restrict__ w,
    const float* __restrict__ bias, float* __restrict__ out,
    int Ci, int Co, int Hi, int Wi, int relu_in, int relu_out)
{
    constexpr int NSLOT = (M_TILE * N_TILE) / 4;
    constexpr int CG = CO_TILE / CO_PT;
    static_assert(NSLOT * CG == 256, "map");
    __shared__ float w_s[4][16][CO_TILE];
    __shared__ float x_s[4][M_TILE + 2][N_TILE + 2];

    const int tid = threadIdx.x;
    const int slot = tid % NSLOT, cg = tid / NSLOT;
    const int m_loc = slot / (N_TILE / 4);
    const int nb = (slot % (N_TILE / 4)) * 4;
    const int n0 = blockIdx.x * N_TILE, m0 = blockIdx.y * M_TILE;
    const int cot = (Co + CO_TILE - 1) / CO_TILE;
    const int b = blockIdx.z / cot, c0 = (blockIdx.z % cot) * CO_TILE;
    const int Ho = 2 * Hi, Wo2 = 2 * Wi;

    float acc[CO_PT][4][2][2];
#pragma unroll
    for (int i = 0; i < CO_PT; i++)
#pragma unroll
        for (int q = 0; q < 4; q++)
#pragma unroll
            for (int a = 0; a < 2; a++)
#pragma unroll
                for (int bb = 0; bb < 2; bb++) acc[i][q][a][bb] = 0.f;

    for (int ci0 = 0; ci0 < Ci; ci0 += 4) {
        for (int idx = tid; idx < 4 * (M_TILE + 2) * (N_TILE + 2); idx += 256) {
            int lc = idx % (N_TILE + 2);
            int t = idx / (N_TILE + 2);
            int lr = t % (M_TILE + 2), ci = t / (M_TILE + 2);
            int m = m0 - 1 + lr, nn = n0 - 1 + lc;
            float v = 0.f;
            if ((unsigned)m < (unsigned)Hi && (unsigned)nn < (unsigned)Wi)
                v = in[((size_t)(b * Ci + ci0 + ci) * Hi + m) * Wi + nn];
            if (relu_in) v = fmaxf(v, 0.f);
            x_s[ci][lr][lc] = v;
        }
        for (int idx = tid; idx < 4 * 16 * CO_TILE; idx += 256) {
            int t = idx & 15;
            int co = (idx >> 4) % CO_TILE;
            int ci = idx / (16 * CO_TILE);
            float v = 0.f;
            if (c0 + co < Co) v = w[((size_t)(ci0 + ci) * Co + c0 + co) * 16 + t];
            w_s[ci][t][co] = v;
        }
        __syncthreads();
#pragma unroll
        for (int ci = 0; ci < 4; ci++)
#pragma unroll
            for (int t = 0; t < 16; t++) {
                const int kh = t >> 2, kw = t & 3;
                const int a = 1 - (kh & 1);
                const int dm = (kh == 0) ? 1 : ((kh == 3) ? -1 : 0);
                const int bb = 1 - (kw & 1);
                const int dn = (kw == 0) ? 1 : ((kw == 3) ? -1 : 0);
                float wr[CO_PT];
#pragma unroll
                for (int i = 0; i < CO_PT; i++)
                    wr[i] = w_s[ci][t][cg * CO_PT + i];
                const float* xrow = &x_s[ci][m_loc + dm + 1][nb + dn + 1];
#pragma unroll
                for (int q = 0; q < 4; q++) {
                    const float xv = xrow[q];
#pragma unroll
                    for (int i = 0; i < CO_PT; i++)
                        acc[i][q][a][bb] = fmaf(wr[i], xv, acc[i][q][a][bb]);
                }
            }
        __syncthreads();
    }

    const int m = m0 + m_loc;
#pragma unroll
    for (int i = 0; i < CO_PT; i++) {
        const int co = c0 + cg * CO_PT + i;
        if (co < Co) {
            const float bv = bias[co];
#pragma unroll
            for (int q = 0; q < 4; q++) {
                const int nn = n0 + nb + q;
#pragma unroll
                for (int a = 0; a < 2; a++) {
                    float2 o = {acc[i][q][a][0] + bv, acc[i][q][a][1] + bv};
                    if (relu_out) { o.x = fmaxf(o.x, 0.f); o.y = fmaxf(o.y, 0.f); }
                    *(float2*)&out[((size_t)(b * Co + co) * Ho + 2 * m + a) * Wo2 + 2 * nn] = o;
                }
            }
        }
    }
}

__global__ void zero_loss_kernel(float* loss) { loss[0] = 0.f; }
__global__ void finish_loss_kernel(const float* __restrict__ loss, float* __restrict__ dst)
{
    dst[0] = 2.f * loss[0] / 2097152.f;
}

// ===========================================================================
// weight prepacks (fp16)
// ===========================================================================

__global__ void wt4s2_f16(const float* __restrict__ w, u32* __restrict__ wT2,
                          int Ci, int Co, int Ci_src)
{
    int idx = blockIdx.x * 256 + threadIdx.x;
    if (idx >= Ci * 8 * Co) return;
    int co = idx % Co, k2 = idx / Co;
    int k = 2 * k2, ci = k >> 4, t = k & 15;
    float v0 = 0.f, v1 = 0.f;
    if (ci < Ci_src) {
        const float* base = &w[((size_t)co * Ci_src + ci) * 16 + t];
        v0 = base[0]; v1 = base[1];
    }
    wT2[idx] = pack_f16x2(v0, v1);
}

__global__ void wtT_f16(const float* __restrict__ w, u32* __restrict__ wT2,
                        int Ci, int Co)
{
    int K2 = Ci * 2;
    int idx = blockIdx.x * 256 + threadIdx.x;
    if (idx >= 4 * K2 * Co) return;
    int co = idx % Co, rr = idx / Co;
    int p = rr / K2, k2 = rr % K2;
    int k = 2 * k2, ci = k >> 2, j = k & 3;
    int a = p >> 1, bb = p & 1;
    int kh = (1 - a) + 2 * (j >> 1);
    const float* base = &w[((size_t)ci * Co + co) * 16 + kh * 4];
    wT2[idx] = pack_f16x2(base[1 - bb], base[3 - bb]);
}

__global__ void wt3_f16(const float* __restrict__ w, u32* __restrict__ wT2, int Ci)
{
    int K = Ci * 9;
    int idx = blockIdx.x * 256 + threadIdx.x;
    if (idx >= (K / 2) * 32) return;
    int co = idx & 31, k2 = idx >> 5;
    int k0 = 2 * k2, k1 = k0 + 1;
    int ci0 = k0 / 9, t0 = k0 - ci0 * 9;
    int ci1 = k1 / 9, t1 = k1 - ci1 * 9;
    wT2[idx] = pack_f16x2(w[((size_t)co * Ci + ci0) * 9 + t0],
                          w[((size_t)co * Ci + ci1) * 9 + t1]);
}

// ===========================================================================
// HMMA conv k4 s2 p1 (mirror input, vectorized staging).
// ===========================================================================

__global__ void __launch_bounds__(256) conv4s2_tcf(
    const u32* __restrict__ mir, const u32* __restrict__ wT2,
    const float* __restrict__ bias, float* __restrict__ out,
    int Ci, int Co, int Hp, int Wp2, int Ho, int Wo, int w_shift, int relu)
{
    __shared__ u32 A_s[32][136];
    __shared__ u32 B_s[32][136];
    const int tid = threadIdx.x;
    const int lane = tid & 31, warp = tid >> 5;
    const int gid = lane >> 2, tig = lane & 3;
    const int m0w = (warp & 3) * 32, n0w = (warp >> 2) * 64;
    const int OWT = 1 << w_shift;
    const int ow0 = blockIdx.x * OWT, oh0 = blockIdx.y * (128 >> w_shift);
    const int cot = Co >> 7;
    const int b = blockIdx.z / cot, c0 = (blockIdx.z % cot) << 7;
    const int K = Ci << 4;

    const int sk = tid >> 3;
    const int sn0 = (tid & 7) << 4;
    const int oh = oh0 + (sn0 >> w_shift);
    const int ow = ow0 + (sn0 & (OWT - 1));

    float acc[2][8][4];
#pragma unroll
    for (int mi = 0; mi < 2; mi++)
#pragma unroll
        for (int ni = 0; ni < 8; ni++)
#pragma unroll
            for (int c = 0; c < 4; c++) acc[mi][ni][c] = 0.f;

    for (int k0 = 0; k0 < K; k0 += 64) {
        const int k02 = k0 >> 1;
        for (int idx = tid; idx < 1024; idx += 256) {
            int kk = idx >> 5, m4 = idx & 31;
            uint4 v = *(const uint4*)&wT2[(size_t)(k02 + kk) * Co + c0 + (m4 << 2)];
            *(uint4*)&A_s[kk][m4 << 2] = v;
        }
        {
            const int k = k0 + 2 * sk;
            const int ci = k >> 4, t = k & 15, kh = t >> 2, kw = t & 3;
            const size_t base = ((size_t)(b * Ci + ci) * Hp + 2 * oh + kh) * Wp2 + ow;
            u32 us[18];
            const uint4* q4 = (const uint4*)(mir + base);
#pragma unroll
            for (int i = 0; i < 4; i++) {
                uint4 v = q4[i];
                us[4 * i] = v.x; us[4 * i + 1] = v.y;
                us[4 * i + 2] = v.z; us[4 * i + 3] = v.w;
            }
            us[16] = mir[base + 16];
            us[17] = mir[base + 17];
            const bool a1 = (kw & 2) != 0, od = (kw & 1) != 0;
            u32* dst = &B_s[sk][sn0];
#pragma unroll
            for (int j = 0; j < 16; j++) {
                u32 x0 = a1 ? us[j + 1] : us[j];
                u32 x1 = a1 ? us[j + 2] : us[j + 1];
                dst[j] = od ? prmt(x0, x1, 0x5432) : x0;
            }
        }
        __syncthreads();
#pragma unroll
        for (int s = 0; s < 4; s++) {
            const int k2b = s * 8;
            u32 a[2][4], bf[8][2];
#pragma unroll
            for (int mi = 0; mi < 2; mi++) {
                a[mi][0] = A_s[k2b + tig][m0w + mi * 16 + gid];
                a[mi][1] = A_s[k2b + tig][m0w + mi * 16 + gid + 8];
                a[mi][2] = A_s[k2b + tig + 4][m0w + mi * 16 + gid];
                a[mi][3] = A_s[k2b + tig + 4][m0w + mi * 16 + gid + 8];
            }
#pragma unroll
            for (int ni = 0; ni < 8; ni++) {
                bf[ni][0] = B_s[k2b + tig][n0w + ni * 8 + gid];
                bf[ni][1] = B_s[k2b + tig + 4][n0w + ni * 8 + gid];
            }
#pragma unroll
            for (int mi = 0; mi < 2; mi++)
#pragma unroll
                for (int ni = 0; ni < 8; ni++)
                    MMA_F16(acc[mi][ni], a[mi][0], a[mi][1], a[mi][2], a[mi][3],
                            bf[ni][0], bf[ni][1]);
        }
        __syncthreads();
    }

#pragma unroll
    for (int mi = 0; mi < 2; mi++)
#pragma unroll
        for (int h = 0; h < 2; h++) {
            const int co = c0 + m0w + mi * 16 + gid + h * 8;
            const float bv = bias[co];
#pragma unroll
            for (int ni = 0; ni < 8; ni++) {
                const int n = n0w + ni * 8 + 2 * tig;
                const int ohl = n >> w_shift, owl = n & (OWT - 1);
                float2 o = {acc[mi][ni][h * 2] + bv, acc[mi][ni][h * 2 + 1] + bv};
                if (relu) { o.x = fmaxf(o.x, 0.f); o.y = fmaxf(o.y, 0.f); }
                *(float2*)&out[((size_t)(b * Co + co) * Ho + oh0 + ohl) * Wo + ow0 + owl] = o;
            }
        }
}

// ===========================================================================
// HMMA conv-transpose k4 s2 p1 per-parity (mirror input, vectorized staging).
// ===========================================================================

__global__ void __launch_bounds__(256) tconv_tcf(
    const u32* __restrict__ mir, const u32* __restrict__ wT2,
    const float* __restrict__ bias, float* __restrict__ out,
    int Ci, int Co, int Hi, int Wi, int Hp, int Wp2, int w_shift, int relu_out)
{
    __shared__ u32 A_s[32][136];
    __shared__ u32 B_s[32][136];
    const int tid = threadIdx.x;
    const int lane = tid & 31, warp = tid >> 5;
    const int gid = lane >> 2, tig = lane & 3;
    const int m0w = (warp & 3) * 32, n0w = (warp >> 2) * 64;
    const int OWT = 1 << w_shift;
    const int ow0 = blockIdx.x * OWT, oh0 = blockIdx.y * (128 >> w_shift);
    const int p = blockIdx.z & 3;
    const int rest = blockIdx.z >> 2;
    const int cot = Co >> 7;
    const int b = rest / cot, c0 = (rest % cot) << 7;
    const int pa = p >> 1, pb = p & 1;
    const int K = Ci << 2, K2 = Ci << 1;
    const int Ho = 2 * Hi, Wo2 = 2 * Wi;
    const u32* wTp = wT2 + (size_t)p * K2 * Co;

    const int sk = tid >> 3;
    const int sn0 = (tid & 7) << 4;
    const int mh = oh0 + (sn0 >> w_shift);
    const int mw = ow0 + (sn0 & (OWT - 1));

    float acc[2][8][4];
#pragma unroll
    for (int mi = 0; mi < 2; mi++)
#pragma unroll
        for (int ni = 0; ni < 8; ni++)
#pragma unroll
            for (int c = 0; c < 4; c++) acc[mi][ni][c] = 0.f;

    for (int k0 = 0; k0 < K; k0 += 64) {
        const int k02 = k0 >> 1;
        for (int idx = tid; idx < 1024; idx += 256) {
            int kk = idx >> 5, m4 = idx & 31;
            uint4 v = *(const uint4*)&wTp[(size_t)(k02 + kk) * Co + c0 + (m4 << 2)];
            *(uint4*)&A_s[kk][m4 << 2] = v;
        }
        {
            const int k = k0 + 2 * sk;
            const int ci = k >> 2, j2 = k & 3;
            const int kh = (1 - pa) + 2 * (j2 >> 1);
            const int dm = (kh == 0) ? 1 : ((kh == 3) ? -1 : 0);
            const size_t base = ((size_t)(b * Ci + ci) * Hp + mh + dm + 1) * Wp2 + (mw >> 1);
            u32 us[9];
            const uint4* q4 = (const uint4*)(mir + base);
#pragma unroll
            for (int i = 0; i < 2; i++) {
                uint4 v = q4[i];
                us[4 * i] = v.x; us[4 * i + 1] = v.y;
                us[4 * i + 2] = v.z; us[4 * i + 3] = v.w;
            }
            us[8] = mir[base + 8];
            u32* dst = &B_s[sk][sn0];
            if (pb == 0) {
#pragma unroll
                for (int q = 0; q < 8; q++) {
                    u32 a = us[q], bb = us[q + 1];
                    dst[2 * q]     = prmt(a, a, 0x1032);
                    dst[2 * q + 1] = prmt(a, bb, 0x3254);
                }
            } else {
#pragma unroll
                for (int q = 0; q < 8; q++) {
                    u32 a = us[q], bb = us[q + 1];
                    dst[2 * q]     = prmt(a, bb, 0x3254);
                    dst[2 * q + 1] = prmt(bb, bb, 0x1032);
                }
            }
        }
        __syncthreads();
#pragma unroll
        for (int s = 0; s < 4; s++) {
            const int k2b = s * 8;
            u32 a[2][4], bf[8][2];
#pragma unroll
            for (int mi = 0; mi < 2; mi++) {
                a[mi][0] = A_s[k2b + tig][m0w + mi * 16 + gid];
                a[mi][1] = A_s[k2b + tig][m0w + mi * 16 + gid + 8];
                a[mi][2] = A_s[k2b + tig + 4][m0w + mi * 16 + gid];
                a[mi][3] = A_s[k2b + tig + 4][m0w + mi * 16 + gid + 8];
            }
#pragma unroll
            for (int ni = 0; ni < 8; ni++) {
                bf[ni][0] = B_s[k2b + tig][n0w + ni * 8 + gid];
                bf[ni][1] = B_s[k2b + tig + 4][n0w + ni * 8 + gid];
            }
#pragma unroll
            for (int mi = 0; mi < 2; mi++)
#pragma unroll
                for (int ni = 0; ni < 8; ni++)
                    MMA_F16(acc[mi][ni], a[mi][0], a[mi][1], a[mi][2], a[mi][3],
                            bf[ni][0], bf[ni][1]);
        }
        __syncthreads();
    }

#pragma unroll
    for (int mi = 0; mi < 2; mi++)
#pragma unroll
        for (int h = 0; h < 2; h++) {
            const int co = c0 + m0w + mi * 16 + gid + h * 8;
            const float bv = bias[co];
#pragma unroll
            for (int ni = 0; ni < 8; ni++) {
                const int n = n0w + ni * 8 + 2 * tig;
                const int mhh = oh0 + (n >> w_shift);
                const int mww = ow0 + (n & (OWT - 1));
                float v0 = acc[mi][ni][h * 2] + bv;
                float v1 = acc[mi][ni][h * 2 + 1] + bv;
                if (relu_out) { v0 = fmaxf(v0, 0.f); v1 = fmaxf(v1, 0.f); }
                float* orow = &out[((size_t)(b * Co + co) * Ho + 2 * mhh + pa) * Wo2];
                orow[2 * mww + pb] = v0;
                orow[2 * (mww + 1) + pb] = v1;
            }
        }
}

// ===========================================================================
// HMMA 3x3 res conv (proven)
// ===========================================================================

__global__ void __launch_bounds__(256) conv3x3_tcf(
    const float* __restrict__ in, const u32* __restrict__ wT2,
    float* __restrict__ out, int Ci, int HW, int hw_shift)
{
    __shared__ u32 A_s[32][40];
    __shared__ u32 B_s[32][264];
    const int tid = threadIdx.x;
    const int lane = tid & 31, warp = tid >> 5;
    const int gid = lane >> 2, tig = lane & 3;
    const int n0w = warp * 32;
    const int p0 = blockIdx.x * 256;
    const int b = blockIdx.z;
    const int K = Ci * 9;

    const int sk = tid >> 3;
    const int sn0 = (tid & 7) << 5;
    const int ng0 = p0 + sn0;
    const int s_oh = ng0 >> hw_shift;
    const int s_ow = ng0 & (HW - 1);

    float acc[2][4][4];
#pragma unroll
    for (int mi = 0; mi < 2; mi++)
#pragma unroll
        for (int ni = 0; ni < 4; ni++)
#pragma unroll
            for (int c = 0; c < 4; c++) acc[mi][ni][c] = 0.f;

    for (int k0 = 0; k0 < K; k0 += 64) {
        const int k02 = k0 >> 1;
        for (int idx = tid; idx < 1024; idx += 256) {
            int kk = idx >> 5, m = idx & 31;
            A_s[kk][m] = wT2[(size_t)(k02 + kk) * 32 + m];
        }
        {
            const int klo = k0 + 2 * sk, khi = klo + 1;
            const int ci0 = klo / 9, t0 = klo - ci0 * 9;
            const int ci1 = khi / 9, t1 = khi - ci1 * 9;
            const int kh0 = t0 / 3, kw0 = t0 - 3 * kh0;
            const int kh1 = t1 / 3, kw1 = t1 - 3 * kh1;
            const int ih0 = s_oh - 1 + kh0, ih1 = s_oh - 1 + kh1;
            const bool ok0 = (unsigned)ih0 < (unsigned)HW;
            const bool ok1 = (unsigned)ih1 < (unsigned)HW;
            const float* r0 = in + ((size_t)(b * Ci + ci0) * HW + ih0) * HW;
            const float* r1 = in + ((size_t)(b * Ci + ci1) * HW + ih1) * HW;
            const int iwb0 = s_ow - 1 + kw0, iwb1 = s_ow - 1 + kw1;
#pragma unroll
            for (int jj = 0; jj < 32; jj++) {
                const int iw0 = iwb0 + jj, iw1 = iwb1 + jj;
                float v0 = (ok0 && (unsigned)iw0 < (unsigned)HW) ? fmaxf(r0[iw0], 0.f) : 0.f;
                float v1 = (ok1 && (unsigned)iw1 < (unsigned)HW) ? fmaxf(r1[iw1], 0.f) : 0.f;
                B_s[sk][sn0 + jj] = pack_f16x2(v0, v1);
            }
        }
        __syncthreads();
#pragma unroll
        for (int s = 0; s < 4; s++) {
            const int k2b = s * 8;
            u32 a[2][4], bf[4][2];
#pragma unroll
            for (int mi = 0; mi < 2; mi++) {
                a[mi][0] = A_s[k2b + tig][mi * 16 + gid];
                a[mi][1] = A_s[k2b + tig][mi * 16 + gid + 8];
                a[mi][2] = A_s[k2b + tig + 4][mi * 16 + gid];
                a[mi][3] = A_s[k2b + tig + 4][mi * 16 + gid + 8];
            }
#pragma unroll
            for (int ni = 0; ni < 4; ni++) {
                bf[ni][0] = B_s[k2b + tig][n0w + ni * 8 + gid];
                bf[ni][1] = B_s[k2b + tig + 4][n0w + ni * 8 + gid];
            }
#pragma unroll
            for (int mi = 0; mi < 2; mi++)
#pragma unroll
                for (int ni = 0; ni < 4; ni++)
                    MMA_F16(acc[mi][ni], a[mi][0], a[mi][1], a[mi][2], a[mi][3],
                            bf[ni][0], bf[ni][1]);
        }
        __syncthreads();
    }

#pragma unroll
    for (int mi = 0; mi < 2; mi++)
#pragma unroll
        for (int h = 0; h < 2; h++) {
            const int co = mi * 16 + gid + h * 8;
#pragma unroll
            for (int ni = 0; ni < 4; ni++) {
                const int ng = p0 + n0w + ni * 8 + 2 * tig;
                const int oh = ng >> hw_shift, ow = ng & (HW - 1);
                float2 o = {acc[mi][ni][h * 2], acc[mi][ni][h * 2 + 1]};
                *(float2*)&out[((size_t)(b * 32 + co) * HW + oh) * HW + ow] = o;
            }
        }
}

// ===========================================================================
extern "C" void kernel_launch(void* const* d_in, const int* in_sizes, int n_in,
                              void* d_out, int out_size)
{
    (void)in_sizes; (void)n_in;
    const float* x       = (const float*)d_in[0];
    const float* enc_w1  = (const float*)d_in[1];
    const float* enc_b1  = (const float*)d_in[2];
    const float* enc_w2  = (const float*)d_in[3];
    const float* enc_b2  = (const float*)d_in[4];
    const float* enc_w3  = (const float*)d_in[5];
    const float* enc_b3  = (const float*)d_in[6];
    const float* enc_rw3 = (const float*)d_in[7];
    const float* enc_rw1 = (const float*)d_in[8];
    const float* prevq_w = (const float*)d_in[9];
    const float* prevq_b = (const float*)d_in[10];
    const float* emb     = (const float*)d_in[11];
    const float* dec_w1  = (const float*)d_in[12];
    const float* dec_b1  = (const float*)d_in[13];
    const float* dec_rw3 = (const float*)d_in[14];
    const float* dec_rw1 = (const float*)d_in[15];
    const float* dec_w2  = (const float*)d_in[16];
    const float* dec_b2  = (const float*)d_in[17];
    const float* dec_w3  = (const float*)d_in[18];
    const float* dec_b3  = (const float*)d_in[19];
    float* out = (float*)d_out;

    float *b0, *b1, *b2, *b3, *ze, *zq, *loss;
    u32 *wt, *mx, *m0, *m1, *mq;
    cudaGetSymbolAddress((void**)&b0, g_b0);
    cudaGetSymbolAddress((void**)&b1, g_b1);
    cudaGetSymbolAddress((void**)&b2, g_b2);
    cudaGetSymbolAddress((void**)&b3, g_b3);
    cudaGetSymbolAddress((void**)&ze, g_ze);
    cudaGetSymbolAddress((void**)&zq, g_zq);
    cudaGetSymbolAddress((void**)&loss, g_loss);
    cudaGetSymbolAddress((void**)&wt, g_wt);
    cudaGetSymbolAddress((void**)&mx, g_mx);
    cudaGetSymbolAddress((void**)&m0, g_m0);
    cudaGetSymbolAddress((void**)&m1, g_m1);
    cudaGetSymbolAddress((void**)&mq, g_mq);

    // ---- encoder ----
    cvt_mirror<<<17028, 256>>>(x, mx, 128, 256, 256, 258, 132, 0, 3, 4);
    wt4s2_f16<<<16, 256>>>(enc_w1, wt, 4, 128, 3);
    conv4s2_tcf<<<dim3(1, 128, 32), 256>>>(mx, wt, enc_b1, b0, 4, 128, 258, 132, 128, 128, 7, 1);

    cvt_mirror<<<141480, 256>>>(b0, m0, 4096, 128, 128, 130, 68, 0, 128, 128);
    wt4s2_f16<<<1024, 256>>>(enc_w2, wt, 128, 256, 128);
    conv4s2_tcf<<<dim3(1, 32, 64), 256>>>(m0, wt, enc_b2, b1, 128, 256, 130, 68, 64, 64, 6, 1);

    cvt_mirror<<<76032, 256>>>(b1, m1, 8192, 64, 64, 66, 36, 0, 256, 256);
    wt4s2_f16<<<4096, 256>>>(enc_w3, wt, 256, 512, 256);
    conv4s2_tcf<<<dim3(1, 8, 128), 256>>>(m1, wt, enc_b3, b2, 256, 512, 66, 36, 32, 32, 5, 0);

    wt3_f16<<<288, 256>>>(enc_rw3, wt, 512);
    for (int l = 0; l < 2; l++) {
        conv3x3_tcf<<<dim3(4, 1, 32), 256>>>(b2, wt, b3, 512, 32, 5);
        conv1x1_kernel<<<dim3(16, 8, 32), 256>>>(b3, enc_rw1, nullptr, b2, 32, 512, 1024, 1, 1);
    }
    conv1x1_kernel<<<dim3(16, 1, 32), 256>>>(b2, prevq_w, prevq_b, ze, 512, 64, 1024, 1, 0);

    // ---- VQ ----
    zero_loss_kernel<<<1, 1>>>(loss);
    vq_kernel<<<128, 256>>>(ze, emb, zq, loss);
    finish_loss_kernel<<<1, 1>>>(loss, out + (out_size - 1));

    // ---- decoder ----
    cvt_mirror<<<5440, 256>>>(zq, mq, 2048, 32, 32, 34, 20, 0, 64, 64);
    wtT_f16<<<512, 256>>>(dec_w1, wt, 64, 256);
    tconv_tcf<<<dim3(1, 8, 256), 256>>>(mq, wt, dec_b1, b1, 64, 256, 32, 32, 34, 20, 5, 0);

    wt3_f16<<<144, 256>>>(dec_rw3, wt, 256);
    for (int l = 0; l < 2; l++) {
        conv3x3_tcf<<<dim3(16, 1, 32), 256>>>(b1, wt, b3, 256, 64, 6);
        conv1x1_kernel<<<dim3(64, 4, 32), 256>>>(b3, dec_rw1, nullptr, b1, 32, 256, 4096, 1, 1);
    }

    cvt_mirror<<<76032, 256>>>(b1, m1, 8192, 64, 64, 66, 36, 1, 256, 256);
    wtT_f16<<<1024, 256>>>(dec_w2, wt, 256, 128);
    tconv_tcf<<<dim3(1, 32, 128), 256>>>(m1, wt, dec_b2, b0, 256, 128, 64, 64, 66, 36, 6, 1);

    tconv_kernel<4, 1, 16, 16><<<dim3(8, 8, 32), 256>>>(b0, dec_w3, dec_b3, out, 128, 3, 128, 128, 0, 0);
}

// round 10
// speedup vs baseline: 4.8708x; 1.0019x over previous
#include <cuda_runtime.h>

typedef unsigned int u32;

__device__ float g_b0[32u * 128 * 128 * 128];
__device__ float g_b1[32u * 256 * 64 * 64];
__device__ float g_b2[32u * 512 * 32 * 32];
__device__ float g_b3[32u * 32 * 64 * 64];
__device__ float g_ze[32u * 64 * 32 * 32];
__device__ float g_zq[32u * 64 * 32 * 32];
__device__ float g_loss[1];
__device__ u32   g_wt[2097152];
__device__ u32   g_mx[4359168];    // enc1 mirror: 128 x 258 x 132 u32
__device__ u32   g_m0[36218880];   // enc2 mirror: 4096 x 130 x 68 u32
__device__ u32   g_m1[19464192];   // enc3/dec2 mirror: 8192 x 66 x 36 u32
__device__ u32   g_mq[1392640];    // dec1 mirror: 2048 x 34 x 20 u32

__device__ __forceinline__ u32 pack_f16x2(float lo, float hi) {
    u32 r; asm("cvt.rn.f16x2.f32 %0,%1,%2;" : "=r"(r) : "f"(hi), "f"(lo)); return r;
}
__device__ __forceinline__ u32 prmt(u32 a, u32 b, u32 s) {
    u32 r; asm("prmt.b32 %0,%1,%2,%3;" : "=r"(r) : "r"(a), "r"(b), "r"(s)); return r;
}
__device__ __forceinline__ u32 smem_u32(const void* p) {
    u32 a; asm("{ .reg .u64 t; cvta.to.shared.u64 t,%1; cvt.u32.u64 %0,t; }"
               : "=r"(a) : "l"(p));
    return a;
}

#define CP_A16(d, s) asm volatile("cp.async.ca.shared.global [%0],[%1],16;" :: "r"(d), "l"(s))
#define CP_A4(d, s)  asm volatile("cp.async.ca.shared.global [%0],[%1],4;"  :: "r"(d), "l"(s))
#define CP_COMMIT()  asm volatile("cp.async.commit_group;" ::: "memory")
#define CP_WAIT0()   asm volatile("cp.async.wait_group 0;" ::: "memory")
#define CP_WAIT1()   asm volatile("cp.async.wait_group 1;" ::: "memory")

#define MMA_F16(d, a0, a1, a2, a3, b0, b1)                                    \
    asm volatile("mma.sync.aligned.m16n8k16.row.col.f32.f16.f16.f32 "         \
                 "{%0,%1,%2,%3},{%4,%5,%6,%7},{%8,%9},{%0,%1,%2,%3};"         \
                 : "+f"(d[0]), "+f"(d[1]), "+f"(d[2]), "+f"(d[3])             \
                 : "r"(a0), "r"(a1), "r"(a2), "r"(a3), "r"(b0), "r"(b1))

// ---- mirror build: per-plane grid (blockIdx.y = dst channel-plane) --------
__global__ void cvt_mirror(const float* __restrict__ src, u32* __restrict__ dst,
                           int Hi, int Wi, int Hp, int Wp2, int relu,
                           int scpb, int dshift)
{
    const int plane = blockIdx.y;
    const int idx = blockIdx.x * 256 + threadIdx.x;
    if (idx >= Hp * Wp2) return;
    const int ph = idx / Wp2, wp2 = idx - ph * Wp2;
    const int b = plane >> dshift;
    const int c = plane & ((1 << dshift) - 1);
    const int ih = ph - 1;
    const int iw0 = 2 * wp2 - 1, iw1 = iw0 + 1;
    float v0 = 0.f, v1 = 0.f;
    if (c < scpb && (unsigned)ih < (unsigned)Hi) {
        const float* r = src + ((size_t)(b * scpb + c) * Hi + ih) * Wi;
        if ((unsigned)iw0 < (unsigned)Wi) v0 = r[iw0];
        if ((unsigned)iw1 < (unsigned)Wi) v1 = r[iw1];
    }
    if (relu) { v0 = fmaxf(v0, 0.f); v1 = fmaxf(v1, 0.f); }
    dst[(size_t)plane * Hp * Wp2 + idx] = pack_f16x2(v0, v1);
}

// ===========================================================================
// fp32 kernels (proven)
// ===========================================================================

__global__ void __launch_bounds__(256) conv1x1_kernel(
    const float* __restrict__ in, const float* __restrict__ w,
    const float* __restrict__ bias, float* __restrict__ out,
    int Ci, int Co, int P, int relu_in, int add_res)
{
    __shared__ float w_s[16][64];
    __shared__ float x_s[16][64];
    const int tid = threadIdx.x;
    const int tx = tid & 15, ty = tid >> 4;
    const int p0 = blockIdx.x * 64, c0 = blockIdx.y * 64, b = blockIdx.z;

    float acc[4][4];
#pragma unroll
    for (int i = 0; i < 4; i++)
#pragma unroll
        for (int j = 0; j < 4; j++) acc[i][j] = 0.f;

    for (int ci0 = 0; ci0 < Ci; ci0 += 16) {
        for (int idx = tid; idx < 1024; idx += 256) {
            int p = idx & 63, ci = idx >> 6;
            float v = in[(size_t)(b * Ci + ci0 + ci) * P + p0 + p];
            x_s[ci][p] = relu_in ? fmaxf(v, 0.f) : v;
        }
        for (int idx = tid; idx < 1024; idx += 256) {
            int ci = idx & 15, co = idx >> 4;
            w_s[ci][co] = w[(size_t)(c0 + co) * Ci + ci0 + ci];
        }
        __syncthreads();
#pragma unroll
        for (int ci = 0; ci < 16; ci++) {
            const float4 wv = *(const float4*)&w_s[ci][ty << 2];
            const float4 xv = *(const float4*)&x_s[ci][tx << 2];
            const float wvv[4] = {wv.x, wv.y, wv.z, wv.w};
            const float xvv[4] = {xv.x, xv.y, xv.z, xv.w};
#pragma unroll
            for (int i = 0; i < 4; i++)
#pragma unroll
                for (int j = 0; j < 4; j++)
                    acc[i][j] = fmaf(wvv[i], xvv[j], acc[i][j]);
        }
        __syncthreads();
    }
#pragma unroll
    for (int i = 0; i < 4; i++) {
        const int co = c0 + (ty << 2) + i;
        const float bv = bias ? bias[co] : 0.f;
        const size_t base = (size_t)(b * Co + co) * P + p0 + (tx << 2);
        float4 o = {acc[i][0] + bv, acc[i][1] + bv, acc[i][2] + bv, acc[i][3] + bv};
        if (add_res) {
            float4 rr = *(const float4*)&out[base];
            o.x += rr.x; o.y += rr.y; o.z += rr.z; o.w += rr.w;
        }
        *(float4*)&out[base] = o;
    }
}

__global__ void __launch_bounds__(256) vq_kernel(
    const float* __restrict__ ze, const float* __restrict__ emb,
    float* __restrict__ zq, float* __restrict__ loss)
{
    __shared__ float e_s[128 * 64];
    __shared__ float n_s[128];
    const int tid = threadIdx.x;
    const int n = blockIdx.x * 256 + tid;
    const int b = n >> 10, hw = n & 1023;

    float xr[64];
#pragma unroll
    for (int d = 0; d < 64; d++)
        xr[d] = ze[((size_t)(b * 64 + d) << 10) + hw];

    float best = 3.4e38f;
    int bi = 0;
    for (int kb = 0; kb < 4; kb++) {
        __syncthreads();
        for (int i = tid; i < 128 * 64; i += 256) e_s[i] = emb[kb * 128 * 64 + i];
        __syncthreads();
        if (tid < 128) {
            float s = 0.f;
#pragma unroll 8
            for (int d = 0; d < 64; d++) { float v = e_s[tid * 64 + d]; s = fmaf(v, v, s); }
            n_s[tid] = s;
        }
        __syncthreads();
        for (int k = 0; k < 128; k++) {
            const float4* e4 = (const float4*)(e_s + k * 64);
            float dot = 0.f;
#pragma unroll
            for (int d4 = 0; d4 < 16; d4++) {
                float4 e = e4[d4];
                dot = fmaf(e.x, xr[d4 * 4 + 0], dot);
                dot = fmaf(e.y, xr[d4 * 4 + 1], dot);
                dot = fmaf(e.z, xr[d4 * 4 + 2], dot);
                dot = fmaf(e.w, xr[d4 * 4 + 3], dot);
            }
            float dist = n_s[k] - 2.f * dot;
            if (dist < best) { best = dist; bi = kb * 128 + k; }
        }
    }

    float ls = 0.f;
#pragma unroll
    for (int d = 0; d < 64; d++) {
        float e = emb[bi * 64 + d];
        zq[((size_t)(b * 64 + d) << 10) + hw] = e;
        float df = e - xr[d];
        ls = fmaf(df, df, ls);
    }
#pragma unroll
    for (int o = 16; o > 0; o >>= 1) ls += __shfl_down_sync(0xffffffffu, ls, o);
    if ((tid & 31) == 0) atomicAdd(loss, ls);
}

template <int CO_TILE, int CO_PT, int M_TILE, int N_TILE>
__global__ void __launch_bounds__(256) tconv_kernel(
    const float* __restrict__ in, const float* __restrict__ w,
    const float* __restrict__ bias, float* __restrict__ out,
    int Ci, int Co, int Hi, int Wi, int relu_in, int relu_out)
{
    constexpr int NSLOT = (M_TILE * N_TILE) / 4;
    constexpr int CG = CO_TILE / CO_PT;
    static_assert(NSLOT * CG == 256, "map");
    __shared__ float w_s[4][16][CO_TILE];
    __shared__ float x_s[4][M_TILE + 2][N_TILE + 2];

    const int tid = threadIdx.x;
    const int slot = tid % NSLOT, cg = tid / NSLOT;
    const int m_loc = slot / (N_TILE / 4);
    const int nb = (slot % (N_TILE / 4)) * 4;
    const int n0 = blockIdx.x * N_TILE, m0 = blockIdx.y * M_TILE;
    const int cot = (Co + CO_TILE - 1) / CO_TILE;
    const int b = blockIdx.z / cot, c0 = (blockIdx.z % cot) * CO_TILE;
    const int Ho = 2 * Hi, Wo2 = 2 * Wi;

    float acc[CO_PT][4][2][2];
#pragma unroll
    for (int i = 0; i < CO_PT; i++)
#pragma unroll
        for (int q = 0; q < 4; q++)
#pragma unroll
            for (int a = 0; a < 2; a++)
#pragma unroll
                for (int bb = 0; bb < 2; bb++) acc[i][q][a][bb] = 0.f;

    for (int ci0 = 0; ci0 < Ci; ci0 += 4) {
        for (int idx = tid; idx < 4 * (M_TILE + 2) * (N_TILE + 2); idx += 256) {
            int lc = idx % (N_TILE + 2);
            int t = idx / (N_TILE + 2);
            int lr = t % (M_TILE + 2), ci = t / (M_TILE + 2);
            int m = m0 - 1 + lr, nn = n0 - 1 + lc;
            float v = 0.f;
            if ((unsigned)m < (unsigned)Hi && (unsigned)nn < (unsigned)Wi)
                v = in[((size_t)(b * Ci + ci0 + ci) * Hi + m) * Wi + nn];
            if (relu_in) v = fmaxf(v, 0.f);
            x_s[ci][lr][lc] = v;
        }
        for (int idx = tid; idx < 4 * 16 * CO_TILE; idx += 256) {
            int t = idx & 15;
            int co = (idx >> 4) % CO_TILE;
            int ci = idx / (16 * CO_TILE);
            float v = 0.f;
            if (c0 + co < Co) v = w[((size_t)(ci0 + ci) * Co + c0 + co) * 16 + t];
            w_s[ci][t][co] = v;
        }
        __syncthreads();
#pragma unroll
        for (int ci = 0; ci < 4; ci++)
#pragma unroll
            for (int t = 0; t < 16; t++) {
                const int kh = t >> 2, kw = t & 3;
                const int a = 1 - (kh & 1);
                const int dm = (kh == 0) ? 1 : ((kh == 3) ? -1 : 0);
                const int bb = 1 - (kw & 1);
                const int dn = (kw == 0) ? 1 : ((kw == 3) ? -1 : 0);
                float wr[CO_PT];
#pragma unroll
                for (int i = 0; i < CO_PT; i++)
                    wr[i] = w_s[ci][t][cg * CO_PT + i];
                const float* xrow = &x_s[ci][m_loc + dm + 1][nb + dn + 1];
#pragma unroll
                for (int q = 0; q < 4; q++) {
                    const float xv = xrow[q];
#pragma unroll
                    for (int i = 0; i < CO_PT; i++)
                        acc[i][q][a][bb] = fmaf(wr[i], xv, acc[i][q][a][bb]);
                }
            }
        __syncthreads();
    }

    const int m = m0 + m_loc;
#pragma unroll
    for (int i = 0; i < CO_PT; i++) {
        const int co = c0 + cg * CO_PT + i;
        if (co < Co) {
            const float bv = bias[co];
#pragma unroll
            for (int q = 0; q < 4; q++) {
                const int nn = n0 + nb + q;
#pragma unroll
                for (int a = 0; a < 2; a++) {
                    float2 o = {acc[i][q][a][0] + bv, acc[i][q][a][1] + bv};
                    if (relu_out) { o.x = fmaxf(o.x, 0.f); o.y = fmaxf(o.y, 0.f); }
                    *(float2*)&out[((size_t)(b * Co + co) * Ho + 2 * m + a) * Wo2 + 2 * nn] = o;
                }
            }
        }
    }
}

__global__ void zero_loss_kernel(float* loss) { loss[0] = 0.f; }
__global__ void finish_loss_kernel(const float* __restrict__ loss, float* __restrict__ dst)
{
    dst[0] = 2.f * loss[0] / 2097152.f;
}

// ===========================================================================
// weight prepacks (fp16)
// ===========================================================================

__global__ void wt4s2_f16(const float* __restrict__ w, u32* __restrict__ wT2,
                          int Ci, int Co, int Ci_src)
{
    int idx = blockIdx.x * 256 + threadIdx.x;
    if (idx >= Ci * 8 * Co) return;
    int co = idx % Co, k2 = idx / Co;
    int k = 2 * k2, ci = k >> 4, t = k & 15;
    float v0 = 0.f, v1 = 0.f;
    if (ci < Ci_src) {
        const float* base = &w[((size_t)co * Ci_src + ci) * 16 + t];
        v0 = base[0]; v1 = base[1];
    }
    wT2[idx] = pack_f16x2(v0, v1);
}

__global__ void wtT_f16(const float* __restrict__ w, u32* __restrict__ wT2,
                        int Ci, int Co)
{
    int K2 = Ci * 2;
    int idx = blockIdx.x * 256 + threadIdx.x;
    if (idx >= 4 * K2 * Co) return;
    int co = idx % Co, rr = idx / Co;
    int p = rr / K2, k2 = rr % K2;
    int k = 2 * k2, ci = k >> 2, j = k & 3;
    int a = p >> 1, bb = p & 1;
    int kh = (1 - a) + 2 * (j >> 1);
    const float* base = &w[((size_t)ci * Co + co) * 16 + kh * 4];
    wT2[idx] = pack_f16x2(base[1 - bb], base[3 - bb]);
}

__global__ void wt3_f16(const float* __restrict__ w, u32* __restrict__ wT2, int Ci)
{
    int K = Ci * 9;
    int idx = blockIdx.x * 256 + threadIdx.x;
    if (idx >= (K / 2) * 32) return;
    int co = idx & 31, k2 = idx >> 5;
    int k0 = 2 * k2, k1 = k0 + 1;
    int ci0 = k0 / 9, t0 = k0 - ci0 * 9;
    int ci1 = k1 / 9, t1 = k1 - ci1 * 9;
    wT2[idx] = pack_f16x2(w[((size_t)co * Ci + ci0) * 9 + t0],
                          w[((size_t)co * Ci + ci1) * 9 + t1]);
}

// ===========================================================================
// HMMA conv k4 s2 p1 — cp.async double-buffered pipeline.
// dyn smem: [A0|A1|B0|B1], each 32x136 u32.
// ===========================================================================

#define CHBUF 4352

__global__ void __launch_bounds__(256, 2) conv4s2_tcf(
    const u32* __restrict__ mir, const u32* __restrict__ wT2,
    const float* __restrict__ bias, float* __restrict__ out,
    int Ci, int Co, int Hp, int Wp2, int Ho, int Wo, int w_shift, int relu)
{
    extern __shared__ u32 sm[];
    const int tid = threadIdx.x;
    const int lane = tid & 31, warp = tid >> 5;
    const int gid = lane >> 2, tig = lane & 3;
    const int m0w = (warp & 3) * 32, n0w = (warp >> 2) * 64;
    const int OWT = 1 << w_shift;
    const int ow0 = blockIdx.x * OWT, oh0 = blockIdx.y * (128 >> w_shift);
    const int cot = Co >> 7;
    const int b = blockIdx.z / cot, c0 = (blockIdx.z % cot) << 7;
    const int K = Ci << 4, NC = K >> 6;
    const int sk = tid >> 3, sn0 = (tid & 7) << 4;
    const int oh = oh0 + (sn0 >> w_shift), ow = ow0 + (sn0 & (OWT - 1));
    const u32 sb = smem_u32(sm);

    auto stage = [&](int c, int buf) {
        const int k02 = c << 5;
#pragma unroll
        for (int q = 0; q < 4; q++) {
            int idx = tid + (q << 8);
            int kk = idx >> 5, m4 = idx & 31;
            u32 dst = sb + ((u32)(buf * CHBUF + kk * 136 + (m4 << 2)) << 2);
            CP_A16(dst, wT2 + (size_t)(k02 + kk) * Co + c0 + (m4 << 2));
        }
        const int k = (c << 6) + 2 * sk;
        const int ci = k >> 4, t = k & 15, kh = t >> 2, a1 = (t & 3) >> 1;
        const u32* src = mir + ((size_t)(b * Ci + ci) * Hp + 2 * oh + kh) * Wp2 + ow + a1;
        u32 dst = sb + ((u32)(2 * CHBUF + buf * CHBUF + sk * 136 + sn0) << 2);
        if (!a1) {
#pragma unroll
            for (int j = 0; j < 4; j++) CP_A16(dst + 16 * j, src + 4 * j);
        } else {
#pragma unroll
            for (int j = 0; j < 16; j++) CP_A4(dst + 4 * j, src + j);
        }
    };

    float acc[2][8][4];
#pragma unroll
    for (int mi = 0; mi < 2; mi++)
#pragma unroll
        for (int ni = 0; ni < 8; ni++)
#pragma unroll
            for (int c = 0; c < 4; c++) acc[mi][ni][c] = 0.f;

    stage(0, 0);
    CP_COMMIT();

    for (int c = 0; c < NC; c++) {
        if (c + 1 < NC) { stage(c + 1, (c + 1) & 1); CP_COMMIT(); CP_WAIT1(); }
        else CP_WAIT0();
        __syncthreads();
        const u32* As = sm + (c & 1) * CHBUF;
        const u32* Bs = sm + 2 * CHBUF + (c & 1) * CHBUF;
#pragma unroll
        for (int s = 0; s < 4; s++) {
            const int k2b = s * 8;
            u32 a[2][4], bf[8][2];
#pragma unroll
            for (int mi = 0; mi < 2; mi++) {
                a[mi][0] = As[(k2b + tig) * 136 + m0w + mi * 16 + gid];
                a[mi][1] = As[(k2b + tig) * 136 + m0w + mi * 16 + gid + 8];
                a[mi][2] = As[(k2b + tig + 4) * 136 + m0w + mi * 16 + gid];
                a[mi][3] = As[(k2b + tig + 4) * 136 + m0w + mi * 16 + gid + 8];
            }
#pragma unroll
            for (int ni = 0; ni < 8; ni++) {
                bf[ni][0] = Bs[(k2b + tig) * 136 + n0w + ni * 8 + gid];
                bf[ni][1] = Bs[(k2b + tig + 4) * 136 + n0w + ni * 8 + gid];
            }
#pragma unroll
            for (int mi = 0; mi < 2; mi++)
#pragma unroll
                for (int ni = 0; ni < 8; ni++)
                    MMA_F16(acc[mi][ni], a[mi][0], a[mi][1], a[mi][2], a[mi][3],
                            bf[ni][0], bf[ni][1]);
        }
        __syncthreads();
    }

#pragma unroll
    for (int mi = 0; mi < 2; mi++)
#pragma unroll
        for (int h = 0; h < 2; h++) {
            const int co = c0 + m0w + mi * 16 + gid + h * 8;
            const float bv = bias[co];
#pragma unroll
            for (int ni = 0; ni < 8; ni++) {
                const int n = n0w + ni * 8 + 2 * tig;
                const int ohl = n >> w_shift, owl = n & (OWT - 1);
                float2 o = {acc[mi][ni][h * 2] + bv, acc[mi][ni][h * 2 + 1] + bv};
                if (relu) { o.x = fmaxf(o.x, 0.f); o.y = fmaxf(o.y, 0.f); }
                *(float2*)&out[((size_t)(b * Co + co) * Ho + oh0 + ohl) * Wo + ow0 + owl] = o;
            }
        }
}

// ===========================================================================
// HMMA conv-transpose k4 s2 p1 per-parity — A cp.async, B LDG-prefetch pipe.
// ===========================================================================

__global__ void __launch_bounds__(256, 2) tconv_tcf(
    const u32* __restrict__ mir, const u32* __restrict__ wT2,
    const float* __restrict__ bias, float* __restrict__ out,
    int Ci, int Co, int Hi, int Wi, int Hp, int Wp2, int w_shift, int relu_out)
{
    extern __shared__ u32 sm[];
    const int tid = threadIdx.x;
    const int lane = tid & 31, warp = tid >> 5;
    const int gid = lane >> 2, tig = lane & 3;
    const int m0w = (warp & 3) * 32, n0w = (warp >> 2) * 64;
    const int OWT = 1 << w_shift;
    const int ow0 = blockIdx.x * OWT, oh0 = blockIdx.y * (128 >> w_shift);
    const int p = blockIdx.z & 3;
    const int rest = blockIdx.z >> 2;
    const int cot = Co >> 7;
    const int b = rest / cot, c0 = (rest % cot) << 7;
    const int pa = p >> 1, pb = p & 1;
    const int K = Ci << 2, K2 = Ci << 1, NC = K >> 6;
    const int Ho = 2 * Hi, Wo2 = 2 * Wi;
    const u32* wTp = wT2 + (size_t)p * K2 * Co;
    const int sk = tid >> 3, sn0 = (tid & 7) << 4;
    const int mh = oh0 + (sn0 >> w_shift), mw = ow0 + (sn0 & (OWT - 1));
    const u32 sb = smem_u32(sm);

    auto stageA = [&](int c, int buf) {
        const int k02 = c << 5;
#pragma unroll
        for (int q = 0; q < 4; q++) {
            int idx = tid + (q << 8);
            int kk = idx >> 5, m4 = idx & 31;
            u32 dst = sb + ((u32)(buf * CHBUF + kk * 136 + (m4 << 2)) << 2);
            CP_A16(dst, wTp + (size_t)(k02 + kk) * Co + c0 + (m4 << 2));
        }
    };

    u32 us[9];
    auto loadB = [&](int c) {
        const int k = (c << 6) + 2 * sk;
        const int ci = k >> 2, j2 = k & 3;
        const int kh = (1 - pa) + 2 * (j2 >> 1);
        const int dm = (kh == 0) ? 1 : ((kh == 3) ? -1 : 0);
        const size_t base = ((size_t)(b * Ci + ci) * Hp + mh + dm + 1) * Wp2 + (mw >> 1);
        const uint4* q4 = (const uint4*)(mir + base);
#pragma unroll
        for (int i = 0; i < 2; i++) {
            uint4 v = q4[i];
            us[4 * i] = v.x; us[4 * i + 1] = v.y;
            us[4 * i + 2] = v.z; us[4 * i + 3] = v.w;
        }
        us[8] = mir[base + 8];
    };

    float acc[2][8][4];
#pragma unroll
    for (int mi = 0; mi < 2; mi++)
#pragma unroll
        for (int ni = 0; ni < 8; ni++)
#pragma unroll
            for (int c = 0; c < 4; c++) acc[mi][ni][c] = 0.f;

    stageA(0, 0);
    CP_COMMIT();
    loadB(0);

    for (int c = 0; c < NC; c++) {
        {   // STS chunk c from us
            u32* dst = sm + 2 * CHBUF + (c & 1) * CHBUF + sk * 136 + sn0;
            if (pb == 0) {
#pragma unroll
                for (int q = 0; q < 8; q++) {
                    u32 a = us[q], bb = us[q + 1];
                    dst[2 * q]     = prmt(a, a, 0x1032);
                    dst[2 * q + 1] = prmt(a, bb, 0x3254);
                }
            } else {
#pragma unroll
                for (int q = 0; q < 8; q++) {
                    u32 a = us[q], bb = us[q + 1];
                    dst[2 * q]     = prmt(a, bb, 0x3254);
                    dst[2 * q + 1] = prmt(bb, bb, 0x1032);
                }
            }
        }
        if (c + 1 < NC) { stageA(c + 1, (c + 1) & 1); CP_COMMIT(); CP_WAIT1(); }
        else CP_WAIT0();
        __syncthreads();
        if (c + 1 < NC) loadB(c + 1);

        const u32* As = sm + (c & 1) * CHBUF;
        const u32* Bs = sm + 2 * CHBUF + (c & 1) * CHBUF;
#pragma unroll
        for (int s = 0; s < 4; s++) {
            const int k2b = s * 8;
            u32 a[2][4], bf[8][2];
#pragma unroll
            for (int mi = 0; mi < 2; mi++) {
                a[mi][0] = As[(k2b + tig) * 136 + m0w + mi * 16 + gid];
                a[mi][1] = As[(k2b + tig) * 136 + m0w + mi * 16 + gid + 8];
                a[mi][2] = As[(k2b + tig + 4) * 136 + m0w + mi * 16 + gid];
                a[mi][3] = As[(k2b + tig + 4) * 136 + m0w + mi * 16 + gid + 8];
            }
#pragma unroll
            for (int ni = 0; ni < 8; ni++) {
                bf[ni][0] = Bs[(k2b + tig) * 136 + n0w + ni * 8 + gid];
                bf[ni][1] = Bs[(k2b + tig + 4) * 136 + n0w + ni * 8 + gid];
            }
#pragma unroll
            for (int mi = 0; mi < 2; mi++)
#pragma unroll
                for (int ni = 0; ni < 8; ni++)
                    MMA_F16(acc[mi][ni], a[mi][0], a[mi][1], a[mi][2], a[mi][3],
                            bf[ni][0], bf[ni][1]);
        }
        __syncthreads();
    }

#pragma unroll
    for (int mi = 0; mi < 2; mi++)
#pragma unroll
        for (int h = 0; h < 2; h++) {
            const int co = c0 + m0w + mi * 16 + gid + h * 8;
            const float bv = bias[co];
#pragma unroll
            for (int ni = 0; ni < 8; ni++) {
                const int n = n0w + ni * 8 + 2 * tig;
                const int mhh = oh0 + (n >> w_shift);
                const int mww = ow0 + (n & (OWT - 1));
                float v0 = acc[mi][ni][h * 2] + bv;
                float v1 = acc[mi][ni][h * 2 + 1] + bv;
                if (relu_out) { v0 = fmaxf(v0, 0.f); v1 = fmaxf(v1, 0.f); }
                float* orow = &out[((size_t)(b * Co + co) * Ho + 2 * mhh + pa) * Wo2];
                orow[2 * mww + pb] = v0;
                orow[2 * (mww + 1) + pb] = v1;
            }
        }
}

// ===========================================================================
// HMMA 3x3 res conv (proven)
// ===========================================================================

__global__ void __launch_bounds__(256) conv3x3_tcf(
    const float* __restrict__ in, const u32* __restrict__ wT2,
    float* __restrict__ out, int Ci, int HW, int hw_shift)
{
    __shared__ u32 A_s[32][40];
    __shared__ u32 B_s[32][264];
    const int tid = threadIdx.x;
    const int lane = tid & 31, warp = tid >> 5;
    const int gid = lane >> 2, tig = lane & 3;
    const int n0w = warp * 32;
    const int p0 = blockIdx.x * 256;
    const int b = blockIdx.z;
    const int K = Ci * 9;

    const int sk = tid >> 3;
    const int sn0 = (tid & 7) << 5;
    const int ng0 = p0 + sn0;
    const int s_oh = ng0 >> hw_shift;
    const int s_ow = ng0 & (HW - 1);

    float acc[2][4][4];
#pragma unroll
    for (int mi = 0; mi < 2; mi++)
#pragma unroll
        for (int ni = 0; ni < 4; ni++)
#pragma unroll
            for (int c = 0; c < 4; c++) acc[mi][ni][c] = 0.f;

    for (int k0 = 0; k0 < K; k0 += 64) {
        const int k02 = k0 >> 1;
        for (int idx = tid; idx < 1024; idx += 256) {
            int kk = idx >> 5, m = idx & 31;
            A_s[kk][m] = wT2[(size_t)(k02 + kk) * 32 + m];
        }
        {
            const int klo = k0 + 2 * sk, khi = klo + 1;
            const int ci0 = klo / 9, t0 = klo - ci0 * 9;
            const int ci1 = khi / 9, t1 = khi - ci1 * 9;
            const int kh0 = t0 / 3, kw0 = t0 - 3 * kh0;
            const int kh1 = t1 / 3, kw1 = t1 - 3 * kh1;
            const int ih0 = s_oh - 1 + kh0, ih1 = s_oh - 1 + kh1;
            const bool ok0 = (unsigned)ih0 < (unsigned)HW;
            const bool ok1 = (unsigned)ih1 < (unsigned)HW;
            const float* r0 = in + ((size_t)(b * Ci + ci0) * HW + ih0) * HW;
            const float* r1 = in + ((size_t)(b * Ci + ci1) * HW + ih1) * HW;
            const int iwb0 = s_ow - 1 + kw0, iwb1 = s_ow - 1 + kw1;
#pragma unroll
            for (int jj = 0; jj < 32; jj++) {
                const int iw0 = iwb0 + jj, iw1 = iwb1 + jj;
                float v0 = (ok0 && (unsigned)iw0 < (unsigned)HW) ? fmaxf(r0[iw0], 0.f) : 0.f;
                float v1 = (ok1 && (unsigned)iw1 < (unsigned)HW) ? fmaxf(r1[iw1], 0.f) : 0.f;
                B_s[sk][sn0 + jj] = pack_f16x2(v0, v1);
            }
        }
        __syncthreads();
#pragma unroll
        for (int s = 0; s < 4; s++) {
            const int k2b = s * 8;
            u32 a[2][4], bf[4][2];
#pragma unroll
            for (int mi = 0; mi < 2; mi++) {
                a[mi][0] = A_s[k2b + tig][mi * 16 + gid];
                a[mi][1] = A_s[k2b + tig][mi * 16 + gid + 8];
                a[mi][2] = A_s[k2b + tig + 4][mi * 16 + gid];
                a[mi][3] = A_s[k2b + tig + 4][mi * 16 + gid + 8];
            }
#pragma unroll
            for (int ni = 0; ni < 4; ni++) {
                bf[ni][0] = B_s[k2b + tig][n0w + ni * 8 + gid];
                bf[ni][1] = B_s[k2b + tig + 4][n0w + ni * 8 + gid];
            }
#pragma unroll
            for (int mi = 0; mi < 2; mi++)
#pragma unroll
                for (int ni = 0; ni < 4; ni++)
                    MMA_F16(acc[mi][ni], a[mi][0], a[mi][1], a[mi][2], a[mi][3],
                            bf[ni][0], bf[ni][1]);
        }
        __syncthreads();
    }

#pragma unroll
    for (int mi = 0; mi < 2; mi++)
#pragma unroll
        for (int h = 0; h < 2; h++) {
            const int co = mi * 16 + gid + h * 8;
#pragma unroll
            for (int ni = 0; ni < 4; ni++) {
                const int ng = p0 + n0w + ni * 8 + 2 * tig;
                const int oh = ng >> hw_shift, ow = ng & (HW - 1);
                float2 o = {acc[mi][ni][h * 2], acc[mi][ni][h * 2 + 1]};
                *(float2*)&out[((size_t)(b * 32 + co) * HW + oh) * HW + ow] = o;
            }
        }
}

// ===========================================================================
extern "C" void kernel_launch(void* const* d_in, const int* in_sizes, int n_in,
                              void* d_out, int out_size)
{
    (void)in_sizes; (void)n_in;
    const float* x       = (const float*)d_in[0];
    const float* enc_w1  = (const float*)d_in[1];
    const float* enc_b1  = (const float*)d_in[2];
    const float* enc_w2  = (const float*)d_in[3];
    const float* enc_b2  = (const float*)d_in[4];
    const float* enc_w3  = (const float*)d_in[5];
    const float* enc_b3  = (const float*)d_in[6];
    const float* enc_rw3 = (const float*)d_in[7];
    const float* enc_rw1 = (const float*)d_in[8];
    const float* prevq_w = (const float*)d_in[9];
    const float* prevq_b = (const float*)d_in[10];
    const float* emb     = (const float*)d_in[11];
    const float* dec_w1  = (const float*)d_in[12];
    const float* dec_b1  = (const float*)d_in[13];
    const float* dec_rw3 = (const float*)d_in[14];
    const float* dec_rw1 = (const float*)d_in[15];
    const float* dec_w2  = (const float*)d_in[16];
    const float* dec_b2  = (const float*)d_in[17];
    const float* dec_w3  = (const float*)d_in[18];
    const float* dec_b3  = (const float*)d_in[19];
    float* out = (float*)d_out;

    float *b0, *b1, *b2, *b3, *ze, *zq, *loss;
    u32 *wt, *mx, *m0, *m1, *mq;
    cudaGetSymbolAddress((void**)&b0, g_b0);
    cudaGetSymbolAddress((void**)&b1, g_b1);
    cudaGetSymbolAddress((void**)&b2, g_b2);
    cudaGetSymbolAddress((void**)&b3, g_b3);
    cudaGetSymbolAddress((void**)&ze, g_ze);
    cudaGetSymbolAddress((void**)&zq, g_zq);
    cudaGetSymbolAddress((void**)&loss, g_loss);
    cudaGetSymbolAddress((void**)&wt, g_wt);
    cudaGetSymbolAddress((void**)&mx, g_mx);
    cudaGetSymbolAddress((void**)&m0, g_m0);
    cudaGetSymbolAddress((void**)&m1, g_m1);
    cudaGetSymbolAddress((void**)&mq, g_mq);

    const int DSM = 4 * CHBUF * 4;   // 69632 bytes
    cudaFuncSetAttribute(conv4s2_tcf, cudaFuncAttributeMaxDynamicSharedMemorySize, DSM);
    cudaFuncSetAttribute(tconv_tcf,   cudaFuncAttributeMaxDynamicSharedMemorySize, DSM);

    // ---- encoder ----
    cvt_mirror<<<dim3(134, 128), 256>>>(x, mx, 256, 256, 258, 132, 0, 3, 2);
    wt4s2_f16<<<16, 256>>>(enc_w1, wt, 4, 128, 3);
    conv4s2_tcf<<<dim3(1, 128, 32), 256, DSM>>>(mx, wt, enc_b1, b0, 4, 128, 258, 132, 128, 128, 7, 1);

    cvt_mirror<<<dim3(35, 4096), 256>>>(b0, m0, 128, 128, 130, 68, 0, 128, 7);
    wt4s2_f16<<<1024, 256>>>(enc_w2, wt, 128, 256, 128);
    conv4s2_tcf<<<dim3(1, 32, 64), 256, DSM>>>(m0, wt, enc_b2, b1, 128, 256, 130, 68, 64, 64, 6, 1);

    cvt_mirror<<<dim3(10, 8192), 256>>>(b1, m1, 64, 64, 66, 36, 0, 256, 8);
    wt4s2_f16<<<4096, 256>>>(enc_w3, wt, 256, 512, 256);
    conv4s2_tcf<<<dim3(1, 8, 128), 256, DSM>>>(m1, wt, enc_b3, b2, 256, 512, 66, 36, 32, 32, 5, 0);

    wt3_f16<<<288, 256>>>(enc_rw3, wt, 512);
    for (int l = 0; l < 2; l++) {
        conv3x3_tcf<<<dim3(4, 1, 32), 256>>>(b2, wt, b3, 512, 32, 5);
        conv1x1_kernel<<<dim3(16, 8, 32), 256>>>(b3, enc_rw1, nullptr, b2, 32, 512, 1024, 1, 1);
    }
    conv1x1_kernel<<<dim3(16, 1, 32), 256>>>(b2, prevq_w, prevq_b, ze, 512, 64, 1024, 1, 0);

    // ---- VQ ----
    zero_loss_kernel<<<1, 1>>>(loss);
    vq_kernel<<<128, 256>>>(ze, emb, zq, loss);
    finish_loss_kernel<<<1, 1>>>(loss, out + (out_size - 1));

    // ---- decoder ----
    cvt_mirror<<<dim3(3, 2048), 256>>>(zq, mq, 32, 32, 34, 20, 0, 64, 6);
    wtT_f16<<<512, 256>>>(dec_w1, wt, 64, 256);
    tconv_tcf<<<dim3(1, 8, 256), 256, DSM>>>(mq, wt, dec_b1, b1, 64, 256, 32, 32, 34, 20, 5, 0);

    wt3_f16<<<144, 256>>>(dec_rw3, wt, 256);
    for (int l = 0; l < 2; l++) {
        conv3x3_tcf<<<dim3(16, 1, 32), 256>>>(b1, wt, b3, 256, 64, 6);
        conv1x1_kernel<<<dim3(64, 4, 32), 256>>>(b3, dec_rw1, nullptr, b1, 32, 256, 4096, 1, 1);
    }

    cvt_mirror<<<dim3(10, 8192), 256>>>(b1, m1, 64, 64, 66, 36, 1, 256, 8);
    wtT_f16<<<1024, 256>>>(dec_w2, wt, 256, 128);
    tconv_tcf<<<dim3(1, 32, 128), 256, DSM>>>(m1, wt, dec_b2, b0, 256, 128, 64, 64, 66, 36, 6, 1);

    tconv_kernel<4, 1, 16, 16><<<dim3(8, 8, 32), 256>>>(b0, dec_w3, dec_b3, out, 128, 3, 128, 128, 0, 0);
}

// round 11
// speedup vs baseline: 4.8831x; 1.0025x over previous
#include <cuda_runtime.h>

typedef unsigned int u32;

__device__ float g_b0[32u * 128 * 128 * 128];
__device__ float g_b1[32u * 256 * 64 * 64];
__device__ float g_b2[32u * 512 * 32 * 32];
__device__ float g_b3[32u * 32 * 64 * 64];
__device__ float g_ze[32u * 64 * 32 * 32];
__device__ float g_zq[32u * 64 * 32 * 32];
__device__ float g_loss[1];
__device__ u32   g_wt[2097152];
__device__ u32   g_mx[4359168];    // enc1 mirror: 128 x 258 x 132 u32
__device__ u32   g_m0[36218880];   // enc2 mirror: 4096 x 130 x 68 u32
__device__ u32   g_m1[19464192];   // enc3/dec2 mirror: 8192 x 66 x 36 u32
__device__ u32   g_mq[1392640];    // dec1 mirror: 2048 x 34 x 20 u32

__device__ __forceinline__ u32 pack_f16x2(float lo, float hi) {
    u32 r; asm("cvt.rn.f16x2.f32 %0,%1,%2;" : "=r"(r) : "f"(hi), "f"(lo)); return r;
}
__device__ __forceinline__ u32 prmt(u32 a, u32 b, u32 s) {
    u32 r; asm("prmt.b32 %0,%1,%2,%3;" : "=r"(r) : "r"(a), "r"(b), "r"(s)); return r;
}
__device__ __forceinline__ u32 smem_u32(const void* p) {
    u32 a; asm("{ .reg .u64 t; cvta.to.shared.u64 t,%1; cvt.u32.u64 %0,t; }"
               : "=r"(a) : "l"(p));
    return a;
}

#define CP_A16(d, s) asm volatile("cp.async.ca.shared.global [%0],[%1],16;" :: "r"(d), "l"(s))
#define CP_A4(d, s)  asm volatile("cp.async.ca.shared.global [%0],[%1],4;"  :: "r"(d), "l"(s))
#define CP_COMMIT()  asm volatile("cp.async.commit_group;" ::: "memory")
#define CP_WAIT0()   asm volatile("cp.async.wait_group 0;" ::: "memory")
#define CP_WAIT1()   asm volatile("cp.async.wait_group 1;" ::: "memory")

#define MMA_F16(d, a0, a1, a2, a3, b0, b1)                                    \
    asm volatile("mma.sync.aligned.m16n8k16.row.col.f32.f16.f16.f32 "         \
                 "{%0,%1,%2,%3},{%4,%5,%6,%7},{%8,%9},{%0,%1,%2,%3};"         \
                 : "+f"(d[0]), "+f"(d[1]), "+f"(d[2]), "+f"(d[3])             \
                 : "r"(a0), "r"(a1), "r"(a2), "r"(a3), "r"(b0), "r"(b1))

// ---- mirror build: per-plane grid ------------------------------------------
__global__ void cvt_mirror(const float* __restrict__ src, u32* __restrict__ dst,
                           int Hi, int Wi, int Hp, int Wp2, int relu,
                           int scpb, int dshift)
{
    const int plane = blockIdx.y;
    const int idx = blockIdx.x * 256 + threadIdx.x;
    if (idx >= Hp * Wp2) return;
    const int ph = idx / Wp2, wp2 = idx - ph * Wp2;
    const int b = plane >> dshift;
    const int c = plane & ((1 << dshift) - 1);
    const int ih = ph - 1;
    const int iw0 = 2 * wp2 - 1, iw1 = iw0 + 1;
    float v0 = 0.f, v1 = 0.f;
    if (c < scpb && (unsigned)ih < (unsigned)Hi) {
        const float* r = src + ((size_t)(b * scpb + c) * Hi + ih) * Wi;
        if ((unsigned)iw0 < (unsigned)Wi) v0 = r[iw0];
        if ((unsigned)iw1 < (unsigned)Wi) v1 = r[iw1];
    }
    if (relu) { v0 = fmaxf(v0, 0.f); v1 = fmaxf(v1, 0.f); }
    dst[(size_t)plane * Hp * Wp2 + idx] = pack_f16x2(v0, v1);
}

// ===========================================================================
// fp32 kernels (proven)
// ===========================================================================

__global__ void __launch_bounds__(256) conv1x1_kernel(
    const float* __restrict__ in, const float* __restrict__ w,
    const float* __restrict__ bias, float* __restrict__ out,
    int Ci, int Co, int P, int relu_in, int add_res)
{
    __shared__ float w_s[16][64];
    __shared__ float x_s[16][64];
    const int tid = threadIdx.x;
    const int tx = tid & 15, ty = tid >> 4;
    const int p0 = blockIdx.x * 64, c0 = blockIdx.y * 64, b = blockIdx.z;

    float acc[4][4];
#pragma unroll
    for (int i = 0; i < 4; i++)
#pragma unroll
        for (int j = 0; j < 4; j++) acc[i][j] = 0.f;

    for (int ci0 = 0; ci0 < Ci; ci0 += 16) {
        for (int idx = tid; idx < 1024; idx += 256) {
            int p = idx & 63, ci = idx >> 6;
            float v = in[(size_t)(b * Ci + ci0 + ci) * P + p0 + p];
            x_s[ci][p] = relu_in ? fmaxf(v, 0.f) : v;
        }
        for (int idx = tid; idx < 1024; idx += 256) {
            int ci = idx & 15, co = idx >> 4;
            w_s[ci][co] = w[(size_t)(c0 + co) * Ci + ci0 + ci];
        }
        __syncthreads();
#pragma unroll
        for (int ci = 0; ci < 16; ci++) {
            const float4 wv = *(const float4*)&w_s[ci][ty << 2];
            const float4 xv = *(const float4*)&x_s[ci][tx << 2];
            const float wvv[4] = {wv.x, wv.y, wv.z, wv.w};
            const float xvv[4] = {xv.x, xv.y, xv.z, xv.w};
#pragma unroll
            for (int i = 0; i < 4; i++)
#pragma unroll
                for (int j = 0; j < 4; j++)
                    acc[i][j] = fmaf(wvv[i], xvv[j], acc[i][j]);
        }
        __syncthreads();
    }
#pragma unroll
    for (int i = 0; i < 4; i++) {
        const int co = c0 + (ty << 2) + i;
        const float bv = bias ? bias[co] : 0.f;
        const size_t base = (size_t)(b * Co + co) * P + p0 + (tx << 2);
        float4 o = {acc[i][0] + bv, acc[i][1] + bv, acc[i][2] + bv, acc[i][3] + bv};
        if (add_res) {
            float4 rr = *(const float4*)&out[base];
            o.x += rr.x; o.y += rr.y; o.z += rr.z; o.w += rr.w;
        }
        *(float4*)&out[base] = o;
    }
}

__global__ void __launch_bounds__(256) vq_kernel(
    const float* __restrict__ ze, const float* __restrict__ emb,
    float* __restrict__ zq, float* __restrict__ loss)
{
    __shared__ float e_s[128 * 64];
    __shared__ float n_s[128];
    const int tid = threadIdx.x;
    const int n = blockIdx.x * 256 + tid;
    const int b = n >> 10, hw = n & 1023;

    float xr[64];
#pragma unroll
    for (int d = 0; d < 64; d++)
        xr[d] = ze[((size_t)(b * 64 + d) << 10) + hw];

    float best = 3.4e38f;
    int bi = 0;
    for (int kb = 0; kb < 4; kb++) {
        __syncthreads();
        for (int i = tid; i < 128 * 64; i += 256) e_s[i] = emb[kb * 128 * 64 + i];
        __syncthreads();
        if (tid < 128) {
            float s = 0.f;
#pragma unroll 8
            for (int d = 0; d < 64; d++) { float v = e_s[tid * 64 + d]; s = fmaf(v, v, s); }
            n_s[tid] = s;
        }
        __syncthreads();
        for (int k = 0; k < 128; k++) {
            const float4* e4 = (const float4*)(e_s + k * 64);
            float dot = 0.f;
#pragma unroll
            for (int d4 = 0; d4 < 16; d4++) {
                float4 e = e4[d4];
                dot = fmaf(e.x, xr[d4 * 4 + 0], dot);
                dot = fmaf(e.y, xr[d4 * 4 + 1], dot);
                dot = fmaf(e.z, xr[d4 * 4 + 2], dot);
                dot = fmaf(e.w, xr[d4 * 4 + 3], dot);
            }
            float dist = n_s[k] - 2.f * dot;
            if (dist < best) { best = dist; bi = kb * 128 + k; }
        }
    }

    float ls = 0.f;
#pragma unroll
    for (int d = 0; d < 64; d++) {
        float e = emb[bi * 64 + d];
        zq[((size_t)(b * 64 + d) << 10) + hw] = e;
        float df = e - xr[d];
        ls = fmaf(df, df, ls);
    }
#pragma unroll
    for (int o = 16; o > 0; o >>= 1) ls += __shfl_down_sync(0xffffffffu, ls, o);
    if ((tid & 31) == 0) atomicAdd(loss, ls);
}

template <int CO_TILE, int CO_PT, int M_TILE, int N_TILE>
__global__ void __launch_bounds__(256) tconv_kernel(
    const float* __restrict__ in, const float* __restrict__ w,
    const float* __restrict__ bias, float* __restrict__ out,
    int Ci, int Co, int Hi, int Wi, int relu_in, int relu_out)
{
    constexpr int NSLOT = (M_TILE * N_TILE) / 4;
    constexpr int CG = CO_TILE / CO_PT;
    static_assert(NSLOT * CG == 256, "map");
    __shared__ float w_s[4][16][CO_TILE];
    __shared__ float x_s[4][M_TILE + 2][N_TILE + 2];

    const int tid = threadIdx.x;
    const int slot = tid % NSLOT, cg = tid / NSLOT;
    const int m_loc = slot / (N_TILE / 4);
    const int nb = (slot % (N_TILE / 4)) * 4;
    const int n0 = blockIdx.x * N_TILE, m0 = blockIdx.y * M_TILE;
    const int cot = (Co + CO_TILE - 1) / CO_TILE;
    const int b = blockIdx.z / cot, c0 = (blockIdx.z % cot) * CO_TILE;
    const int Ho = 2 * Hi, Wo2 = 2 * Wi;

    float acc[CO_PT][4][2][2];
#pragma unroll
    for (int i = 0; i < CO_PT; i++)
#pragma unroll
        for (int q = 0; q < 4; q++)
#pragma unroll
            for (int a = 0; a < 2; a++)
#pragma unroll
                for (int bb = 0; bb < 2; bb++) acc[i][q][a][bb] = 0.f;

    for (int ci0 = 0; ci0 < Ci; ci0 += 4) {
        for (int idx = tid; idx < 4 * (M_TILE + 2) * (N_TILE + 2); idx += 256) {
            int lc = idx % (N_TILE + 2);
            int t = idx / (N_TILE + 2);
            int lr = t % (M_TILE + 2), ci = t / (M_TILE + 2);
            int m = m0 - 1 + lr, nn = n0 - 1 + lc;
            float v = 0.f;
            if ((unsigned)m < (unsigned)Hi && (unsigned)nn < (unsigned)Wi)
                v = in[((size_t)(b * Ci + ci0 + ci) * Hi + m) * Wi + nn];
            if (relu_in) v = fmaxf(v, 0.f);
            x_s[ci][lr][lc] = v;
        }
        for (int idx = tid; idx < 4 * 16 * CO_TILE; idx += 256) {
            int t = idx & 15;
            int co = (idx >> 4) % CO_TILE;
            int ci = idx / (16 * CO_TILE);
            float v = 0.f;
            if (c0 + co < Co) v = w[((size_t)(ci0 + ci) * Co + c0 + co) * 16 + t];
            w_s[ci][t][co] = v;
        }
        __syncthreads();
#pragma unroll
        for (int ci = 0; ci < 4; ci++)
#pragma unroll
            for (int t = 0; t < 16; t++) {
                const int kh = t >> 2, kw = t & 3;
                const int a = 1 - (kh & 1);
                const int dm = (kh == 0) ? 1 : ((kh == 3) ? -1 : 0);
                const int bb = 1 - (kw & 1);
                const int dn = (kw == 0) ? 1 : ((kw == 3) ? -1 : 0);
                float wr[CO_PT];
#pragma unroll
                for (int i = 0; i < CO_PT; i++)
                    wr[i] = w_s[ci][t][cg * CO_PT + i];
                const float* xrow = &x_s[ci][m_loc + dm + 1][nb + dn + 1];
#pragma unroll
                for (int q = 0; q < 4; q++) {
                    const float xv = xrow[q];
#pragma unroll
                    for (int i = 0; i < CO_PT; i++)
                        acc[i][q][a][bb] = fmaf(wr[i], xv, acc[i][q][a][bb]);
                }
            }
        __syncthreads();
    }

    const int m = m0 + m_loc;
#pragma unroll
    for (int i = 0; i < CO_PT; i++) {
        const int co = c0 + cg * CO_PT + i;
        if (co < Co) {
            const float bv = bias[co];
#pragma unroll
            for (int q = 0; q < 4; q++) {
                const int nn = n0 + nb + q;
#pragma unroll
                for (int a = 0; a < 2; a++) {
                    float2 o = {acc[i][q][a][0] + bv, acc[i][q][a][1] + bv};
                    if (relu_out) { o.x = fmaxf(o.x, 0.f); o.y = fmaxf(o.y, 0.f); }
                    *(float2*)&out[((size_t)(b * Co + co) * Ho + 2 * m + a) * Wo2 + 2 * nn] = o;
                }
            }
        }
    }
}

__global__ void zero_loss_kernel(float* loss) { loss[0] = 0.f; }
__global__ void finish_loss_kernel(const float* __restrict__ loss, float* __restrict__ dst)
{
    dst[0] = 2.f * loss[0] / 2097152.f;
}

// ===========================================================================
// weight prepacks (fp16)
// ===========================================================================

__global__ void wt4s2_f16(const float* __restrict__ w, u32* __restrict__ wT2,
                          int Ci, int Co, int Ci_src)
{
    int idx = blockIdx.x * 256 + threadIdx.x;
    if (idx >= Ci * 8 * Co) return;
    int co = idx % Co, k2 = idx / Co;
    int k = 2 * k2, ci = k >> 4, t = k & 15;
    float v0 = 0.f, v1 = 0.f;
    if (ci < Ci_src) {
        const float* base = &w[((size_t)co * Ci_src + ci) * 16 + t];
        v0 = base[0]; v1 = base[1];
    }
    wT2[idx] = pack_f16x2(v0, v1);
}

__global__ void wtT_f16(const float* __restrict__ w, u32* __restrict__ wT2,
                        int Ci, int Co)
{
    int K2 = Ci * 2;
    int idx = blockIdx.x * 256 + threadIdx.x;
    if (idx >= 4 * K2 * Co) return;
    int co = idx % Co, rr = idx / Co;
    int p = rr / K2, k2 = rr % K2;
    int k = 2 * k2, ci = k >> 2, j = k & 3;
    int a = p >> 1, bb = p & 1;
    int kh = (1 - a) + 2 * (j >> 1);
    const float* base = &w[((size_t)ci * Co + co) * 16 + kh * 4];
    wT2[idx] = pack_f16x2(base[1 - bb], base[3 - bb]);
}

__global__ void wt3_f16(const float* __restrict__ w, u32* __restrict__ wT2, int Ci)
{
    int K = Ci * 9;
    int idx = blockIdx.x * 256 + threadIdx.x;
    if (idx >= (K / 2) * 32) return;
    int co = idx & 31, k2 = idx >> 5;
    int k0 = 2 * k2, k1 = k0 + 1;
    int ci0 = k0 / 9, t0 = k0 - ci0 * 9;
    int ci1 = k1 / 9, t1 = k1 - ci1 * 9;
    wT2[idx] = pack_f16x2(w[((size_t)co * Ci + ci0) * 9 + t0],
                          w[((size_t)co * Ci + ci1) * 9 + t1]);
}

// ===========================================================================
// HMMA conv k4 s2 p1 — 4 warps, warp tile m64 x n64, cp.async pipeline.
// dyn smem: [A0|A1|B0|B1], each 32x136 u32.
// ===========================================================================

#define CHBUF 4352

__global__ void __launch_bounds__(128, 2) conv4s2_tcf(
    const u32* __restrict__ mir, const u32* __restrict__ wT2,
    const float* __restrict__ bias, float* __restrict__ out,
    int Ci, int Co, int Hp, int Wp2, int Ho, int Wo, int w_shift, int relu)
{
    extern __shared__ u32 sm[];
    const int tid = threadIdx.x;
    const int lane = tid & 31, warp = tid >> 5;
    const int gid = lane >> 2, tig = lane & 3;
    const int m0w = (warp & 1) * 64, n0w = (warp >> 1) * 64;
    const int OWT = 1 << w_shift;
    const int ow0 = blockIdx.x * OWT, oh0 = blockIdx.y * (128 >> w_shift);
    const int cot = Co >> 7;
    const int b = blockIdx.z / cot, c0 = (blockIdx.z % cot) << 7;
    const int K = Ci << 4, NC = K >> 6;
    const int sk = tid >> 2, sn0 = (tid & 3) << 5;
    const int oh = oh0 + (sn0 >> w_shift), ow = ow0 + (sn0 & (OWT - 1));
    const u32 sb = smem_u32(sm);

    auto stage = [&](int c, int buf) {
        const int k02 = c << 5;
#pragma unroll
        for (int q = 0; q < 8; q++) {
            int idx = tid + (q << 7);
            int kk = idx >> 5, m4 = idx & 31;
            u32 dst = sb + ((u32)(buf * CHBUF + kk * 136 + (m4 << 2)) << 2);
            CP_A16(dst, wT2 + (size_t)(k02 + kk) * Co + c0 + (m4 << 2));
        }
        const int k = (c << 6) + 2 * sk;
        const int ci = k >> 4, t = k & 15, kh = t >> 2, a1 = (t & 3) >> 1;
        const u32* src = mir + ((size_t)(b * Ci + ci) * Hp + 2 * oh + kh) * Wp2 + ow + a1;
        u32 dst = sb + ((u32)(2 * CHBUF + buf * CHBUF + sk * 136 + sn0) << 2);
        if (!a1) {
#pragma unroll
            for (int j = 0; j < 8; j++) CP_A16(dst + 16 * j, src + 4 * j);
        } else {
#pragma unroll
            for (int j = 0; j < 32; j++) CP_A4(dst + 4 * j, src + j);
        }
    };

    float acc[4][8][4];
#pragma unroll
    for (int mi = 0; mi < 4; mi++)
#pragma unroll
        for (int ni = 0; ni < 8; ni++)
#pragma unroll
            for (int c = 0; c < 4; c++) acc[mi][ni][c] = 0.f;

    stage(0, 0);
    CP_COMMIT();

    for (int c = 0; c < NC; c++) {
        if (c + 1 < NC) { stage(c + 1, (c + 1) & 1); CP_COMMIT(); CP_WAIT1(); }
        else CP_WAIT0();
        __syncthreads();
        const u32* As = sm + (c & 1) * CHBUF;
        const u32* Bs = sm + 2 * CHBUF + (c & 1) * CHBUF;
#pragma unroll
        for (int s = 0; s < 4; s++) {
            const int k2b = s * 8;
            u32 a[4][4], bf[8][2];
#pragma unroll
            for (int mi = 0; mi < 4; mi++) {
                a[mi][0] = As[(k2b + tig) * 136 + m0w + mi * 16 + gid];
                a[mi][1] = As[(k2b + tig) * 136 + m0w + mi * 16 + gid + 8];
                a[mi][2] = As[(k2b + tig + 4) * 136 + m0w + mi * 16 + gid];
                a[mi][3] = As[(k2b + tig + 4) * 136 + m0w + mi * 16 + gid + 8];
            }
#pragma unroll
            for (int ni = 0; ni < 8; ni++) {
                bf[ni][0] = Bs[(k2b + tig) * 136 + n0w + ni * 8 + gid];
                bf[ni][1] = Bs[(k2b + tig + 4) * 136 + n0w + ni * 8 + gid];
            }
#pragma unroll
            for (int mi = 0; mi < 4; mi++)
#pragma unroll
                for (int ni = 0; ni < 8; ni++)
                    MMA_F16(acc[mi][ni], a[mi][0], a[mi][1], a[mi][2], a[mi][3],
                            bf[ni][0], bf[ni][1]);
        }
        __syncthreads();
    }

#pragma unroll
    for (int mi = 0; mi < 4; mi++)
#pragma unroll
        for (int h = 0; h < 2; h++) {
            const int co = c0 + m0w + mi * 16 + gid + h * 8;
            const float bv = bias[co];
#pragma unroll
            for (int ni = 0; ni < 8; ni++) {
                const int n = n0w + ni * 8 + 2 * tig;
                const int ohl = n >> w_shift, owl = n & (OWT - 1);
                float2 o = {acc[mi][ni][h * 2] + bv, acc[mi][ni][h * 2 + 1] + bv};
                if (relu) { o.x = fmaxf(o.x, 0.f); o.y = fmaxf(o.y, 0.f); }
                *(float2*)&out[((size_t)(b * Co + co) * Ho + oh0 + ohl) * Wo + ow0 + owl] = o;
            }
        }
}

// ===========================================================================
// HMMA conv-transpose per-parity — 4 warps m64 x n64, A cp.async, B prefetch.
// ===========================================================================

__global__ void __launch_bounds__(128, 2) tconv_tcf(
    const u32* __restrict__ mir, const u32* __restrict__ wT2,
    const float* __restrict__ bias, float* __restrict__ out,
    int Ci, int Co, int Hi, int Wi, int Hp, int Wp2, int w_shift, int relu_out)
{
    extern __shared__ u32 sm[];
    const int tid = threadIdx.x;
    const int lane = tid & 31, warp = tid >> 5;
    const int gid = lane >> 2, tig = lane & 3;
    const int m0w = (warp & 1) * 64, n0w = (warp >> 1) * 64;
    const int OWT = 1 << w_shift;
    const int ow0 = blockIdx.x * OWT, oh0 = blockIdx.y * (128 >> w_shift);
    const int p = blockIdx.z & 3;
    const int rest = blockIdx.z >> 2;
    const int cot = Co >> 7;
    const int b = rest / cot, c0 = (rest % cot) << 7;
    const int pa = p >> 1, pb = p & 1;
    const int K = Ci << 2, K2 = Ci << 1, NC = K >> 6;
    const int Ho = 2 * Hi, Wo2 = 2 * Wi;
    const u32* wTp = wT2 + (size_t)p * K2 * Co;
    const int sk = tid >> 2, sn0 = (tid & 3) << 5;
    const int mh = oh0 + (sn0 >> w_shift), mw = ow0 + (sn0 & (OWT - 1));
    const u32 sb = smem_u32(sm);

    auto stageA = [&](int c, int buf) {
        const int k02 = c << 5;
#pragma unroll
        for (int q = 0; q < 8; q++) {
            int idx = tid + (q << 7);
            int kk = idx >> 5, m4 = idx & 31;
            u32 dst = sb + ((u32)(buf * CHBUF + kk * 136 + (m4 << 2)) << 2);
            CP_A16(dst, wTp + (size_t)(k02 + kk) * Co + c0 + (m4 << 2));
        }
    };

    u32 us[17];
    auto loadB = [&](int c) {
        const int k = (c << 6) + 2 * sk;
        const int ci = k >> 2, j2 = k & 3;
        const int kh = (1 - pa) + 2 * (j2 >> 1);
        const int dm = (kh == 0) ? 1 : ((kh == 3) ? -1 : 0);
        const size_t base = ((size_t)(b * Ci + ci) * Hp + mh + dm + 1) * Wp2 + (mw >> 1);
        const uint4* q4 = (const uint4*)(mir + base);
#pragma unroll
        for (int i = 0; i < 4; i++) {
            uint4 v = q4[i];
            us[4 * i] = v.x; us[4 * i + 1] = v.y;
            us[4 * i + 2] = v.z; us[4 * i + 3] = v.w;
        }
        us[16] = mir[base + 16];
    };

    float acc[4][8][4];
#pragma unroll
    for (int mi = 0; mi < 4; mi++)
#pragma unroll
        for (int ni = 0; ni < 8; ni++)
#pragma unroll
            for (int c = 0; c < 4; c++) acc[mi][ni][c] = 0.f;

    stageA(0, 0);
    CP_COMMIT();
    loadB(0);

    for (int c = 0; c < NC; c++) {
        {
            u32* dst = sm + 2 * CHBUF + (c & 1) * CHBUF + sk * 136 + sn0;
            if (pb == 0) {
#pragma unroll
                for (int q = 0; q < 16; q++) {
                    u32 a = us[q], bb = us[q + 1];
                    dst[2 * q]     = prmt(a, a, 0x1032);
                    dst[2 * q + 1] = prmt(a, bb, 0x3254);
                }
            } else {
#pragma unroll
                for (int q = 0; q < 16; q++) {
                    u32 a = us[q], bb = us[q + 1];
                    dst[2 * q]     = prmt(a, bb, 0x3254);
                    dst[2 * q + 1] = prmt(bb, bb, 0x1032);
                }
            }
        }
        if (c + 1 < NC) { stageA(c + 1, (c + 1) & 1); CP_COMMIT(); CP_WAIT1(); }
        else CP_WAIT0();
        __syncthreads();
        if (c + 1 < NC) loadB(c + 1);

        const u32* As = sm + (c & 1) * CHBUF;
        const u32* Bs = sm + 2 * CHBUF + (c & 1) * CHBUF;
#pragma unroll
        for (int s = 0; s < 4; s++) {
            const int k2b = s * 8;
            u32 a[4][4], bf[8][2];
#pragma unroll
            for (int mi = 0; mi < 4; mi++) {
                a[mi][0] = As[(k2b + tig) * 136 + m0w + mi * 16 + gid];
                a[mi][1] = As[(k2b + tig) * 136 + m0w + mi * 16 + gid + 8];
                a[mi][2] = As[(k2b + tig + 4) * 136 + m0w + mi * 16 + gid];
                a[mi][3] = As[(k2b + tig + 4) * 136 + m0w + mi * 16 + gid + 8];
            }
#pragma unroll
            for (int ni = 0; ni < 8; ni++) {
                bf[ni][0] = Bs[(k2b + tig) * 136 + n0w + ni * 8 + gid];
                bf[ni][1] = Bs[(k2b + tig + 4) * 136 + n0w + ni * 8 + gid];
            }
#pragma unroll
            for (int mi = 0; mi < 4; mi++)
#pragma unroll
                for (int ni = 0; ni < 8; ni++)
                    MMA_F16(acc[mi][ni], a[mi][0], a[mi][1], a[mi][2], a[mi][3],
                            bf[ni][0], bf[ni][1]);
        }
        __syncthreads();
    }

#pragma unroll
    for (int mi = 0; mi < 4; mi++)
#pragma unroll
        for (int h = 0; h < 2; h++) {
            const int co = c0 + m0w + mi * 16 + gid + h * 8;
            const float bv = bias[co];
#pragma unroll
            for (int ni = 0; ni < 8; ni++) {
                const int n = n0w + ni * 8 + 2 * tig;
                const int mhh = oh0 + (n >> w_shift);
                const int mww = ow0 + (n & (OWT - 1));
                float v0 = acc[mi][ni][h * 2] + bv;
                float v1 = acc[mi][ni][h * 2 + 1] + bv;
                if (relu_out) { v0 = fmaxf(v0, 0.f); v1 = fmaxf(v1, 0.f); }
                float* orow = &out[((size_t)(b * Co + co) * Ho + 2 * mhh + pa) * Wo2];
                orow[2 * mww + pb] = v0;
                orow[2 * (mww + 1) + pb] = v1;
            }
        }
}

// ===========================================================================
// HMMA 3x3 res conv (proven)
// ===========================================================================

__global__ void __launch_bounds__(256) conv3x3_tcf(
    const float* __restrict__ in, const u32* __restrict__ wT2,
    float* __restrict__ out, int Ci, int HW, int hw_shift)
{
    __shared__ u32 A_s[32][40];
    __shared__ u32 B_s[32][264];
    const int tid = threadIdx.x;
    const int lane = tid & 31, warp = tid >> 5;
    const int gid = lane >> 2, tig = lane & 3;
    const int n0w = warp * 32;
    const int p0 = blockIdx.x * 256;
    const int b = blockIdx.z;
    const int K = Ci * 9;

    const int sk = tid >> 3;
    const int sn0 = (tid & 7) << 5;
    const int ng0 = p0 + sn0;
    const int s_oh = ng0 >> hw_shift;
    const int s_ow = ng0 & (HW - 1);

    float acc[2][4][4];
#pragma unroll
    for (int mi = 0; mi < 2; mi++)
#pragma unroll
        for (int ni = 0; ni < 4; ni++)
#pragma unroll
            for (int c = 0; c < 4; c++) acc[mi][ni][c] = 0.f;

    for (int k0 = 0; k0 < K; k0 += 64) {
        const int k02 = k0 >> 1;
        for (int idx = tid; idx < 1024; idx += 256) {
            int kk = idx >> 5, m = idx & 31;
            A_s[kk][m] = wT2[(size_t)(k02 + kk) * 32 + m];
        }
        {
            const int klo = k0 + 2 * sk, khi = klo + 1;
            const int ci0 = klo / 9, t0 = klo - ci0 * 9;
            const int ci1 = khi / 9, t1 = khi - ci1 * 9;
            const int kh0 = t0 / 3, kw0 = t0 - 3 * kh0;
            const int kh1 = t1 / 3, kw1 = t1 - 3 * kh1;
            const int ih0 = s_oh - 1 + kh0, ih1 = s_oh - 1 + kh1;
            const bool ok0 = (unsigned)ih0 < (unsigned)HW;
            const bool ok1 = (unsigned)ih1 < (unsigned)HW;
            const float* r0 = in + ((size_t)(b * Ci + ci0) * HW + ih0) * HW;
            const float* r1 = in + ((size_t)(b * Ci + ci1) * HW + ih1) * HW;
            const int iwb0 = s_ow - 1 + kw0, iwb1 = s_ow - 1 + kw1;
#pragma unroll
            for (int jj = 0; jj < 32; jj++) {
                const int iw0 = iwb0 + jj, iw1 = iwb1 + jj;
                float v0 = (ok0 && (unsigned)iw0 < (unsigned)HW) ? fmaxf(r0[iw0], 0.f) : 0.f;
                float v1 = (ok1 && (unsigned)iw1 < (unsigned)HW) ? fmaxf(r1[iw1], 0.f) : 0.f;
                B_s[sk][sn0 + jj] = pack_f16x2(v0, v1);
            }
        }
        __syncthreads();
#pragma unroll
        for (int s = 0; s < 4; s++) {
            const int k2b = s * 8;
            u32 a[2][4], bf[4][2];
#pragma unroll
            for (int mi = 0; mi < 2; mi++) {
                a[mi][0] = A_s[k2b + tig][mi * 16 + gid];
                a[mi][1] = A_s[k2b + tig][mi * 16 + gid + 8];
                a[mi][2] = A_s[k2b + tig + 4][mi * 16 + gid];
                a[mi][3] = A_s[k2b + tig + 4][mi * 16 + gid + 8];
            }
#pragma unroll
            for (int ni = 0; ni < 4; ni++) {
                bf[ni][0] = B_s[k2b + tig][n0w + ni * 8 + gid];
                bf[ni][1] = B_s[k2b + tig + 4][n0w + ni * 8 + gid];
            }
#pragma unroll
            for (int mi = 0; mi < 2; mi++)
#pragma unroll
                for (int ni = 0; ni < 4; ni++)
                    MMA_F16(acc[mi][ni], a[mi][0], a[mi][1], a[mi][2], a[mi][3],
                            bf[ni][0], bf[ni][1]);
        }
        __syncthreads();
    }

#pragma unroll
    for (int mi = 0; mi < 2; mi++)
#pragma unroll
        for (int h = 0; h < 2; h++) {
            const int co = mi * 16 + gid + h * 8;
#pragma unroll
            for (int ni = 0; ni < 4; ni++) {
                const int ng = p0 + n0w + ni * 8 + 2 * tig;
                const int oh = ng >> hw_shift, ow = ng & (HW - 1);
                float2 o = {acc[mi][ni][h * 2], acc[mi][ni][h * 2 + 1]};
                *(float2*)&out[((size_t)(b * 32 + co) * HW + oh) * HW + ow] = o;
            }
        }
}

// ===========================================================================
extern "C" void kernel_launch(void* const* d_in, const int* in_sizes, int n_in,
                              void* d_out, int out_size)
{
    (void)in_sizes; (void)n_in;
    const float* x       = (const float*)d_in[0];
    const float* enc_w1  = (const float*)d_in[1];
    const float* enc_b1  = (const float*)d_in[2];
    const float* enc_w2  = (const float*)d_in[3];
    const float* enc_b2  = (const float*)d_in[4];
    const float* enc_w3  = (const float*)d_in[5];
    const float* enc_b3  = (const float*)d_in[6];
    const float* enc_rw3 = (const float*)d_in[7];
    const float* enc_rw1 = (const float*)d_in[8];
    const float* prevq_w = (const float*)d_in[9];
    const float* prevq_b = (const float*)d_in[10];
    const float* emb     = (const float*)d_in[11];
    const float* dec_w1  = (const float*)d_in[12];
    const float* dec_b1  = (const float*)d_in[13];
    const float* dec_rw3 = (const float*)d_in[14];
    const float* dec_rw1 = (const float*)d_in[15];
    const float* dec_w2  = (const float*)d_in[16];
    const float* dec_b2  = (const float*)d_in[17];
    const float* dec_w3  = (const float*)d_in[18];
    const float* dec_b3  = (const float*)d_in[19];
    float* out = (float*)d_out;

    float *b0, *b1, *b2, *b3, *ze, *zq, *loss;
    u32 *wt, *mx, *m0, *m1, *mq;
    cudaGetSymbolAddress((void**)&b0, g_b0);
    cudaGetSymbolAddress((void**)&b1, g_b1);
    cudaGetSymbolAddress((void**)&b2, g_b2);
    cudaGetSymbolAddress((void**)&b3, g_b3);
    cudaGetSymbolAddress((void**)&ze, g_ze);
    cudaGetSymbolAddress((void**)&zq, g_zq);
    cudaGetSymbolAddress((void**)&loss, g_loss);
    cudaGetSymbolAddress((void**)&wt, g_wt);
    cudaGetSymbolAddress((void**)&mx, g_mx);
    cudaGetSymbolAddress((void**)&m0, g_m0);
    cudaGetSymbolAddress((void**)&m1, g_m1);
    cudaGetSymbolAddress((void**)&mq, g_mq);

    const int DSM = 4 * CHBUF * 4;   // 69632 bytes
    cudaFuncSetAttribute(conv4s2_tcf, cudaFuncAttributeMaxDynamicSharedMemorySize, DSM);
    cudaFuncSetAttribute(tconv_tcf,   cudaFuncAttributeMaxDynamicSharedMemorySize, DSM);

    // ---- encoder ----
    cvt_mirror<<<dim3(134, 128), 256>>>(x, mx, 256, 256, 258, 132, 0, 3, 2);
    wt4s2_f16<<<16, 256>>>(enc_w1, wt, 4, 128, 3);
    conv4s2_tcf<<<dim3(1, 128, 32), 128, DSM>>>(mx, wt, enc_b1, b0, 4, 128, 258, 132, 128, 128, 7, 1);

    cvt_mirror<<<dim3(35, 4096), 256>>>(b0, m0, 128, 128, 130, 68, 0, 128, 7);
    wt4s2_f16<<<1024, 256>>>(enc_w2, wt, 128, 256, 128);
    conv4s2_tcf<<<dim3(1, 32, 64), 128, DSM>>>(m0, wt, enc_b2, b1, 128, 256, 130, 68, 64, 64, 6, 1);

    cvt_mirror<<<dim3(10, 8192), 256>>>(b1, m1, 64, 64, 66, 36, 0, 256, 8);
    wt4s2_f16<<<4096, 256>>>(enc_w3, wt, 256, 512, 256);
    conv4s2_tcf<<<dim3(1, 8, 128), 128, DSM>>>(m1, wt, enc_b3, b2, 256, 512, 66, 36, 32, 32, 5, 0);

    wt3_f16<<<288, 256>>>(enc_rw3, wt, 512);
    for (int l = 0; l < 2; l++) {
        conv3x3_tcf<<<dim3(4, 1, 32), 256>>>(b2, wt, b3, 512, 32, 5);
        conv1x1_kernel<<<dim3(16, 8, 32), 256>>>(b3, enc_rw1, nullptr, b2, 32, 512, 1024, 1, 1);
    }
    conv1x1_kernel<<<dim3(16, 1, 32), 256>>>(b2, prevq_w, prevq_b, ze, 512, 64, 1024, 1, 0);

    // ---- VQ ----
    zero_loss_kernel<<<1, 1>>>(loss);
    vq_kernel<<<128, 256>>>(ze, emb, zq, loss);
    finish_loss_kernel<<<1, 1>>>(loss, out + (out_size - 1));

    // ---- decoder ----
    cvt_mirror<<<dim3(3, 2048), 256>>>(zq, mq, 32, 32, 34, 20, 0, 64, 6);
    wtT_f16<<<512, 256>>>(dec_w1, wt, 64, 256);
    tconv_tcf<<<dim3(1, 8, 256), 128, DSM>>>(mq, wt, dec_b1, b1, 64, 256, 32, 32, 34, 20, 5, 0);

    wt3_f16<<<144, 256>>>(dec_rw3, wt, 256);
    for (int l = 0; l < 2; l++) {
        conv3x3_tcf<<<dim3(16, 1, 32), 256>>>(b1, wt, b3, 256, 64, 6);
        conv1x1_kernel<<<dim3(64, 4, 32), 256>>>(b3, dec_rw1, nullptr, b1, 32, 256, 4096, 1, 1);
    }

    cvt_mirror<<<dim3(10, 8192), 256>>>(b1, m1, 64, 64, 66, 36, 1, 256, 8);
    wtT_f16<<<1024, 256>>>(dec_w2, wt, 256, 128);
    tconv_tcf<<<dim3(1, 32, 128), 128, DSM>>>(m1, wt, dec_b2, b0, 256, 128, 64, 64, 66, 36, 6, 1);

    tconv_kernel<4, 1, 16, 16><<<dim3(8, 8, 32), 256>>>(b0, dec_w3, dec_b3, out, 128, 3, 128, 128, 0, 0);
}

// round 12
// speedup vs baseline: 5.8109x; 1.1900x over previous
#include <cuda_runtime.h>

typedef unsigned int u32;

__device__ float g_b0[32u * 128 * 128 * 128];
__device__ float g_b1[32u * 256 * 64 * 64];
__device__ float g_b2[32u * 512 * 32 * 32];
__device__ float g_b3[32u * 32 * 64 * 64];
__device__ float g_ze[32u * 64 * 32 * 32];
__device__ float g_zq[32u * 64 * 32 * 32];
__device__ float g_loss[1];
__device__ u32   g_wt[2097152];
__device__ u32   g_mx[4359168];    // enc1 mirror: 128 x 258 x 132 u32
__device__ u32   g_m0[36218880];   // enc2 mirror / enc-res mirror
__device__ u32   g_m1[19464192];   // enc3+dec2 mirror / dec-res mirror
__device__ u32   g_mq[1392640];    // dec1 mirror: 2048 x 34 x 20 u32

__device__ __forceinline__ u32 pack_f16x2(float lo, float hi) {
    u32 r; asm("cvt.rn.f16x2.f32 %0,%1,%2;" : "=r"(r) : "f"(hi), "f"(lo)); return r;
}
__device__ __forceinline__ u32 prmt(u32 a, u32 b, u32 s) {
    u32 r; asm("prmt.b32 %0,%1,%2,%3;" : "=r"(r) : "r"(a), "r"(b), "r"(s)); return r;
}
__device__ __forceinline__ u32 smem_u32(const void* p) {
    u32 a; asm("{ .reg .u64 t; cvta.to.shared.u64 t,%1; cvt.u32.u64 %0,t; }"
               : "=r"(a) : "l"(p));
    return a;
}

#define CP_A16(d, s) asm volatile("cp.async.ca.shared.global [%0],[%1],16;" :: "r"(d), "l"(s))
#define CP_A4(d, s)  asm volatile("cp.async.ca.shared.global [%0],[%1],4;"  :: "r"(d), "l"(s))
#define CP_COMMIT()  asm volatile("cp.async.commit_group;" ::: "memory")
#define CP_WAIT0()   asm volatile("cp.async.wait_group 0;" ::: "memory")
#define CP_WAIT1()   asm volatile("cp.async.wait_group 1;" ::: "memory")

#define MMA_F16(d, a0, a1, a2, a3, b0, b1)                                    \
    asm volatile("mma.sync.aligned.m16n8k16.row.col.f32.f16.f16.f32 "         \
                 "{%0,%1,%2,%3},{%4,%5,%6,%7},{%8,%9},{%0,%1,%2,%3};"         \
                 : "+f"(d[0]), "+f"(d[1]), "+f"(d[2]), "+f"(d[3])             \
                 : "r"(a0), "r"(a1), "r"(a2), "r"(a3), "r"(b0), "r"(b1))

// ---- mirror build: per-plane grid ------------------------------------------
__global__ void cvt_mirror(const float* __restrict__ src, u32* __restrict__ dst,
                           int Hi, int Wi, int Hp, int Wp2, int relu,
                           int scpb, int dshift)
{
    const int plane = blockIdx.y;
    const int idx = blockIdx.x * 256 + threadIdx.x;
    if (idx >= Hp * Wp2) return;
    const int ph = idx / Wp2, wp2 = idx - ph * Wp2;
    const int b = plane >> dshift;
    const int c = plane & ((1 << dshift) - 1);
    const int ih = ph - 1;
    const int iw0 = 2 * wp2 - 1, iw1 = iw0 + 1;
    float v0 = 0.f, v1 = 0.f;
    if (c < scpb && (unsigned)ih < (unsigned)Hi) {
        const float* r = src + ((size_t)(b * scpb + c) * Hi + ih) * Wi;
        if ((unsigned)iw0 < (unsigned)Wi) v0 = r[iw0];
        if ((unsigned)iw1 < (unsigned)Wi) v1 = r[iw1];
    }
    if (relu) { v0 = fmaxf(v0, 0.f); v1 = fmaxf(v1, 0.f); }
    dst[(size_t)plane * Hp * Wp2 + idx] = pack_f16x2(v0, v1);
}

// ===========================================================================
// fp32 kernels (proven)
// ===========================================================================

__global__ void __launch_bounds__(256) conv1x1_kernel(
    const float* __restrict__ in, const float* __restrict__ w,
    const float* __restrict__ bias, float* __restrict__ out,
    int Ci, int Co, int P, int relu_in, int add_res)
{
    __shared__ float w_s[16][64];
    __shared__ float x_s[16][64];
    const int tid = threadIdx.x;
    const int tx = tid & 15, ty = tid >> 4;
    const int p0 = blockIdx.x * 64, c0 = blockIdx.y * 64, b = blockIdx.z;

    float acc[4][4];
#pragma unroll
    for (int i = 0; i < 4; i++)
#pragma unroll
        for (int j = 0; j < 4; j++) acc[i][j] = 0.f;

    for (int ci0 = 0; ci0 < Ci; ci0 += 16) {
        for (int idx = tid; idx < 1024; idx += 256) {
            int p = idx & 63, ci = idx >> 6;
            float v = in[(size_t)(b * Ci + ci0 + ci) * P + p0 + p];
            x_s[ci][p] = relu_in ? fmaxf(v, 0.f) : v;
        }
        for (int idx = tid; idx < 1024; idx += 256) {
            int ci = idx & 15, co = idx >> 4;
            w_s[ci][co] = w[(size_t)(c0 + co) * Ci + ci0 + ci];
        }
        __syncthreads();
#pragma unroll
        for (int ci = 0; ci < 16; ci++) {
            const float4 wv = *(const float4*)&w_s[ci][ty << 2];
            const float4 xv = *(const float4*)&x_s[ci][tx << 2];
            const float wvv[4] = {wv.x, wv.y, wv.z, wv.w};
            const float xvv[4] = {xv.x, xv.y, xv.z, xv.w};
#pragma unroll
            for (int i = 0; i < 4; i++)
#pragma unroll
                for (int j = 0; j < 4; j++)
                    acc[i][j] = fmaf(wvv[i], xvv[j], acc[i][j]);
        }
        __syncthreads();
    }
#pragma unroll
    for (int i = 0; i < 4; i++) {
        const int co = c0 + (ty << 2) + i;
        const float bv = bias ? bias[co] : 0.f;
        const size_t base = (size_t)(b * Co + co) * P + p0 + (tx << 2);
        float4 o = {acc[i][0] + bv, acc[i][1] + bv, acc[i][2] + bv, acc[i][3] + bv};
        if (add_res) {
            float4 rr = *(const float4*)&out[base];
            o.x += rr.x; o.y += rr.y; o.z += rr.z; o.w += rr.w;
        }
        *(float4*)&out[base] = o;
    }
}

__global__ void __launch_bounds__(256) vq_kernel(
    const float* __restrict__ ze, const float* __restrict__ emb,
    float* __restrict__ zq, float* __restrict__ loss)
{
    __shared__ float e_s[128 * 64];
    __shared__ float n_s[128];
    const int tid = threadIdx.x;
    const int n = blockIdx.x * 256 + tid;
    const int b = n >> 10, hw = n & 1023;

    float xr[64];
#pragma unroll
    for (int d = 0; d < 64; d++)
        xr[d] = ze[((size_t)(b * 64 + d) << 10) + hw];

    float best = 3.4e38f;
    int bi = 0;
    for (int kb = 0; kb < 4; kb++) {
        __syncthreads();
        for (int i = tid; i < 128 * 64; i += 256) e_s[i] = emb[kb * 128 * 64 + i];
        __syncthreads();
        if (tid < 128) {
            float s = 0.f;
#pragma unroll 8
            for (int d = 0; d < 64; d++) { float v = e_s[tid * 64 + d]; s = fmaf(v, v, s); }
            n_s[tid] = s;
        }
        __syncthreads();
        for (int k = 0; k < 128; k++) {
            const float4* e4 = (const float4*)(e_s + k * 64);
            float dot = 0.f;
#pragma unroll
            for (int d4 = 0; d4 < 16; d4++) {
                float4 e = e4[d4];
                dot = fmaf(e.x, xr[d4 * 4 + 0], dot);
                dot = fmaf(e.y, xr[d4 * 4 + 1], dot);
                dot = fmaf(e.z, xr[d4 * 4 + 2], dot);
                dot = fmaf(e.w, xr[d4 * 4 + 3], dot);
            }
            float dist = n_s[k] - 2.f * dot;
            if (dist < best) { best = dist; bi = kb * 128 + k; }
        }
    }

    float ls = 0.f;
#pragma unroll
    for (int d = 0; d < 64; d++) {
        float e = emb[bi * 64 + d];
        zq[((size_t)(b * 64 + d) << 10) + hw] = e;
        float df = e - xr[d];
        ls = fmaf(df, df, ls);
    }
#pragma unroll
    for (int o = 16; o > 0; o >>= 1) ls += __shfl_down_sync(0xffffffffu, ls, o);
    if ((tid & 31) == 0) atomicAdd(loss, ls);
}

template <int CO_TILE, int CO_PT, int M_TILE, int N_TILE>
__global__ void __launch_bounds__(256) tconv_kernel(
    const float* __restrict__ in, const float* __restrict__ w,
    const float* __restrict__ bias, float* __restrict__ out,
    int Ci, int Co, int Hi, int Wi, int relu_in, int relu_out)
{
    constexpr int NSLOT = (M_TILE * N_TILE) / 4;
    constexpr int CG = CO_TILE / CO_PT;
    static_assert(NSLOT * CG == 256, "map");
    __shared__ float w_s[4][16][CO_TILE];
    __shared__ float x_s[4][M_TILE + 2][N_TILE + 2];

    const int tid = threadIdx.x;
    const int slot = tid % NSLOT, cg = tid / NSLOT;
    const int m_loc = slot / (N_TILE / 4);
    const int nb = (slot % (N_TILE / 4)) * 4;
    const int n0 = blockIdx.x * N_TILE, m0 = blockIdx.y * M_TILE;
    const int cot = (Co + CO_TILE - 1) / CO_TILE;
    const int b = blockIdx.z / cot, c0 = (blockIdx.z % cot) * CO_TILE;
    const int Ho = 2 * Hi, Wo2 = 2 * Wi;

    float acc[CO_PT][4][2][2];
#pragma unroll
    for (int i = 0; i < CO_PT; i++)
#pragma unroll
        for (int q = 0; q < 4; q++)
#pragma unroll
            for (int a = 0; a < 2; a++)
#pragma unroll
                for (int bb = 0; bb < 2; bb++) acc[i][q][a][bb] = 0.f;

    for (int ci0 = 0; ci0 < Ci; ci0 += 4) {
        for (int idx = tid; idx < 4 * (M_TILE + 2) * (N_TILE + 2); idx += 256) {
            int lc = idx % (N_TILE + 2);
            int t = idx / (N_TILE + 2);
            int lr = t % (M_TILE + 2), ci = t / (M_TILE + 2);
            int m = m0 - 1 + lr, nn = n0 - 1 + lc;
            float v = 0.f;
            if ((unsigned)m < (unsigned)Hi && (unsigned)nn < (unsigned)Wi)
                v = in[((size_t)(b * Ci + ci0 + ci) * Hi + m) * Wi + nn];
            if (relu_in) v = fmaxf(v, 0.f);
            x_s[ci][lr][lc] = v;
        }
        for (int idx = tid; idx < 4 * 16 * CO_TILE; idx += 256) {
            int t = idx & 15;
            int co = (idx >> 4) % CO_TILE;
            int ci = idx / (16 * CO_TILE);
            float v = 0.f;
            if (c0 + co < Co) v = w[((size_t)(ci0 + ci) * Co + c0 + co) * 16 + t];
            w_s[ci][t][co] = v;
        }
        __syncthreads();
#pragma unroll
        for (int ci = 0; ci < 4; ci++)
#pragma unroll
            for (int t = 0; t < 16; t++) {
                const int kh = t >> 2, kw = t & 3;
                const int a = 1 - (kh & 1);
                const int dm = (kh == 0) ? 1 : ((kh == 3) ? -1 : 0);
                const int bb = 1 - (kw & 1);
                const int dn = (kw == 0) ? 1 : ((kw == 3) ? -1 : 0);
                float wr[CO_PT];
#pragma unroll
                for (int i = 0; i < CO_PT; i++)
                    wr[i] = w_s[ci][t][cg * CO_PT + i];
                const float* xrow = &x_s[ci][m_loc + dm + 1][nb + dn + 1];
#pragma unroll
                for (int q = 0; q < 4; q++) {
                    const float xv = xrow[q];
#pragma unroll
                    for (int i = 0; i < CO_PT; i++)
                        acc[i][q][a][bb] = fmaf(wr[i], xv, acc[i][q][a][bb]);
                }
            }
        __syncthreads();
    }

    const int m = m0 + m_loc;
#pragma unroll
    for (int i = 0; i < CO_PT; i++) {
        const int co = c0 + cg * CO_PT + i;
        if (co < Co) {
            const float bv = bias[co];
#pragma unroll
            for (int q = 0; q < 4; q++) {
                const int nn = n0 + nb + q;
#pragma unroll
                for (int a = 0; a < 2; a++) {
                    float2 o = {acc[i][q][a][0] + bv, acc[i][q][a][1] + bv};
                    if (relu_out) { o.x = fmaxf(o.x, 0.f); o.y = fmaxf(o.y, 0.f); }
                    *(float2*)&out[((size_t)(b * Co + co) * Ho + 2 * m + a) * Wo2 + 2 * nn] = o;
                }
            }
        }
    }
}

__global__ void zero_loss_kernel(float* loss) { loss[0] = 0.f; }
__global__ void finish_loss_kernel(const float* __restrict__ loss, float* __restrict__ dst)
{
    dst[0] = 2.f * loss[0] / 2097152.f;
}

// ===========================================================================
// weight prepacks (fp16)
// ===========================================================================

__global__ void wt4s2_f16(const float* __restrict__ w, u32* __restrict__ wT2,
                          int Ci, int Co, int Ci_src)
{
    int idx = blockIdx.x * 256 + threadIdx.x;
    if (idx >= Ci * 8 * Co) return;
    int co = idx % Co, k2 = idx / Co;
    int k = 2 * k2, ci = k >> 4, t = k & 15;
    float v0 = 0.f, v1 = 0.f;
    if (ci < Ci_src) {
        const float* base = &w[((size_t)co * Ci_src + ci) * 16 + t];
        v0 = base[0]; v1 = base[1];
    }
    wT2[idx] = pack_f16x2(v0, v1);
}

__global__ void wtT_f16(const float* __restrict__ w, u32* __restrict__ wT2,
                        int Ci, int Co)
{
    int K2 = Ci * 2;
    int idx = blockIdx.x * 256 + threadIdx.x;
    if (idx >= 4 * K2 * Co) return;
    int co = idx % Co, rr = idx / Co;
    int p = rr / K2, k2 = rr % K2;
    int k = 2 * k2, ci = k >> 2, j = k & 3;
    int a = p >> 1, bb = p & 1;
    int kh = (1 - a) + 2 * (j >> 1);
    const float* base = &w[((size_t)ci * Co + co) * 16 + kh * 4];
    wT2[idx] = pack_f16x2(base[1 - bb], base[3 - bb]);
}

__global__ void wt3_f16(const float* __restrict__ w, u32* __restrict__ wT2, int Ci)
{
    int K = Ci * 9;
    int idx = blockIdx.x * 256 + threadIdx.x;
    if (idx >= (K / 2) * 32) return;
    int co = idx & 31, k2 = idx >> 5;
    int k0 = 2 * k2, k1 = k0 + 1;
    int ci0 = k0 / 9, t0 = k0 - ci0 * 9;
    int ci1 = k1 / 9, t1 = k1 - ci1 * 9;
    wT2[idx] = pack_f16x2(w[((size_t)co * Ci + ci0) * 9 + t0],
                          w[((size_t)co * Ci + ci1) * 9 + t1]);
}

// ===========================================================================
// HMMA conv k4 s2 p1 — 4 warps m64 x n64, cp.async pipeline. (round-11)
// ===========================================================================

#define CHBUF 4352

__global__ void __launch_bounds__(128, 2) conv4s2_tcf(
    const u32* __restrict__ mir, const u32* __restrict__ wT2,
    const float* __restrict__ bias, float* __restrict__ out,
    int Ci, int Co, int Hp, int Wp2, int Ho, int Wo, int w_shift, int relu)
{
    extern __shared__ u32 sm[];
    const int tid = threadIdx.x;
    const int lane = tid & 31, warp = tid >> 5;
    const int gid = lane >> 2, tig = lane & 3;
    const int m0w = (warp & 1) * 64, n0w = (warp >> 1) * 64;
    const int OWT = 1 << w_shift;
    const int ow0 = blockIdx.x * OWT, oh0 = blockIdx.y * (128 >> w_shift);
    const int cot = Co >> 7;
    const int b = blockIdx.z / cot, c0 = (blockIdx.z % cot) << 7;
    const int K = Ci << 4, NC = K >> 6;
    const int sk = tid >> 2, sn0 = (tid & 3) << 5;
    const int oh = oh0 + (sn0 >> w_shift), ow = ow0 + (sn0 & (OWT - 1));
    const u32 sb = smem_u32(sm);

    auto stage = [&](int c, int buf) {
        const int k02 = c << 5;
#pragma unroll
        for (int q = 0; q < 8; q++) {
            int idx = tid + (q << 7);
            int kk = idx >> 5, m4 = idx & 31;
            u32 dst = sb + ((u32)(buf * CHBUF + kk * 136 + (m4 << 2)) << 2);
            CP_A16(dst, wT2 + (size_t)(k02 + kk) * Co + c0 + (m4 << 2));
        }
        const int k = (c << 6) + 2 * sk;
        const int ci = k >> 4, t = k & 15, kh = t >> 2, a1 = (t & 3) >> 1;
        const u32* src = mir + ((size_t)(b * Ci + ci) * Hp + 2 * oh + kh) * Wp2 + ow + a1;
        u32 dst = sb + ((u32)(2 * CHBUF + buf * CHBUF + sk * 136 + sn0) << 2);
        if (!a1) {
#pragma unroll
            for (int j = 0; j < 8; j++) CP_A16(dst + 16 * j, src + 4 * j);
        } else {
#pragma unroll
            for (int j = 0; j < 32; j++) CP_A4(dst + 4 * j, src + j);
        }
    };

    float acc[4][8][4];
#pragma unroll
    for (int mi = 0; mi < 4; mi++)
#pragma unroll
        for (int ni = 0; ni < 8; ni++)
#pragma unroll
            for (int c = 0; c < 4; c++) acc[mi][ni][c] = 0.f;

    stage(0, 0);
    CP_COMMIT();

    for (int c = 0; c < NC; c++) {
        if (c + 1 < NC) { stage(c + 1, (c + 1) & 1); CP_COMMIT(); CP_WAIT1(); }
        else CP_WAIT0();
        __syncthreads();
        const u32* As = sm + (c & 1) * CHBUF;
        const u32* Bs = sm + 2 * CHBUF + (c & 1) * CHBUF;
#pragma unroll
        for (int s = 0; s < 4; s++) {
            const int k2b = s * 8;
            u32 a[4][4], bf[8][2];
#pragma unroll
            for (int mi = 0; mi < 4; mi++) {
                a[mi][0] = As[(k2b + tig) * 136 + m0w + mi * 16 + gid];
                a[mi][1] = As[(k2b + tig) * 136 + m0w + mi * 16 + gid + 8];
                a[mi][2] = As[(k2b + tig + 4) * 136 + m0w + mi * 16 + gid];
                a[mi][3] = As[(k2b + tig + 4) * 136 + m0w + mi * 16 + gid + 8];
            }
#pragma unroll
            for (int ni = 0; ni < 8; ni++) {
                bf[ni][0] = Bs[(k2b + tig) * 136 + n0w + ni * 8 + gid];
                bf[ni][1] = Bs[(k2b + tig + 4) * 136 + n0w + ni * 8 + gid];
            }
#pragma unroll
            for (int mi = 0; mi < 4; mi++)
#pragma unroll
                for (int ni = 0; ni < 8; ni++)
                    MMA_F16(acc[mi][ni], a[mi][0], a[mi][1], a[mi][2], a[mi][3],
                            bf[ni][0], bf[ni][1]);
        }
        __syncthreads();
    }

#pragma unroll
    for (int mi = 0; mi < 4; mi++)
#pragma unroll
        for (int h = 0; h < 2; h++) {
            const int co = c0 + m0w + mi * 16 + gid + h * 8;
            const float bv = bias[co];
#pragma unroll
            for (int ni = 0; ni < 8; ni++) {
                const int n = n0w + ni * 8 + 2 * tig;
                const int ohl = n >> w_shift, owl = n & (OWT - 1);
                float2 o = {acc[mi][ni][h * 2] + bv, acc[mi][ni][h * 2 + 1] + bv};
                if (relu) { o.x = fmaxf(o.x, 0.f); o.y = fmaxf(o.y, 0.f); }
                *(float2*)&out[((size_t)(b * Co + co) * Ho + oh0 + ohl) * Wo + ow0 + owl] = o;
            }
        }
}

// ===========================================================================
// HMMA conv-transpose per-parity — 4 warps m64 x n64. (round-11)
// ===========================================================================

__global__ void __launch_bounds__(128, 2) tconv_tcf(
    const u32* __restrict__ mir, const u32* __restrict__ wT2,
    const float* __restrict__ bias, float* __restrict__ out,
    int Ci, int Co, int Hi, int Wi, int Hp, int Wp2, int w_shift, int relu_out)
{
    extern __shared__ u32 sm[];
    const int tid = threadIdx.x;
    const int lane = tid & 31, warp = tid >> 5;
    const int gid = lane >> 2, tig = lane & 3;
    const int m0w = (warp & 1) * 64, n0w = (warp >> 1) * 64;
    const int OWT = 1 << w_shift;
    const int ow0 = blockIdx.x * OWT, oh0 = blockIdx.y * (128 >> w_shift);
    const int p = blockIdx.z & 3;
    const int rest = blockIdx.z >> 2;
    const int cot = Co >> 7;
    const int b = rest / cot, c0 = (rest % cot) << 7;
    const int pa = p >> 1, pb = p & 1;
    const int K = Ci << 2, K2 = Ci << 1, NC = K >> 6;
    const int Ho = 2 * Hi, Wo2 = 2 * Wi;
    const u32* wTp = wT2 + (size_t)p * K2 * Co;
    const int sk = tid >> 2, sn0 = (tid & 3) << 5;
    const int mh = oh0 + (sn0 >> w_shift), mw = ow0 + (sn0 & (OWT - 1));
    const u32 sb = smem_u32(sm);

    auto stageA = [&](int c, int buf) {
        const int k02 = c << 5;
#pragma unroll
        for (int q = 0; q < 8; q++) {
            int idx = tid + (q << 7);
            int kk = idx >> 5, m4 = idx & 31;
            u32 dst = sb + ((u32)(buf * CHBUF + kk * 136 + (m4 << 2)) << 2);
            CP_A16(dst, wTp + (size_t)(k02 + kk) * Co + c0 + (m4 << 2));
        }
    };

    u32 us[17];
    auto loadB = [&](int c) {
        const int k = (c << 6) + 2 * sk;
        const int ci = k >> 2, j2 = k & 3;
        const int kh = (1 - pa) + 2 * (j2 >> 1);
        const int dm = (kh == 0) ? 1 : ((kh == 3) ? -1 : 0);
        const size_t base = ((size_t)(b * Ci + ci) * Hp + mh + dm + 1) * Wp2 + (mw >> 1);
        const uint4* q4 = (const uint4*)(mir + base);
#pragma unroll
        for (int i = 0; i < 4; i++) {
            uint4 v = q4[i];
            us[4 * i] = v.x; us[4 * i + 1] = v.y;
            us[4 * i + 2] = v.z; us[4 * i + 3] = v.w;
        }
        us[16] = mir[base + 16];
    };

    float acc[4][8][4];
#pragma unroll
    for (int mi = 0; mi < 4; mi++)
#pragma unroll
        for (int ni = 0; ni < 8; ni++)
#pragma unroll
            for (int c = 0; c < 4; c++) acc[mi][ni][c] = 0.f;

    stageA(0, 0);
    CP_COMMIT();
    loadB(0);

    for (int c = 0; c < NC; c++) {
        {
            u32* dst = sm + 2 * CHBUF + (c & 1) * CHBUF + sk * 136 + sn0;
            if (pb == 0) {
#pragma unroll
                for (int q = 0; q < 16; q++) {
                    u32 a = us[q], bb = us[q + 1];
                    dst[2 * q]     = prmt(a, a, 0x1032);
                    dst[2 * q + 1] = prmt(a, bb, 0x3254);
                }
            } else {
#pragma unroll
                for (int q = 0; q < 16; q++) {
                    u32 a = us[q], bb = us[q + 1];
                    dst[2 * q]     = prmt(a, bb, 0x3254);
                    dst[2 * q + 1] = prmt(bb, bb, 0x1032);
                }
            }
        }
        if (c + 1 < NC) { stageA(c + 1, (c + 1) & 1); CP_COMMIT(); CP_WAIT1(); }
        else CP_WAIT0();
        __syncthreads();
        if (c + 1 < NC) loadB(c + 1);

        const u32* As = sm + (c & 1) * CHBUF;
        const u32* Bs = sm + 2 * CHBUF + (c & 1) * CHBUF;
#pragma unroll
        for (int s = 0; s < 4; s++) {
            const int k2b = s * 8;
            u32 a[4][4], bf[8][2];
#pragma unroll
            for (int mi = 0; mi < 4; mi++) {
                a[mi][0] = As[(k2b + tig) * 136 + m0w + mi * 16 + gid];
                a[mi][1] = As[(k2b + tig) * 136 + m0w + mi * 16 + gid + 8];
                a[mi][2] = As[(k2b + tig + 4) * 136 + m0w + mi * 16 + gid];
                a[mi][3] = As[(k2b + tig + 4) * 136 + m0w + mi * 16 + gid + 8];
            }
#pragma unroll
            for (int ni = 0; ni < 8; ni++) {
                bf[ni][0] = Bs[(k2b + tig) * 136 + n0w + ni * 8 + gid];
                bf[ni][1] = Bs[(k2b + tig + 4) * 136 + n0w + ni * 8 + gid];
            }
#pragma unroll
            for (int mi = 0; mi < 4; mi++)
#pragma unroll
                for (int ni = 0; ni < 8; ni++)
                    MMA_F16(acc[mi][ni], a[mi][0], a[mi][1], a[mi][2], a[mi][3],
                            bf[ni][0], bf[ni][1]);
        }
        __syncthreads();
    }

#pragma unroll
    for (int mi = 0; mi < 4; mi++)
#pragma unroll
        for (int h = 0; h < 2; h++) {
            const int co = c0 + m0w + mi * 16 + gid + h * 8;
            const float bv = bias[co];
#pragma unroll
            for (int ni = 0; ni < 8; ni++) {
                const int n = n0w + ni * 8 + 2 * tig;
                const int mhh = oh0 + (n >> w_shift);
                const int mww = ow0 + (n & (OWT - 1));
                float v0 = acc[mi][ni][h * 2] + bv;
                float v1 = acc[mi][ni][h * 2 + 1] + bv;
                if (relu_out) { v0 = fmaxf(v0, 0.f); v1 = fmaxf(v1, 0.f); }
                float* orow = &out[((size_t)(b * Co + co) * Ho + 2 * mhh + pa) * Wo2];
                orow[2 * mww + pb] = v0;
                orow[2 * (mww + 1) + pb] = v1;
            }
        }
}

// ===========================================================================
// HMMA 3x3 res conv — MIRROR-staged (new this round)
// ===========================================================================

template <int O>
__device__ __forceinline__ void canon16(u32* w, const u32 (&us)[20], int p) {
    if (p) {
#pragma unroll
        for (int i = 0; i < 16; i++) w[i] = prmt(us[O + i], us[O + i + 1], 0x5432);
    } else {
#pragma unroll
        for (int i = 0; i < 16; i++) w[i] = us[O + i];
    }
}
__device__ __forceinline__ void canon(u32* w, const u32 (&us)[20], int o, int p) {
    switch (o) {
    case 0:  canon16<0>(w, us, p); break;
    case 1:  canon16<1>(w, us, p); break;
    case 2:  canon16<2>(w, us, p); break;
    default: canon16<3>(w, us, p); break;
    }
}

__global__ void __launch_bounds__(256, 2) conv3x3_tcf(
    const u32* __restrict__ mir, const u32* __restrict__ wT2,
    float* __restrict__ out, int Ci, int HW, int hw_shift, int Hp, int Wp2)
{
    __shared__ u32 A_s[32][40];
    __shared__ u32 B_s[32][264];
    const int tid = threadIdx.x;
    const int lane = tid & 31, warp = tid >> 5;
    const int gid = lane >> 2, tig = lane & 3;
    const int n0w = warp * 32;
    const int p0 = blockIdx.x * 256;
    const int b = blockIdx.z;
    const int K = Ci * 9;

    const int sk = tid >> 3;
    const int sn0 = (tid & 7) << 5;
    const int ng0 = p0 + sn0;
    const int s_oh = ng0 >> hw_shift;
    const int s_ow = ng0 & (HW - 1);

    float acc[2][4][4];
#pragma unroll
    for (int mi = 0; mi < 2; mi++)
#pragma unroll
        for (int ni = 0; ni < 4; ni++)
#pragma unroll
            for (int c = 0; c < 4; c++) acc[mi][ni][c] = 0.f;

    for (int k0 = 0; k0 < K; k0 += 64) {
        const int k02 = k0 >> 1;
        for (int idx = tid; idx < 1024; idx += 256) {
            int kk = idx >> 5, m = idx & 31;
            A_s[kk][m] = wT2[(size_t)(k02 + kk) * 32 + m];
        }
        {
            const int klo = k0 + 2 * sk, khi = klo + 1;
            const int ci0 = klo / 9, t0 = klo - ci0 * 9;
            const int ci1 = khi / 9, t1 = khi - ci1 * 9;
            const int kh0 = t0 / 3, kw0 = t0 - 3 * kh0;
            const int kh1 = t1 / 3, kw1 = t1 - 3 * kh1;
            const u32* r0 = mir + ((size_t)(b * Ci + ci0) * Hp + s_oh + kh0) * Wp2;
            const u32* r1 = mir + ((size_t)(b * Ci + ci1) * Hp + s_oh + kh1) * Wp2;
            const int h0 = s_ow + kw0, h1 = s_ow + kw1;
            const int b0i = h0 >> 1, b1i = h1 >> 1;
            const int al0 = b0i & ~3, al1 = b1i & ~3;
            u32 us0[20], us1[20], w0[16], w1[16];
            {
                const uint4* q4 = (const uint4*)(r0 + al0);
#pragma unroll
                for (int i = 0; i < 5; i++) {
                    uint4 v = q4[i];
                    us0[4 * i] = v.x; us0[4 * i + 1] = v.y;
                    us0[4 * i + 2] = v.z; us0[4 * i + 3] = v.w;
                }
            }
            canon(w0, us0, b0i - al0, h0 & 1);
            {
                const uint4* q4 = (const uint4*)(r1 + al1);
#pragma unroll
                for (int i = 0; i < 5; i++) {
                    uint4 v = q4[i];
                    us1[4 * i] = v.x; us1[4 * i + 1] = v.y;
                    us1[4 * i + 2] = v.z; us1[4 * i + 3] = v.w;
                }
            }
            canon(w1, us1, b1i - al1, h1 & 1);
            u32* dst = &B_s[sk][sn0];
#pragma unroll
            for (int t = 0; t < 8; t++) {
                uint4 o;
                o.x = prmt(w0[2 * t],     w1[2 * t],     0x5410);
                o.y = prmt(w0[2 * t],     w1[2 * t],     0x7632);
                o.z = prmt(w0[2 * t + 1], w1[2 * t + 1], 0x5410);
                o.w = prmt(w0[2 * t + 1], w1[2 * t + 1], 0x7632);
                *(uint4*)(dst + 4 * t) = o;
            }
        }
        __syncthreads();
#pragma unroll
        for (int s = 0; s < 4; s++) {
            const int k2b = s * 8;
            u32 a[2][4], bf[4][2];
#pragma unroll
            for (int mi = 0; mi < 2; mi++) {
                a[mi][0] = A_s[k2b + tig][mi * 16 + gid];
                a[mi][1] = A_s[k2b + tig][mi * 16 + gid + 8];
                a[mi][2] = A_s[k2b + tig + 4][mi * 16 + gid];
                a[mi][3] = A_s[k2b + tig + 4][mi * 16 + gid + 8];
            }
#pragma unroll
            for (int ni = 0; ni < 4; ni++) {
                bf[ni][0] = B_s[k2b + tig][n0w + ni * 8 + gid];
                bf[ni][1] = B_s[k2b + tig + 4][n0w + ni * 8 + gid];
            }
#pragma unroll
            for (int mi = 0; mi < 2; mi++)
#pragma unroll
                for (int ni = 0; ni < 4; ni++)
                    MMA_F16(acc[mi][ni], a[mi][0], a[mi][1], a[mi][2], a[mi][3],
                            bf[ni][0], bf[ni][1]);
        }
        __syncthreads();
    }

#pragma unroll
    for (int mi = 0; mi < 2; mi++)
#pragma unroll
        for (int h = 0; h < 2; h++) {
            const int co = mi * 16 + gid + h * 8;
#pragma unroll
            for (int ni = 0; ni < 4; ni++) {
                const int ng = p0 + n0w + ni * 8 + 2 * tig;
                const int oh = ng >> hw_shift, ow = ng & (HW - 1);
                float2 o = {acc[mi][ni][h * 2], acc[mi][ni][h * 2 + 1]};
                *(float2*)&out[((size_t)(b * 32 + co) * HW + oh) * HW + ow] = o;
            }
        }
}

// ===========================================================================
extern "C" void kernel_launch(void* const* d_in, const int* in_sizes, int n_in,
                              void* d_out, int out_size)
{
    (void)in_sizes; (void)n_in;
    const float* x       = (const float*)d_in[0];
    const float* enc_w1  = (const float*)d_in[1];
    const float* enc_b1  = (const float*)d_in[2];
    const float* enc_w2  = (const float*)d_in[3];
    const float* enc_b2  = (const float*)d_in[4];
    const float* enc_w3  = (const float*)d_in[5];
    const float* enc_b3  = (const float*)d_in[6];
    const float* enc_rw3 = (const float*)d_in[7];
    const float* enc_rw1 = (const float*)d_in[8];
    const float* prevq_w = (const float*)d_in[9];
    const float* prevq_b = (const float*)d_in[10];
    const float* emb     = (const float*)d_in[11];
    const float* dec_w1  = (const float*)d_in[12];
    const float* dec_b1  = (const float*)d_in[13];
    const float* dec_rw3 = (const float*)d_in[14];
    const float* dec_rw1 = (const float*)d_in[15];
    const float* dec_w2  = (const float*)d_in[16];
    const float* dec_b2  = (const float*)d_in[17];
    const float* dec_w3  = (const float*)d_in[18];
    const float* dec_b3  = (const float*)d_in[19];
    float* out = (float*)d_out;

    float *b0, *b1, *b2, *b3, *ze, *zq, *loss;
    u32 *wt, *mx, *m0, *m1, *mq;
    cudaGetSymbolAddress((void**)&b0, g_b0);
    cudaGetSymbolAddress((void**)&b1, g_b1);
    cudaGetSymbolAddress((void**)&b2, g_b2);
    cudaGetSymbolAddress((void**)&b3, g_b3);
    cudaGetSymbolAddress((void**)&ze, g_ze);
    cudaGetSymbolAddress((void**)&zq, g_zq);
    cudaGetSymbolAddress((void**)&loss, g_loss);
    cudaGetSymbolAddress((void**)&wt, g_wt);
    cudaGetSymbolAddress((void**)&mx, g_mx);
    cudaGetSymbolAddress((void**)&m0, g_m0);
    cudaGetSymbolAddress((void**)&m1, g_m1);
    cudaGetSymbolAddress((void**)&mq, g_mq);

    const int DSM = 4 * CHBUF * 4;   // 69632 bytes
    cudaFuncSetAttribute(conv4s2_tcf, cudaFuncAttributeMaxDynamicSharedMemorySize, DSM);
    cudaFuncSetAttribute(tconv_tcf,   cudaFuncAttributeMaxDynamicSharedMemorySize, DSM);

    // ---- encoder ----
    cvt_mirror<<<dim3(134, 128), 256>>>(x, mx, 256, 256, 258, 132, 0, 3, 2);
    wt4s2_f16<<<16, 256>>>(enc_w1, wt, 4, 128, 3);
    conv4s2_tcf<<<dim3(1, 128, 32), 128, DSM>>>(mx, wt, enc_b1, b0, 4, 128, 258, 132, 128, 128, 7, 1);

    cvt_mirror<<<dim3(35, 4096), 256>>>(b0, m0, 128, 128, 130, 68, 0, 128, 7);
    wt4s2_f16<<<1024, 256>>>(enc_w2, wt, 128, 256, 128);
    conv4s2_tcf<<<dim3(1, 32, 64), 128, DSM>>>(m0, wt, enc_b2, b1, 128, 256, 130, 68, 64, 64, 6, 1);

    cvt_mirror<<<dim3(10, 8192), 256>>>(b1, m1, 64, 64, 66, 36, 0, 256, 8);
    wt4s2_f16<<<4096, 256>>>(enc_w3, wt, 256, 512, 256);
    conv4s2_tcf<<<dim3(1, 8, 128), 128, DSM>>>(m1, wt, enc_b3, b2, 256, 512, 66, 36, 32, 32, 5, 0);

    wt3_f16<<<288, 256>>>(enc_rw3, wt, 512);
    for (int l = 0; l < 2; l++) {
        cvt_mirror<<<dim3(3, 16384), 256>>>(b2, m0, 32, 32, 34, 20, 1, 512, 9);
        conv3x3_tcf<<<dim3(4, 1, 32), 256>>>(m0, wt, b3, 512, 32, 5, 34, 20);
        conv1x1_kernel<<<dim3(16, 8, 32), 256>>>(b3, enc_rw1, nullptr, b2, 32, 512, 1024, 1, 1);
    }
    conv1x1_kernel<<<dim3(16, 1, 32), 256>>>(b2, prevq_w, prevq_b, ze, 512, 64, 1024, 1, 0);

    // ---- VQ ----
    zero_loss_kernel<<<1, 1>>>(loss);
    vq_kernel<<<128, 256>>>(ze, emb, zq, loss);
    finish_loss_kernel<<<1, 1>>>(loss, out + (out_size - 1));

    // ---- decoder ----
    cvt_mirror<<<dim3(3, 2048), 256>>>(zq, mq, 32, 32, 34, 20, 0, 64, 6);
    wtT_f16<<<512, 256>>>(dec_w1, wt, 64, 256);
    tconv_tcf<<<dim3(1, 8, 256), 128, DSM>>>(mq, wt, dec_b1, b1, 64, 256, 32, 32, 34, 20, 5, 0);

    wt3_f16<<<144, 256>>>(dec_rw3, wt, 256);
    for (int l = 0; l < 2; l++) {
        cvt_mirror<<<dim3(10, 8192), 256>>>(b1, m1, 64, 64, 66, 36, 1, 256, 8);
        conv3x3_tcf<<<dim3(16, 1, 32), 256>>>(m1, wt, b3, 256, 64, 6, 66, 36);
        conv1x1_kernel<<<dim3(64, 4, 32), 256>>>(b3, dec_rw1, nullptr, b1, 32, 256, 4096, 1, 1);
    }

    cvt_mirror<<<dim3(10, 8192), 256>>>(b1, m1, 64, 64, 66, 36, 1, 256, 8);
    wtT_f16<<<1024, 256>>>(dec_w2, wt, 256, 128);
    tconv_tcf<<<dim3(1, 32, 128), 128, DSM>>>(m1, wt, dec_b2, b0, 256, 128, 64, 64, 66, 36, 6, 1);

    tconv_kernel<4, 1, 16, 16><<<dim3(8, 8, 32), 256>>>(b0, dec_w3, dec_b3, out, 128, 3, 128, 128, 0, 0);
}

// round 13
// speedup vs baseline: 6.2420x; 1.0742x over previous
#include <cuda_runtime.h>

typedef unsigned int u32;
typedef unsigned short u16;

__device__ float g_b0[32u * 128 * 128 * 128];
__device__ float g_b1[32u * 256 * 64 * 64];
__device__ float g_b2[32u * 512 * 32 * 32];
__device__ float g_b3[32u * 32 * 64 * 64];
__device__ float g_ze[32u * 64 * 32 * 32];
__device__ float g_loss[1];
__device__ u32   g_wt[2097152];
__device__ u32   g_mx[4359168];    // enc1 in: 128 x 258 x 132 u32
__device__ u32   g_m0[36218880];   // enc2 in: 4096 x 130 x 68 u32
__device__ u32   g_m1[19464192];   // enc3-in / dec-res / dec2-in: 8192 x 66 x 36
__device__ u32   g_me[11141120];   // enc-res: 16384 x 34 x 20 u32
__device__ u32   g_mq[1392640];    // dec1 in: 2048 x 34 x 20 u32

__device__ __forceinline__ u32 pack_f16x2(float lo, float hi) {
    u32 r; asm("cvt.rn.f16x2.f32 %0,%1,%2;" : "=r"(r) : "f"(hi), "f"(lo)); return r;
}
__device__ __forceinline__ u16 f2h(float f) {
    u16 h; asm("cvt.rn.f16.f32 %0,%1;" : "=h"(h) : "f"(f)); return h;
}
__device__ __forceinline__ u32 prmt(u32 a, u32 b, u32 s) {
    u32 r; asm("prmt.b32 %0,%1,%2,%3;" : "=r"(r) : "r"(a), "r"(b), "r"(s)); return r;
}
__device__ __forceinline__ u32 smem_u32(const void* p) {
    u32 a; asm("{ .reg .u64 t; cvta.to.shared.u64 t,%1; cvt.u32.u64 %0,t; }"
               : "=r"(a) : "l"(p));
    return a;
}

#define CP_A16(d, s) asm volatile("cp.async.ca.shared.global [%0],[%1],16;" :: "r"(d), "l"(s))
#define CP_A4(d, s)  asm volatile("cp.async.ca.shared.global [%0],[%1],4;"  :: "r"(d), "l"(s))
#define CP_COMMIT()  asm volatile("cp.async.commit_group;" ::: "memory")
#define CP_WAIT0()   asm volatile("cp.async.wait_group 0;" ::: "memory")
#define CP_WAIT1()   asm volatile("cp.async.wait_group 1;" ::: "memory")

#define MMA_F16(d, a0, a1, a2, a3, b0, b1)                                    \
    asm volatile("mma.sync.aligned.m16n8k16.row.col.f32.f16.f16.f32 "         \
                 "{%0,%1,%2,%3},{%4,%5,%6,%7},{%8,%9},{%0,%1,%2,%3};"         \
                 : "+f"(d[0]), "+f"(d[1]), "+f"(d[2]), "+f"(d[3])             \
                 : "r"(a0), "r"(a1), "r"(a2), "r"(a3), "r"(b0), "r"(b1))

// ---- mirror build (network input only) -------------------------------------
__global__ void cvt_mirror(const float* __restrict__ src, u32* __restrict__ dst,
                           int Hi, int Wi, int Hp, int Wp2, int relu,
                           int scpb, int dshift)
{
    const int plane = blockIdx.y;
    const int idx = blockIdx.x * 256 + threadIdx.x;
    if (idx >= Hp * Wp2) return;
    const int ph = idx / Wp2, wp2 = idx - ph * Wp2;
    const int b = plane >> dshift;
    const int c = plane & ((1 << dshift) - 1);
    const int ih = ph - 1;
    const int iw0 = 2 * wp2 - 1, iw1 = iw0 + 1;
    float v0 = 0.f, v1 = 0.f;
    if (c < scpb && (unsigned)ih < (unsigned)Hi) {
        const float* r = src + ((size_t)(b * scpb + c) * Hi + ih) * Wi;
        if ((unsigned)iw0 < (unsigned)Wi) v0 = r[iw0];
        if ((unsigned)iw1 < (unsigned)Wi) v1 = r[iw1];
    }
    if (relu) { v0 = fmaxf(v0, 0.f); v1 = fmaxf(v1, 0.f); }
    dst[(size_t)plane * Hp * Wp2 + idx] = pack_f16x2(v0, v1);
}

// ===========================================================================
// conv1x1 fp32 — optional fused mirror output
// ===========================================================================

__global__ void __launch_bounds__(256) conv1x1_kernel(
    const float* __restrict__ in, const float* __restrict__ w,
    const float* __restrict__ bias, float* __restrict__ out,
    int Ci, int Co, int P, int relu_in, int add_res,
    int wout, u16* __restrict__ mout, int MHp, int MWp, int hw_shift, int hwm)
{
    __shared__ float w_s[16][64];
    __shared__ float x_s[16][64];
    const int tid = threadIdx.x;
    const int tx = tid & 15, ty = tid >> 4;
    const int p0 = blockIdx.x * 64, c0 = blockIdx.y * 64, b = blockIdx.z;

    float acc[4][4];
#pragma unroll
    for (int i = 0; i < 4; i++)
#pragma unroll
        for (int j = 0; j < 4; j++) acc[i][j] = 0.f;

    for (int ci0 = 0; ci0 < Ci; ci0 += 16) {
        for (int idx = tid; idx < 1024; idx += 256) {
            int p = idx & 63, ci = idx >> 6;
            float v = in[(size_t)(b * Ci + ci0 + ci) * P + p0 + p];
            x_s[ci][p] = relu_in ? fmaxf(v, 0.f) : v;
        }
        for (int idx = tid; idx < 1024; idx += 256) {
            int ci = idx & 15, co = idx >> 4;
            w_s[ci][co] = w[(size_t)(c0 + co) * Ci + ci0 + ci];
        }
        __syncthreads();
#pragma unroll
        for (int ci = 0; ci < 16; ci++) {
            const float4 wv = *(const float4*)&w_s[ci][ty << 2];
            const float4 xv = *(const float4*)&x_s[ci][tx << 2];
            const float wvv[4] = {wv.x, wv.y, wv.z, wv.w};
            const float xvv[4] = {xv.x, xv.y, xv.z, xv.w};
#pragma unroll
            for (int i = 0; i < 4; i++)
#pragma unroll
                for (int j = 0; j < 4; j++)
                    acc[i][j] = fmaf(wvv[i], xvv[j], acc[i][j]);
        }
        __syncthreads();
    }
#pragma unroll
    for (int i = 0; i < 4; i++) {
        const int co = c0 + (ty << 2) + i;
        const float bv = bias ? bias[co] : 0.f;
        const int px = p0 + (tx << 2);
        const size_t base = (size_t)(b * Co + co) * P + px;
        float4 o = {acc[i][0] + bv, acc[i][1] + bv, acc[i][2] + bv, acc[i][3] + bv};
        if (add_res) {
            float4 rr = *(const float4*)&out[base];
            o.x += rr.x; o.y += rr.y; o.z += rr.z; o.w += rr.w;
        }
        if (wout) *(float4*)&out[base] = o;
        if (mout) {
            const int oh = px >> hw_shift, ow = px & hwm;
            u16* mp = mout + ((size_t)(b * Co + co) * MHp + oh + 1) * MWp + ow + 1;
            mp[0] = f2h(fmaxf(o.x, 0.f));
            mp[1] = f2h(fmaxf(o.y, 0.f));
            mp[2] = f2h(fmaxf(o.z, 0.f));
            mp[3] = f2h(fmaxf(o.w, 0.f));
        }
    }
}

// ===========================================================================
// VQ — writes dec1 mirror directly
// ===========================================================================

__global__ void __launch_bounds__(256) vq_kernel(
    const float* __restrict__ ze, const float* __restrict__ emb,
    u16* __restrict__ mq, float* __restrict__ loss)
{
    __shared__ float e_s[128 * 64];
    __shared__ float n_s[128];
    const int tid = threadIdx.x;
    const int n = blockIdx.x * 256 + tid;
    const int b = n >> 10, hw = n & 1023;

    float xr[64];
#pragma unroll
    for (int d = 0; d < 64; d++)
        xr[d] = ze[((size_t)(b * 64 + d) << 10) + hw];

    float best = 3.4e38f;
    int bi = 0;
    for (int kb = 0; kb < 4; kb++) {
        __syncthreads();
        for (int i = tid; i < 128 * 64; i += 256) e_s[i] = emb[kb * 128 * 64 + i];
        __syncthreads();
        if (tid < 128) {
            float s = 0.f;
#pragma unroll 8
            for (int d = 0; d < 64; d++) { float v = e_s[tid * 64 + d]; s = fmaf(v, v, s); }
            n_s[tid] = s;
        }
        __syncthreads();
        for (int k = 0; k < 128; k++) {
            const float4* e4 = (const float4*)(e_s + k * 64);
            float dot = 0.f;
#pragma unroll
            for (int d4 = 0; d4 < 16; d4++) {
                float4 e = e4[d4];
                dot = fmaf(e.x, xr[d4 * 4 + 0], dot);
                dot = fmaf(e.y, xr[d4 * 4 + 1], dot);
                dot = fmaf(e.z, xr[d4 * 4 + 2], dot);
                dot = fmaf(e.w, xr[d4 * 4 + 3], dot);
            }
            float dist = n_s[k] - 2.f * dot;
            if (dist < best) { best = dist; bi = kb * 128 + k; }
        }
    }

    const int oh = hw >> 5, ow = hw & 31;
    float ls = 0.f;
#pragma unroll
    for (int d = 0; d < 64; d++) {
        float e = emb[bi * 64 + d];
        mq[((size_t)(b * 64 + d) * 34 + oh + 1) * 40 + ow + 1] = f2h(e);
        float df = e - xr[d];
        ls = fmaf(df, df, ls);
    }
#pragma unroll
    for (int o = 16; o > 0; o >>= 1) ls += __shfl_down_sync(0xffffffffu, ls, o);
    if ((tid & 31) == 0) atomicAdd(loss, ls);
}

// fp32 tconv for dec3 (proven)
template <int CO_TILE, int CO_PT, int M_TILE, int N_TILE>
__global__ void __launch_bounds__(256) tconv_kernel(
    const float* __restrict__ in, const float* __restrict__ w,
    const float* __restrict__ bias, float* __restrict__ out,
    int Ci, int Co, int Hi, int Wi, int relu_in, int relu_out)
{
    constexpr int NSLOT = (M_TILE * N_TILE) / 4;
    constexpr int CG = CO_TILE / CO_PT;
    static_assert(NSLOT * CG == 256, "map");
    __shared__ float w_s[4][16][CO_TILE];
    __shared__ float x_s[4][M_TILE + 2][N_TILE + 2];

    const int tid = threadIdx.x;
    const int slot = tid % NSLOT, cg = tid / NSLOT;
    const int m_loc = slot / (N_TILE / 4);
    const int nb = (slot % (N_TILE / 4)) * 4;
    const int n0 = blockIdx.x * N_TILE, m0 = blockIdx.y * M_TILE;
    const int cot = (Co + CO_TILE - 1) / CO_TILE;
    const int b = blockIdx.z / cot, c0 = (blockIdx.z % cot) * CO_TILE;
    const int Ho = 2 * Hi, Wo2 = 2 * Wi;

    float acc[CO_PT][4][2][2];
#pragma unroll
    for (int i = 0; i < CO_PT; i++)
#pragma unroll
        for (int q = 0; q < 4; q++)
#pragma unroll
            for (int a = 0; a < 2; a++)
#pragma unroll
                for (int bb = 0; bb < 2; bb++) acc[i][q][a][bb] = 0.f;

    for (int ci0 = 0; ci0 < Ci; ci0 += 4) {
        for (int idx = tid; idx < 4 * (M_TILE + 2) * (N_TILE + 2); idx += 256) {
            int lc = idx % (N_TILE + 2);
            int t = idx / (N_TILE + 2);
            int lr = t % (M_TILE + 2), ci = t / (M_TILE + 2);
            int m = m0 - 1 + lr, nn = n0 - 1 + lc;
            float v = 0.f;
            if ((unsigned)m < (unsigned)Hi && (unsigned)nn < (unsigned)Wi)
                v = in[((size_t)(b * Ci + ci0 + ci) * Hi + m) * Wi + nn];
            if (relu_in) v = fmaxf(v, 0.f);
            x_s[ci][lr][lc] = v;
        }
        for (int idx = tid; idx < 4 * 16 * CO_TILE; idx += 256) {
            int t = idx & 15;
            int co = (idx >> 4) % CO_TILE;
            int ci = idx / (16 * CO_TILE);
            float v = 0.f;
            if (c0 + co < Co) v = w[((size_t)(ci0 + ci) * Co + c0 + co) * 16 + t];
            w_s[ci][t][co] = v;
        }
        __syncthreads();
#pragma unroll
        for (int ci = 0; ci < 4; ci++)
#pragma unroll
            for (int t = 0; t < 16; t++) {
                const int kh = t >> 2, kw = t & 3;
                const int a = 1 - (kh & 1);
                const int dm = (kh == 0) ? 1 : ((kh == 3) ? -1 : 0);
                const int bb = 1 - (kw & 1);
                const int dn = (kw == 0) ? 1 : ((kw == 3) ? -1 : 0);
                float wr[CO_PT];
#pragma unroll
                for (int i = 0; i < CO_PT; i++)
                    wr[i] = w_s[ci][t][cg * CO_PT + i];
                const float* xrow = &x_s[ci][m_loc + dm + 1][nb + dn + 1];
#pragma unroll
                for (int q = 0; q < 4; q++) {
                    const float xv = xrow[q];
#pragma unroll
                    for (int i = 0; i < CO_PT; i++)
                        acc[i][q][a][bb] = fmaf(wr[i], xv, acc[i][q][a][bb]);
                }
            }
        __syncthreads();
    }

    const int m = m0 + m_loc;
#pragma unroll
    for (int i = 0; i < CO_PT; i++) {
        const int co = c0 + cg * CO_PT + i;
        if (co < Co) {
            const float bv = bias[co];
#pragma unroll
            for (int q = 0; q < 4; q++) {
                const int nn = n0 + nb + q;
#pragma unroll
                for (int a = 0; a < 2; a++) {
                    float2 o = {acc[i][q][a][0] + bv, acc[i][q][a][1] + bv};
                    if (relu_out) { o.x = fmaxf(o.x, 0.f); o.y = fmaxf(o.y, 0.f); }
                    *(float2*)&out[((size_t)(b * Co + co) * Ho + 2 * m + a) * Wo2 + 2 * nn] = o;
                }
            }
        }
    }
}

__global__ void zero_loss_kernel(float* loss) { loss[0] = 0.f; }
__global__ void finish_loss_kernel(const float* __restrict__ loss, float* __restrict__ dst)
{
    dst[0] = 2.f * loss[0] / 2097152.f;
}

// ===========================================================================
// weight prepacks (fp16)
// ===========================================================================

__global__ void wt4s2_f16(const float* __restrict__ w, u32* __restrict__ wT2,
                          int Ci, int Co, int Ci_src)
{
    int idx = blockIdx.x * 256 + threadIdx.x;
    if (idx >= Ci * 8 * Co) return;
    int co = idx % Co, k2 = idx / Co;
    int k = 2 * k2, ci = k >> 4, t = k & 15;
    float v0 = 0.f, v1 = 0.f;
    if (ci < Ci_src) {
        const float* base = &w[((size_t)co * Ci_src + ci) * 16 + t];
        v0 = base[0]; v1 = base[1];
    }
    wT2[idx] = pack_f16x2(v0, v1);
}

__global__ void wtT_f16(const float* __restrict__ w, u32* __restrict__ wT2,
                        int Ci, int Co)
{
    int K2 = Ci * 2;
    int idx = blockIdx.x * 256 + threadIdx.x;
    if (idx >= 4 * K2 * Co) return;
    int co = idx % Co, rr = idx / Co;
    int p = rr / K2, k2 = rr % K2;
    int k = 2 * k2, ci = k >> 2, j = k & 3;
    int a = p >> 1, bb = p & 1;
    int kh = (1 - a) + 2 * (j >> 1);
    const float* base = &w[((size_t)ci * Co + co) * 16 + kh * 4];
    wT2[idx] = pack_f16x2(base[1 - bb], base[3 - bb]);
}

__global__ void wt3_f16(const float* __restrict__ w, u32* __restrict__ wT2, int Ci)
{
    int K = Ci * 9;
    int idx = blockIdx.x * 256 + threadIdx.x;
    if (idx >= (K / 2) * 32) return;
    int co = idx & 31, k2 = idx >> 5;
    int k0 = 2 * k2, k1 = k0 + 1;
    int ci0 = k0 / 9, t0 = k0 - ci0 * 9;
    int ci1 = k1 / 9, t1 = k1 - ci1 * 9;
    wT2[idx] = pack_f16x2(w[((size_t)co * Ci + ci0) * 9 + t0],
                          w[((size_t)co * Ci + ci1) * 9 + t1]);
}

// ===========================================================================
// HMMA conv k4 s2 p1 — fused mirror epilogue
// ===========================================================================

#define CHBUF 4352

__global__ void __launch_bounds__(128, 2) conv4s2_tcf(
    const u32* __restrict__ mir, const u32* __restrict__ wT2,
    const float* __restrict__ bias, float* __restrict__ out,
    int Ci, int Co, int Hp, int Wp2, int Ho, int Wo, int w_shift, int relu,
    int wout, u16* __restrict__ mout, int MHp, int MWp)
{
    extern __shared__ u32 sm[];
    const int tid = threadIdx.x;
    const int lane = tid & 31, warp = tid >> 5;
    const int gid = lane >> 2, tig = lane & 3;
    const int m0w = (warp & 1) * 64, n0w = (warp >> 1) * 64;
    const int OWT = 1 << w_shift;
    const int ow0 = blockIdx.x * OWT, oh0 = blockIdx.y * (128 >> w_shift);
    const int cot = Co >> 7;
    const int b = blockIdx.z / cot, c0 = (blockIdx.z % cot) << 7;
    const int K = Ci << 4, NC = K >> 6;
    const int sk = tid >> 2, sn0 = (tid & 3) << 5;
    const int oh = oh0 + (sn0 >> w_shift), ow = ow0 + (sn0 & (OWT - 1));
    const u32 sb = smem_u32(sm);

    auto stage = [&](int c, int buf) {
        const int k02 = c << 5;
#pragma unroll
        for (int q = 0; q < 8; q++) {
            int idx = tid + (q << 7);
            int kk = idx >> 5, m4 = idx & 31;
            u32 dst = sb + ((u32)(buf * CHBUF + kk * 136 + (m4 << 2)) << 2);
            CP_A16(dst, wT2 + (size_t)(k02 + kk) * Co + c0 + (m4 << 2));
        }
        const int k = (c << 6) + 2 * sk;
        const int ci = k >> 4, t = k & 15, kh = t >> 2, a1 = (t & 3) >> 1;
        const u32* src = mir + ((size_t)(b * Ci + ci) * Hp + 2 * oh + kh) * Wp2 + ow + a1;
        u32 dst = sb + ((u32)(2 * CHBUF + buf * CHBUF + sk * 136 + sn0) << 2);
        if (!a1) {
#pragma unroll
            for (int j = 0; j < 8; j++) CP_A16(dst + 16 * j, src + 4 * j);
        } else {
#pragma unroll
            for (int j = 0; j < 32; j++) CP_A4(dst + 4 * j, src + j);
        }
    };

    float acc[4][8][4];
#pragma unroll
    for (int mi = 0; mi < 4; mi++)
#pragma unroll
        for (int ni = 0; ni < 8; ni++)
#pragma unroll
            for (int c = 0; c < 4; c++) acc[mi][ni][c] = 0.f;

    stage(0, 0);
    CP_COMMIT();

    for (int c = 0; c < NC; c++) {
        if (c + 1 < NC) { stage(c + 1, (c + 1) & 1); CP_COMMIT(); CP_WAIT1(); }
        else CP_WAIT0();
        __syncthreads();
        const u32* As = sm + (c & 1) * CHBUF;
        const u32* Bs = sm + 2 * CHBUF + (c & 1) * CHBUF;
#pragma unroll
        for (int s = 0; s < 4; s++) {
            const int k2b = s * 8;
            u32 a[4][4], bf[8][2];
#pragma unroll
            for (int mi = 0; mi < 4; mi++) {
                a[mi][0] = As[(k2b + tig) * 136 + m0w + mi * 16 + gid];
                a[mi][1] = As[(k2b + tig) * 136 + m0w + mi * 16 + gid + 8];
                a[mi][2] = As[(k2b + tig + 4) * 136 + m0w + mi * 16 + gid];
                a[mi][3] = As[(k2b + tig + 4) * 136 + m0w + mi * 16 + gid + 8];
            }
#pragma unroll
            for (int ni = 0; ni < 8; ni++) {
                bf[ni][0] = Bs[(k2b + tig) * 136 + n0w + ni * 8 + gid];
                bf[ni][1] = Bs[(k2b + tig + 4) * 136 + n0w + ni * 8 + gid];
            }
#pragma unroll
            for (int mi = 0; mi < 4; mi++)
#pragma unroll
                for (int ni = 0; ni < 8; ni++)
                    MMA_F16(acc[mi][ni], a[mi][0], a[mi][1], a[mi][2], a[mi][3],
                            bf[ni][0], bf[ni][1]);
        }
        __syncthreads();
    }

#pragma unroll
    for (int mi = 0; mi < 4; mi++)
#pragma unroll
        for (int h = 0; h < 2; h++) {
            const int co = c0 + m0w + mi * 16 + gid + h * 8;
            const float bv = bias[co];
#pragma unroll
            for (int ni = 0; ni < 8; ni++) {
                const int n = n0w + ni * 8 + 2 * tig;
                const int ohl = n >> w_shift, owl = n & (OWT - 1);
                float v0 = acc[mi][ni][h * 2] + bv;
                float v1 = acc[mi][ni][h * 2 + 1] + bv;
                if (wout) {
                    float2 o = {relu ? fmaxf(v0, 0.f) : v0, relu ? fmaxf(v1, 0.f) : v1};
                    *(float2*)&out[((size_t)(b * Co + co) * Ho + oh0 + ohl) * Wo + ow0 + owl] = o;
                }
                if (mout) {
                    u16* mp = mout + ((size_t)(b * Co + co) * MHp + oh0 + ohl + 1) * MWp
                              + ow0 + owl + 1;
                    mp[0] = f2h(fmaxf(v0, 0.f));
                    mp[1] = f2h(fmaxf(v1, 0.f));
                }
            }
        }
}

// ===========================================================================
// HMMA conv-transpose per-parity — fused mirror epilogue
// ===========================================================================

__global__ void __launch_bounds__(128, 2) tconv_tcf(
    const u32* __restrict__ mir, const u32* __restrict__ wT2,
    const float* __restrict__ bias, float* __restrict__ out,
    int Ci, int Co, int Hi, int Wi, int Hp, int Wp2, int w_shift, int relu_out,
    int wout, u16* __restrict__ mout, int MHp, int MWp)
{
    extern __shared__ u32 sm[];
    const int tid = threadIdx.x;
    const int lane = tid & 31, warp = tid >> 5;
    const int gid = lane >> 2, tig = lane & 3;
    const int m0w = (warp & 1) * 64, n0w = (warp >> 1) * 64;
    const int OWT = 1 << w_shift;
    const int ow0 = blockIdx.x * OWT, oh0 = blockIdx.y * (128 >> w_shift);
    const int p = blockIdx.z & 3;
    const int rest = blockIdx.z >> 2;
    const int cot = Co >> 7;
    const int b = rest / cot, c0 = (rest % cot) << 7;
    const int pa = p >> 1, pb = p & 1;
    const int K = Ci << 2, K2 = Ci << 1, NC = K >> 6;
    const int Ho = 2 * Hi, Wo2 = 2 * Wi;
    const u32* wTp = wT2 + (size_t)p * K2 * Co;
    const int sk = tid >> 2, sn0 = (tid & 3) << 5;
    const int mh = oh0 + (sn0 >> w_shift), mw = ow0 + (sn0 & (OWT - 1));
    const u32 sb = smem_u32(sm);

    auto stageA = [&](int c, int buf) {
        const int k02 = c << 5;
#pragma unroll
        for (int q = 0; q < 8; q++) {
            int idx = tid + (q << 7);
            int kk = idx >> 5, m4 = idx & 31;
            u32 dst = sb + ((u32)(buf * CHBUF + kk * 136 + (m4 << 2)) << 2);
            CP_A16(dst, wTp + (size_t)(k02 + kk) * Co + c0 + (m4 << 2));
        }
    };

    u32 us[17];
    auto loadB = [&](int c) {
        const int k = (c << 6) + 2 * sk;
        const int ci = k >> 2, j2 = k & 3;
        const int kh = (1 - pa) + 2 * (j2 >> 1);
        const int dm = (kh == 0) ? 1 : ((kh == 3) ? -1 : 0);
        const size_t base = ((size_t)(b * Ci + ci) * Hp + mh + dm + 1) * Wp2 + (mw >> 1);
        const uint4* q4 = (const uint4*)(mir + base);
#pragma unroll
        for (int i = 0; i < 4; i++) {
            uint4 v = q4[i];
            us[4 * i] = v.x; us[4 * i + 1] = v.y;
            us[4 * i + 2] = v.z; us[4 * i + 3] = v.w;
        }
        us[16] = mir[base + 16];
    };

    float acc[4][8][4];
#pragma unroll
    for (int mi = 0; mi < 4; mi++)
#pragma unroll
        for (int ni = 0; ni < 8; ni++)
#pragma unroll
            for (int c = 0; c < 4; c++) acc[mi][ni][c] = 0.f;

    stageA(0, 0);
    CP_COMMIT();
    loadB(0);

    for (int c = 0; c < NC; c++) {
        {
            u32* dst = sm + 2 * CHBUF + (c & 1) * CHBUF + sk * 136 + sn0;
            if (pb == 0) {
#pragma unroll
                for (int q = 0; q < 16; q++) {
                    u32 a = us[q], bb = us[q + 1];
                    dst[2 * q]     = prmt(a, a, 0x1032);
                    dst[2 * q + 1] = prmt(a, bb, 0x3254);
                }
            } else {
#pragma unroll
                for (int q = 0; q < 16; q++) {
                    u32 a = us[q], bb = us[q + 1];
                    dst[2 * q]     = prmt(a, bb, 0x3254);
                    dst[2 * q + 1] = prmt(bb, bb, 0x1032);
                }
            }
        }
        if (c + 1 < NC) { stageA(c + 1, (c + 1) & 1); CP_COMMIT(); CP_WAIT1(); }
        else CP_WAIT0();
        __syncthreads();
        if (c + 1 < NC) loadB(c + 1);

        const u32* As = sm + (c & 1) * CHBUF;
        const u32* Bs = sm + 2 * CHBUF + (c & 1) * CHBUF;
#pragma unroll
        for (int s = 0; s < 4; s++) {
            const int k2b = s * 8;
            u32 a[4][4], bf[8][2];
#pragma unroll
            for (int mi = 0; mi < 4; mi++) {
                a[mi][0] = As[(k2b + tig) * 136 + m0w + mi * 16 + gid];
                a[mi][1] = As[(k2b + tig) * 136 + m0w + mi * 16 + gid + 8];
                a[mi][2] = As[(k2b + tig + 4) * 136 + m0w + mi * 16 + gid];
                a[mi][3] = As[(k2b + tig + 4) * 136 + m0w + mi * 16 + gid + 8];
            }
#pragma unroll
            for (int ni = 0; ni < 8; ni++) {
                bf[ni][0] = Bs[(k2b + tig) * 136 + n0w + ni * 8 + gid];
                bf[ni][1] = Bs[(k2b + tig + 4) * 136 + n0w + ni * 8 + gid];
            }
#pragma unroll
            for (int mi = 0; mi < 4; mi++)
#pragma unroll
                for (int ni = 0; ni < 8; ni++)
                    MMA_F16(acc[mi][ni], a[mi][0], a[mi][1], a[mi][2], a[mi][3],
                            bf[ni][0], bf[ni][1]);
        }
        __syncthreads();
    }

#pragma unroll
    for (int mi = 0; mi < 4; mi++)
#pragma unroll
        for (int h = 0; h < 2; h++) {
            const int co = c0 + m0w + mi * 16 + gid + h * 8;
            const float bv = bias[co];
#pragma unroll
            for (int ni = 0; ni < 8; ni++) {
                const int n = n0w + ni * 8 + 2 * tig;
                const int mhh = oh0 + (n >> w_shift);
                const int mww = ow0 + (n & (OWT - 1));
                float v0 = acc[mi][ni][h * 2] + bv;
                float v1 = acc[mi][ni][h * 2 + 1] + bv;
                const int orow_i = 2 * mhh + pa;
                if (wout) {
                    float s0 = relu_out ? fmaxf(v0, 0.f) : v0;
                    float s1 = relu_out ? fmaxf(v1, 0.f) : v1;
                    float* orow = &out[((size_t)(b * Co + co) * Ho + orow_i) * Wo2];
                    orow[2 * mww + pb] = s0;
                    orow[2 * (mww + 1) + pb] = s1;
                }
                if (mout) {
                    u16* mp = mout + ((size_t)(b * Co + co) * MHp + orow_i + 1) * MWp;
                    mp[2 * mww + pb + 1] = f2h(fmaxf(v0, 0.f));
                    mp[2 * (mww + 1) + pb + 1] = f2h(fmaxf(v1, 0.f));
                }
            }
        }
}

// ===========================================================================
// HMMA 3x3 res conv — mirror-staged (proven round-12)
// ===========================================================================

template <int O>
__device__ __forceinline__ void canon16(u32* w, const u32 (&us)[20], int p) {
    if (p) {
#pragma unroll
        for (int i = 0; i < 16; i++) w[i] = prmt(us[O + i], us[O + i + 1], 0x5432);
    } else {
#pragma unroll
        for (int i = 0; i < 16; i++) w[i] = us[O + i];
    }
}
__device__ __forceinline__ void canon(u32* w, const u32 (&us)[20], int o, int p) {
    switch (o) {
    case 0:  canon16<0>(w, us, p); break;
    case 1:  canon16<1>(w, us, p); break;
    case 2:  canon16<2>(w, us, p); break;
    default: canon16<3>(w, us, p); break;
    }
}

__global__ void __launch_bounds__(256, 2) conv3x3_tcf(
    const u32* __restrict__ mir, const u32* __restrict__ wT2,
    float* __restrict__ out, int Ci, int HW, int hw_shift, int Hp, int Wp2)
{
    __shared__ u32 A_s[32][40];
    __shared__ u32 B_s[32][264];
    const int tid = threadIdx.x;
    const int lane = tid & 31, warp = tid >> 5;
    const int gid = lane >> 2, tig = lane & 3;
    const int n0w = warp * 32;
    const int p0 = blockIdx.x * 256;
    const int b = blockIdx.z;
    const int K = Ci * 9;

    const int sk = tid >> 3;
    const int sn0 = (tid & 7) << 5;
    const int ng0 = p0 + sn0;
    const int s_oh = ng0 >> hw_shift;
    const int s_ow = ng0 & (HW - 1);

    float acc[2][4][4];
#pragma unroll
    for (int mi = 0; mi < 2; mi++)
#pragma unroll
        for (int ni = 0; ni < 4; ni++)
#pragma unroll
            for (int c = 0; c < 4; c++) acc[mi][ni][c] = 0.f;

    for (int k0 = 0; k0 < K; k0 += 64) {
        const int k02 = k0 >> 1;
        for (int idx = tid; idx < 1024; idx += 256) {
            int kk = idx >> 5, m = idx & 31;
            A_s[kk][m] = wT2[(size_t)(k02 + kk) * 32 + m];
        }
        {
            const int klo = k0 + 2 * sk, khi = klo + 1;
            const int ci0 = klo / 9, t0 = klo - ci0 * 9;
            const int ci1 = khi / 9, t1 = khi - ci1 * 9;
            const int kh0 = t0 / 3, kw0 = t0 - 3 * kh0;
            const int kh1 = t1 / 3, kw1 = t1 - 3 * kh1;
            const u32* r0 = mir + ((size_t)(b * Ci + ci0) * Hp + s_oh + kh0) * Wp2;
            const u32* r1 = mir + ((size_t)(b * Ci + ci1) * Hp + s_oh + kh1) * Wp2;
            const int h0 = s_ow + kw0, h1 = s_ow + kw1;
            const int b0i = h0 >> 1, b1i = h1 >> 1;
            const int al0 = b0i & ~3, al1 = b1i & ~3;
            u32 us0[20], us1[20], w0[16], w1[16];
            {
                const uint4* q4 = (const uint4*)(r0 + al0);
#pragma unroll
                for (int i = 0; i < 5; i++) {
                    uint4 v = q4[i];
                    us0[4 * i] = v.x; us0[4 * i + 1] = v.y;
                    us0[4 * i + 2] = v.z; us0[4 * i + 3] = v.w;
                }
            }
            canon(w0, us0, b0i - al0, h0 & 1);
            {
                const uint4* q4 = (const uint4*)(r1 + al1);
#pragma unroll
                for (int i = 0; i < 5; i++) {
                    uint4 v = q4[i];
                    us1[4 * i] = v.x; us1[4 * i + 1] = v.y;
                    us1[4 * i + 2] = v.z; us1[4 * i + 3] = v.w;
                }
            }
            canon(w1, us1, b1i - al1, h1 & 1);
            u32* dst = &B_s[sk][sn0];
#pragma unroll
            for (int t = 0; t < 8; t++) {
                uint4 o;
                o.x = prmt(w0[2 * t],     w1[2 * t],     0x5410);
                o.y = prmt(w0[2 * t],     w1[2 * t],     0x7632);
                o.z = prmt(w0[2 * t + 1], w1[2 * t + 1], 0x5410);
                o.w = prmt(w0[2 * t + 1], w1[2 * t + 1], 0x7632);
                *(uint4*)(dst + 4 * t) = o;
            }
        }
        __syncthreads();
#pragma unroll
        for (int s = 0; s < 4; s++) {
            const int k2b = s * 8;
            u32 a[2][4], bf[4][2];
#pragma unroll
            for (int mi = 0; mi < 2; mi++) {
                a[mi][0] = A_s[k2b + tig][mi * 16 + gid];
                a[mi][1] = A_s[k2b + tig][mi * 16 + gid + 8];
                a[mi][2] = A_s[k2b + tig + 4][mi * 16 + gid];
                a[mi][3] = A_s[k2b + tig + 4][mi * 16 + gid + 8];
            }
#pragma unroll
            for (int ni = 0; ni < 4; ni++) {
                bf[ni][0] = B_s[k2b + tig][n0w + ni * 8 + gid];
                bf[ni][1] = B_s[k2b + tig + 4][n0w + ni * 8 + gid];
            }
#pragma unroll
            for (int mi = 0; mi < 2; mi++)
#pragma unroll
                for (int ni = 0; ni < 4; ni++)
                    MMA_F16(acc[mi][ni], a[mi][0], a[mi][1], a[mi][2], a[mi][3],
                            bf[ni][0], bf[ni][1]);
        }
        __syncthreads();
    }

#pragma unroll
    for (int mi = 0; mi < 2; mi++)
#pragma unroll
        for (int h = 0; h < 2; h++) {
            const int co = mi * 16 + gid + h * 8;
#pragma unroll
            for (int ni = 0; ni < 4; ni++) {
                const int ng = p0 + n0w + ni * 8 + 2 * tig;
                const int oh = ng >> hw_shift, ow = ng & (HW - 1);
                float2 o = {acc[mi][ni][h * 2], acc[mi][ni][h * 2 + 1]};
                *(float2*)&out[((size_t)(b * 32 + co) * HW + oh) * HW + ow] = o;
            }
        }
}

// ===========================================================================
extern "C" void kernel_launch(void* const* d_in, const int* in_sizes, int n_in,
                              void* d_out, int out_size)
{
    (void)in_sizes; (void)n_in;
    const float* x       = (const float*)d_in[0];
    const float* enc_w1  = (const float*)d_in[1];
    const float* enc_b1  = (const float*)d_in[2];
    const float* enc_w2  = (const float*)d_in[3];
    const float* enc_b2  = (const float*)d_in[4];
    const float* enc_w3  = (const float*)d_in[5];
    const float* enc_b3  = (const float*)d_in[6];
    const float* enc_rw3 = (const float*)d_in[7];
    const float* enc_rw1 = (const float*)d_in[8];
    const float* prevq_w = (const float*)d_in[9];
    const float* prevq_b = (const float*)d_in[10];
    const float* emb     = (const float*)d_in[11];
    const float* dec_w1  = (const float*)d_in[12];
    const float* dec_b1  = (const float*)d_in[13];
    const float* dec_rw3 = (const float*)d_in[14];
    const float* dec_rw1 = (const float*)d_in[15];
    const float* dec_w2  = (const float*)d_in[16];
    const float* dec_b2  = (const float*)d_in[17];
    const float* dec_w3  = (const float*)d_in[18];
    const float* dec_b3  = (const float*)d_in[19];
    float* out = (float*)d_out;

    float *b0, *b1, *b2, *b3, *ze, *loss;
    u32 *wt, *mx, *m0, *m1, *me, *mq;
    cudaGetSymbolAddress((void**)&b0, g_b0);
    cudaGetSymbolAddress((void**)&b1, g_b1);
    cudaGetSymbolAddress((void**)&b2, g_b2);
    cudaGetSymbolAddress((void**)&b3, g_b3);
    cudaGetSymbolAddress((void**)&ze, g_ze);
    cudaGetSymbolAddress((void**)&loss, g_loss);
    cudaGetSymbolAddress((void**)&wt, g_wt);
    cudaGetSymbolAddress((void**)&mx, g_mx);
    cudaGetSymbolAddress((void**)&m0, g_m0);
    cudaGetSymbolAddress((void**)&m1, g_m1);
    cudaGetSymbolAddress((void**)&me, g_me);
    cudaGetSymbolAddress((void**)&mq, g_mq);

    const int DSM = 4 * CHBUF * 4;   // 69632 bytes
    cudaFuncSetAttribute(conv4s2_tcf, cudaFuncAttributeMaxDynamicSharedMemorySize, DSM);
    cudaFuncSetAttribute(tconv_tcf,   cudaFuncAttributeMaxDynamicSharedMemorySize, DSM);

    // ---- encoder ----
    cvt_mirror<<<dim3(134, 128), 256>>>(x, mx, 256, 256, 258, 132, 0, 3, 2);
    wt4s2_f16<<<16, 256>>>(enc_w1, wt, 4, 128, 3);
    conv4s2_tcf<<<dim3(1, 128, 32), 128, DSM>>>(mx, wt, enc_b1, nullptr,
        4, 128, 258, 132, 128, 128, 7, 1, 0, (u16*)m0, 130, 136);

    wt4s2_f16<<<1024, 256>>>(enc_w2, wt, 128, 256, 128);
    conv4s2_tcf<<<dim3(1, 32, 64), 128, DSM>>>(m0, wt, enc_b2, nullptr,
        128, 256, 130, 68, 64, 64, 6, 1, 0, (u16*)m1, 66, 72);

    wt4s2_f16<<<4096, 256>>>(enc_w3, wt, 256, 512, 256);
    conv4s2_tcf<<<dim3(1, 8, 128), 128, DSM>>>(m1, wt, enc_b3, b2,
        256, 512, 66, 36, 32, 32, 5, 0, 1, (u16*)me, 34, 40);

    wt3_f16<<<288, 256>>>(enc_rw3, wt, 512);
    for (int l = 0; l < 2; l++) {
        conv3x3_tcf<<<dim3(4, 1, 32), 256>>>(me, wt, b3, 512, 32, 5, 34, 20);
        conv1x1_kernel<<<dim3(16, 8, 32), 256>>>(b3, enc_rw1, nullptr, b2,
            32, 512, 1024, 1, 1, 1, l == 0 ? (u16*)me : nullptr, 34, 40, 5, 31);
    }
    conv1x1_kernel<<<dim3(16, 1, 32), 256>>>(b2, prevq_w, prevq_b, ze,
        512, 64, 1024, 1, 0, 1, nullptr, 0, 0, 5, 31);

    // ---- VQ ----
    zero_loss_kernel<<<1, 1>>>(loss);
    vq_kernel<<<128, 256>>>(ze, emb, (u16*)mq, loss);
    finish_loss_kernel<<<1, 1>>>(loss, out + (out_size - 1));

    // ---- decoder ----
    wtT_f16<<<512, 256>>>(dec_w1, wt, 64, 256);
    tconv_tcf<<<dim3(1, 8, 256), 128, DSM>>>(mq, wt, dec_b1, b1,
        64, 256, 32, 32, 34, 20, 5, 0, 1, (u16*)m1, 66, 72);

    wt3_f16<<<144, 256>>>(dec_rw3, wt, 256);
    for (int l = 0; l < 2; l++) {
        conv3x3_tcf<<<dim3(16, 1, 32), 256>>>(m1, wt, b3, 256, 64, 6, 66, 36);
        conv1x1_kernel<<<dim3(64, 4, 32), 256>>>(b3, dec_rw1, nullptr, b1,
            32, 256, 4096, 1, 1, l == 0 ? 1 : 0, (u16*)m1, 66, 72, 6, 63);
    }

    wt4s2_f16<<<1024, 256>>>(dec_w2, wt, 256, 128, 256);   // placeholder, unused
    wtT_f16<<<1024, 256>>>(dec_w2, wt, 256, 128);
    tconv_tcf<<<dim3(1, 32, 128), 128, DSM>>>(m1, wt, dec_b2, b0,
        256, 128, 64, 64, 66, 36, 6, 1, 1, nullptr, 0, 0);

    tconv_kernel<4, 1, 16, 16><<<dim3(8, 8, 32), 256>>>(b0, dec_w3, dec_b3, out, 128, 3, 128, 128, 0, 0);
}